// round 9
// baseline (speedup 1.0000x reference)
#include <cuda_runtime.h>
#include <cuda_fp16.h>
#include <cstdint>

// ---------------------------------------------------------------------------
// Problem constants
// ---------------------------------------------------------------------------
#define B 32
#define N_TOK 1024
#define DIM 512
#define IC 512
#define CC 256
#define NH 8
#define AG 49
#define HD 64
#define HH 32
#define WW 32
#define CIN 768            // IC + CC
#define KCONV 6912         // 768*9
#define MCONV 1568         // B*49
#define NQKV 1536          // IC + 2*IC
#define AGFLAT 25088       // IC*AG
#define KSPLIT 4
#define KSLAB 1728         // KCONV / KSPLIT

// ---------------------------------------------------------------------------
// Scratch (static device globals; no allocation allowed)
// ---------------------------------------------------------------------------
__device__ __half g_qkvh[(size_t)B * N_TOK * NQKV];          // [q|k|v] fp16
__device__ __half g_xh[(size_t)B * N_TOK * DIM];             // x in fp16
__device__ __half g_whT[(size_t)NQKV * DIM];                 // [j][k] hi
__device__ __half g_wlT[(size_t)NQKV * DIM];                 // [j][k] lo
__device__ __half g_pwhT[(size_t)IC * DIM];
__device__ __half g_pwlT[(size_t)IC * DIM];
__device__ __half g_cwh[(size_t)IC * KCONV];
__device__ __half g_cwl[(size_t)IC * KCONV];
__device__ float  g_pooled[(size_t)B * AG * CIN];
__device__ __half g_colh[(size_t)MCONV * KCONV];
__device__ float  g_convp[(size_t)KSPLIT * MCONV * IC];
__device__ float  g_agent_cs[(size_t)B * AGFLAT];
__device__ float  g_bias_an[NH * AG * N_TOK];
__device__ float  g_bias_na[NH * N_TOK * AG];
__device__ float  g_agv[(size_t)B * NH * AG * HD];
__device__ __half g_outh[(size_t)B * N_TOK * IC];

// ---------------------------------------------------------------------------
// PTX helpers
// ---------------------------------------------------------------------------
#define LDSM4(r0, r1, r2, r3, addr)                                      \
    asm volatile("ldmatrix.sync.aligned.m8n8.x4.shared.b16 "             \
                 "{%0,%1,%2,%3}, [%4];"                                  \
                 : "=r"(r0), "=r"(r1), "=r"(r2), "=r"(r3) : "r"(addr))

#define MMA_F16(d, a, b0, b1)                                            \
    asm volatile(                                                        \
        "mma.sync.aligned.m16n8k16.row.col.f32.f16.f16.f32 "             \
        "{%0,%1,%2,%3}, {%4,%5,%6,%7}, {%8,%9}, {%0,%1,%2,%3};"          \
        : "+f"((d)[0]), "+f"((d)[1]), "+f"((d)[2]), "+f"((d)[3])         \
        : "r"((a)[0]), "r"((a)[1]), "r"((a)[2]), "r"((a)[3]),            \
          "r"(b0), "r"(b1))

#define CP16(dst, src, bytes)                                            \
    asm volatile("cp.async.ca.shared.global [%0], [%1], 16, %2;"         \
                 :: "r"(dst), "l"(src), "r"(bytes))
#define CP_COMMIT() asm volatile("cp.async.commit_group;")
#define CP_WAIT(n)  asm volatile("cp.async.wait_group %0;" :: "n"(n))

__device__ __forceinline__ uint32_t smem_u32(const void* p) {
    uint32_t a;
    asm("{ .reg .u64 t; cvta.to.shared.u64 t, %1; cvt.u32.u64 %0, t; }"
        : "=r"(a) : "l"(p));
    return a;
}

__device__ __forceinline__ void split_h(float v, __half& h, __half& l) {
    h = __float2half(v);
    l = __float2half(v - __half2float(h));
}

// ---------------------------------------------------------------------------
// fp16x2 tensor-core GEMM, cp.async 3-stage pipeline.
// C/Ch[M,N] = A[M,K] @ B'[N,K]^T (+bias).  A fp16 row-major (lda halves),
// B' pre-split hi/lo fp16 row-major (ldb halves), both K-contiguous.
// Output: fp32 to C if Ch==null, else fp16 to Ch.
// Block tile 128x128, K chunk 32, 8 warps of 64x32; 2 CTAs/SM.
// Requires N%128==0, K%32==0. M guarded. blockIdx.z adds az/bz/cz offsets.
// ---------------------------------------------------------------------------
#define TROW   40                  // padded row stride in halves (80 bytes)
#define TILEB  10240               // 128 * 80 bytes
#define STAGEB (3 * TILEB)         // Ah | Bh | Bl
#define NSTAGE 3
#define GSMEM  (NSTAGE * STAGEB)   // 92160 bytes

__global__ __launch_bounds__(256, 2) void gemm_f16a(
    const __half* __restrict__ A, int lda,
    const __half* __restrict__ Bh, const __half* __restrict__ Bl, int ldb,
    const float* __restrict__ bias, float* __restrict__ C,
    __half* __restrict__ Ch,
    int M, int N, int K,
    size_t az, size_t bz, size_t cz)
{
    extern __shared__ __half sm[];

    A  += (size_t)blockIdx.z * az;
    Bh += (size_t)blockIdx.z * bz;
    Bl += (size_t)blockIdx.z * bz;
    if (C)  C  += (size_t)blockIdx.z * cz;
    if (Ch) Ch += (size_t)blockIdx.z * cz;

    int t = threadIdx.x;
    int lane = t & 31, wid = t >> 5;
    int wm = (wid & 1) * 64, wn = (wid >> 1) * 32;
    int rr = lane & 7, j = lane >> 3;
    int m0 = blockIdx.y * 128, n0 = blockIdx.x * 128;

    float acc[4][4][4];
#pragma unroll
    for (int i = 0; i < 4; i++)
#pragma unroll
        for (int jj = 0; jj < 4; jj++)
#pragma unroll
            for (int k = 0; k < 4; k++) acc[i][jj][k] = 0.0f;

    // cp.async mapping: thread -> row t>>1, 32-byte half-row t&1
    int srow = t >> 1, shalf = t & 1;
    bool aok = (m0 + srow) < M;
    const __half* Ap  = A + (size_t)(aok ? (m0 + srow) : 0) * lda + shalf * 16;
    const __half* Bhp = Bh + (size_t)(n0 + srow) * ldb + shalf * 16;
    const __half* Blp = Bl + (size_t)(n0 + srow) * ldb + shalf * 16;
    uint32_t abytes = aok ? 16u : 0u;
    uint32_t sm_u = smem_u32(sm);
    uint32_t sdst = (uint32_t)(srow * 80 + shalf * 32);

    // LDSM fragment offsets within a tile (bytes)
    uint32_t a_off[2][4];
#pragma unroll
    for (int kk = 0; kk < 2; kk++)
#pragma unroll
        for (int mf = 0; mf < 4; mf++)
            a_off[kk][mf] = (uint32_t)(((wm + mf * 16 + rr + (j & 1) * 8) * TROW
                                        + kk * 16 + (j >> 1) * 8) * 2);
    uint32_t b_off[2][2];
#pragma unroll
    for (int kk = 0; kk < 2; kk++)
#pragma unroll
        for (int p = 0; p < 2; p++)
            b_off[kk][p] = (uint32_t)(((wn + p * 16 + rr + (j >> 1) * 8) * TROW
                                       + kk * 16 + (j & 1) * 8) * 2);

#define ISSUE(stg, kt)                                                    \
    {   uint32_t base = sm_u + (stg) * STAGEB + sdst;                     \
        const __half* as = Ap + (kt);                                     \
        CP16(base, as, abytes); CP16(base + 16, as + 8, abytes);          \
        const __half* hs = Bhp + (kt);                                    \
        CP16(base + TILEB, hs, 16u); CP16(base + TILEB + 16, hs + 8, 16u);\
        const __half* ls = Blp + (kt);                                    \
        CP16(base + 2 * TILEB, ls, 16u);                                  \
        CP16(base + 2 * TILEB + 16, ls + 8, 16u);                         \
        CP_COMMIT(); }

    int NC = K / 32;
    ISSUE(0, 0);
    if (NC > 1) ISSUE(1, 32);

    for (int c = 0; c < NC; c++) {
        if (c + 1 < NC) { CP_WAIT(1); } else { CP_WAIT(0); }
        __syncthreads();
        if (c + 2 < NC) ISSUE((c + 2) % NSTAGE, (c + 2) * 32);

        uint32_t bb = sm_u + (c % NSTAGE) * STAGEB;
#pragma unroll
        for (int kk = 0; kk < 2; kk++) {
            uint32_t bhf[8], blf[8];
            LDSM4(bhf[0], bhf[1], bhf[2], bhf[3], bb + TILEB + b_off[kk][0]);
            LDSM4(bhf[4], bhf[5], bhf[6], bhf[7], bb + TILEB + b_off[kk][1]);
            LDSM4(blf[0], blf[1], blf[2], blf[3], bb + 2 * TILEB + b_off[kk][0]);
            LDSM4(blf[4], blf[5], blf[6], blf[7], bb + 2 * TILEB + b_off[kk][1]);
#pragma unroll
            for (int mf = 0; mf < 4; mf++) {
                uint32_t ahf[4];
                LDSM4(ahf[0], ahf[1], ahf[2], ahf[3], bb + a_off[kk][mf]);
#pragma unroll
                for (int nf = 0; nf < 4; nf++) {
                    MMA_F16(acc[mf][nf], ahf, bhf[nf * 2], bhf[nf * 2 + 1]);
                    MMA_F16(acc[mf][nf], ahf, blf[nf * 2], blf[nf * 2 + 1]);
                }
            }
        }
        __syncthreads();
    }

    // epilogue
    int er = lane >> 2, ec = (lane & 3) * 2;
#pragma unroll
    for (int nf = 0; nf < 4; nf++) {
        int col = n0 + wn + nf * 8 + ec;
        float bb0 = bias ? bias[col] : 0.0f;
        float bb1 = bias ? bias[col + 1] : 0.0f;
#pragma unroll
        for (int mf = 0; mf < 4; mf++) {
            int row = m0 + wm + mf * 16 + er;
            if (row < M) {
                float v0 = acc[mf][nf][0] + bb0, v1 = acc[mf][nf][1] + bb1;
                if (Ch)
                    *(__half2*)&Ch[(size_t)row * N + col]
                        = __halves2half2(__float2half(v0), __float2half(v1));
                else
                    *(float2*)&C[(size_t)row * N + col] = make_float2(v0, v1);
            }
            if (row + 8 < M) {
                float v0 = acc[mf][nf][2] + bb0, v1 = acc[mf][nf][3] + bb1;
                if (Ch)
                    *(__half2*)&Ch[(size_t)(row + 8) * N + col]
                        = __halves2half2(__float2half(v0), __float2half(v1));
                else
                    *(float2*)&C[(size_t)(row + 8) * N + col] = make_float2(v0, v1);
            }
        }
    }
}

// ---------------------------------------------------------------------------
// Pre-convert kernels
// ---------------------------------------------------------------------------
__global__ void cvt_h_kernel(const float* __restrict__ src,
                             __half* __restrict__ dst, size_t n)
{
    size_t i = (size_t)blockIdx.x * blockDim.x + threadIdx.x;
    if (i < n) dst[i] = __float2half(src[i]);
}

__global__ void split_w_kernel(const float* __restrict__ src,
                               __half* __restrict__ h, __half* __restrict__ l,
                               size_t n)
{
    size_t i = (size_t)blockIdx.x * blockDim.x + threadIdx.x;
    if (i < n) { __half hh, ll; split_h(src[i], hh, ll); h[i] = hh; l[i] = ll; }
}

// Tiled transpose + split: dstH/L[c*R + r] = split(src[r*C + c])
__global__ __launch_bounds__(256) void transpose_split(
    const float* __restrict__ src, __half* __restrict__ dh,
    __half* __restrict__ dl, int R, int C)
{
    __shared__ float tile[32][33];
    int cb = blockIdx.x * 32, rb = blockIdx.y * 32;
    int tx = threadIdx.x & 31, ty = threadIdx.x >> 5;
    for (int i = ty; i < 32; i += 8) {
        int r = rb + i, c = cb + tx;
        if (r < R && c < C) tile[i][tx] = src[(size_t)r * C + c];
    }
    __syncthreads();
    for (int i = ty; i < 32; i += 8) {
        int c = cb + i, r = rb + tx;
        if (c < C && r < R) {
            __half hh, ll; split_h(tile[tx][i], hh, ll);
            dh[(size_t)c * R + r] = hh;
            dl[(size_t)c * R + r] = ll;
        }
    }
}

// ---------------------------------------------------------------------------
// Adaptive pooling -> pooled[b][a*768 + c].  One block per (a, b).
// ---------------------------------------------------------------------------
__global__ __launch_bounds__(256) void pool_kernel(
    const __half* __restrict__ qkvh, const float* __restrict__ context,
    float* __restrict__ pooled)
{
    int a = blockIdx.x, b = blockIdx.y;
    int p = a / 7, q = a % 7;
    int sh = p * 32 / 7, eh = ((p + 1) * 32 + 6) / 7;
    int sw = q * 32 / 7, ew = ((q + 1) * 32 + 6) / 7;
    float inv = 1.0f / (float)((eh - sh) * (ew - sw));
    for (int c = threadIdx.x; c < CIN; c += 256) {
        float s = 0.0f;
        if (c < IC) {
            for (int hh = sh; hh < eh; hh++) {
                const __half* row = qkvh + ((size_t)(b * N_TOK) + hh * WW) * NQKV + c;
                for (int ww = sw; ww < ew; ww++)
                    s += __half2float(row[(size_t)ww * NQKV]);
            }
        } else {
            for (int hh = sh; hh < eh; hh++) {
                const float* row = context + ((size_t)(b * N_TOK) + hh * WW) * CC + (c - IC);
                for (int ww = sw; ww < ew; ww++) s += row[(size_t)ww * CC];
            }
        }
        pooled[((size_t)b * AG + a) * CIN + c] = s * inv;
    }
}

// im2col (fp16 out): col[(b*49+p)][ci*9+k9] = pooled[b][ci*49 + sy*7+sx]
__global__ void im2col_kernel(const float* __restrict__ pooled,
                              __half* __restrict__ col)
{
    size_t idx = (size_t)blockIdx.x * blockDim.x + threadIdx.x;
    if (idx >= (size_t)MCONV * KCONV) return;
    int ck = idx % KCONV;
    int row = idx / KCONV;
    int ci = ck / 9, k9 = ck % 9;
    int ky = k9 / 3, kx = k9 % 3;
    int b = row / AG, p = row % AG;
    int py = p / 7, px = p % 7;
    int sy = py + ky - 1, sx = px + kx - 1;
    float v = 0.0f;
    if (sy >= 0 && sy < 7 && sx >= 0 && sx < 7)
        v = pooled[(size_t)b * (AG * CIN) + ci * AG + sy * 7 + sx];
    col[idx] = __float2half(v);
}

// Reduce split-K partials + conv bias, transpose to agent_cs[b][c*49+s]
__global__ __launch_bounds__(256) void conv_reduce_tr(
    const float* __restrict__ parts, const float* __restrict__ conv_b,
    float* __restrict__ out)
{
    int b = blockIdx.x, cb = blockIdx.y * 64;
    __shared__ float tile[64][50];
    int t = threadIdx.x;
    for (int e = t; e < 64 * AG; e += 256) {
        int c = e & 63, s = e >> 6;
        float v = conv_b[cb + c];
#pragma unroll
        for (int p = 0; p < KSPLIT; p++)
            v += parts[(size_t)p * MCONV * IC + ((size_t)b * AG + s) * IC + cb + c];
        tile[c][s] = v;
    }
    __syncthreads();
    for (int e = t; e < 64 * AG; e += 256) {
        int s = e % AG, c = e / AG;
        out[(size_t)b * AGFLAT + (cb + c) * AG + s] = tile[c][s];
    }
}

// ---------------------------------------------------------------------------
// Bias tables
// ---------------------------------------------------------------------------
__device__ __forceinline__ float bilin7(const float* __restrict__ src, int yi, int xi)
{
    float fy = (yi + 0.5f) * (7.0f / 32.0f) - 0.5f;
    float fx = (xi + 0.5f) * (7.0f / 32.0f) - 0.5f;
    int y0 = (int)floorf(fy); float wy = fy - (float)y0;
    int x0 = (int)floorf(fx); float wx = fx - (float)x0;
    int y0c = max(y0, 0), y1c = min(y0 + 1, 6);
    int x0c = max(x0, 0), x1c = min(x0 + 1, 6);
    float v00 = src[y0c * 7 + x0c], v01 = src[y0c * 7 + x1c];
    float v10 = src[y1c * 7 + x0c], v11 = src[y1c * 7 + x1c];
    return (1.f - wy) * ((1.f - wx) * v00 + wx * v01)
         + wy * ((1.f - wx) * v10 + wx * v11);
}

__global__ void bias_an_kernel(const float* __restrict__ an_bias,
                               const float* __restrict__ ah_bias,
                               const float* __restrict__ aw_bias,
                               float* __restrict__ out)
{
    int idx = blockIdx.x * blockDim.x + threadIdx.x;
    if (idx >= NH * AG * N_TOK) return;
    int n = idx % N_TOK;
    int r = idx / N_TOK;
    int a = r % AG, h = r / AG;
    int hi = n >> 5, wi = n & 31;
    const float* src = an_bias + (size_t)(h * AG + a) * 49;
    float v = bilin7(src, hi, wi)
            + ah_bias[(h * AG + a) * 32 + hi]
            + aw_bias[(h * AG + a) * 32 + wi];
    out[idx] = v;
}

__global__ void bias_na_kernel(const float* __restrict__ na_bias,
                               const float* __restrict__ ha_bias,
                               const float* __restrict__ wa_bias,
                               float* __restrict__ out)
{
    int idx = blockIdx.x * blockDim.x + threadIdx.x;
    if (idx >= NH * N_TOK * AG) return;
    int a = idx % AG;
    int r = idx / AG;
    int n = r % N_TOK, h = r / N_TOK;
    int hi = n >> 5, wi = n & 31;
    const float* src = na_bias + (size_t)(h * AG + a) * 49;
    float v = bilin7(src, hi, wi)
            + ha_bias[(h * 32 + hi) * AG + a]
            + wa_bias[(h * 32 + wi) * AG + a];
    out[idx] = v;
}

// ---------------------------------------------------------------------------
// Fused agent attention: logits + online softmax + P@V in one kernel.
// One block per (b,h); 256 threads.
// ---------------------------------------------------------------------------
#define FO_AT 0
#define FO_KT 3136
#define FO_VT 7296
#define FO_SP 11392
#define FO_MR 14528
#define FO_LR 14577
#define FO_FR 14626
#define FO_PM 14675
#define FO_PS 14871
#define FLASH_SMEM ((FO_PS + 196) * 4)

__global__ __launch_bounds__(256) void agent_flash(
    const __half* __restrict__ qkvh, const float* __restrict__ agent_cs,
    const float* __restrict__ bias_an, float* __restrict__ agv)
{
    extern __shared__ float fs[];
    float* AT = fs + FO_AT;
    float* KT = fs + FO_KT;
    float* VT = fs + FO_VT;
    float* SP = fs + FO_SP;
    float* MR = fs + FO_MR;
    float* LR = fs + FO_LR;
    float* FR = fs + FO_FR;
    float* PM = fs + FO_PM;
    float* PS = fs + FO_PS;

    int b = blockIdx.x, h = blockIdx.y, t = threadIdx.x;
    int d = t & 63, ap = t >> 6;
    int rid = t >> 2, seg = t & 3;

    for (int e = t; e < AG * HD; e += 256) {
        int a = e >> 6, dd = e & 63;
        AT[e] = agent_cs[(size_t)b * AGFLAT + a * IC + h * HD + dd];
    }
    if (t < AG) { MR[t] = -1e30f; LR[t] = 0.0f; }

    float acc[13];
#pragma unroll
    for (int i = 0; i < 13; i++) acc[i] = 0.0f;

    for (int jt = 0; jt < N_TOK; jt += 64) {
        __syncthreads();
        for (int e = t; e < 64 * 64; e += 256) {
            int jj = e >> 6, dd = e & 63;
            const __half* row = qkvh + ((size_t)(b * N_TOK + jt + jj)) * NQKV + h * HD + dd;
            KT[jj * 65 + dd] = __half2float(row[IC]);
            VT[jj * 64 + dd] = __half2float(row[2 * IC]);
        }
        __syncthreads();

        {
            float part[13];
#pragma unroll
            for (int i = 0; i < 13; i++) part[i] = 0.0f;
#pragma unroll
            for (int dc = 0; dc < 4; dc++) {
                float kr[16];
#pragma unroll
                for (int i = 0; i < 16; i++) kr[i] = KT[d * 65 + dc * 16 + i];
#pragma unroll
                for (int ii = 0; ii < 13; ii++) {
                    int a = ap + ii * 4;
                    if (a < AG) {
                        float s = 0.0f;
#pragma unroll
                        for (int i = 0; i < 16; i++)
                            s += AT[a * 64 + dc * 16 + i] * kr[i];
                        part[ii] += s;
                    }
                }
            }
#pragma unroll
            for (int ii = 0; ii < 13; ii++) {
                int a = ap + ii * 4;
                if (a < AG)
                    SP[a * 64 + d] = part[ii] * 0.125f
                                   + bias_an[(h * AG + a) * N_TOK + jt + d];
            }
        }
        __syncthreads();

        if (rid < AG) {
            float pm = -1e30f;
            for (int jj = seg * 16; jj < seg * 16 + 16; jj++)
                pm = fmaxf(pm, SP[rid * 64 + jj]);
            PM[rid * 4 + seg] = pm;
        }
        __syncthreads();
        if (t < AG) {
            float mnew = fmaxf(fmaxf(PM[t * 4], PM[t * 4 + 1]),
                               fmaxf(PM[t * 4 + 2], PM[t * 4 + 3]));
            mnew = fmaxf(MR[t], mnew);
            FR[t] = __expf(MR[t] - mnew);
            MR[t] = mnew;
        }
        __syncthreads();
        if (rid < AG) {
            float m = MR[rid], ps = 0.0f;
            for (int jj = seg * 16; jj < seg * 16 + 16; jj++) {
                float e = __expf(SP[rid * 64 + jj] - m);
                SP[rid * 64 + jj] = e;
                ps += e;
            }
            PS[rid * 4 + seg] = ps;
        }
        __syncthreads();
        if (t < AG)
            LR[t] = LR[t] * FR[t]
                  + PS[t * 4] + PS[t * 4 + 1] + PS[t * 4 + 2] + PS[t * 4 + 3];
        __syncthreads();

#pragma unroll
        for (int ii = 0; ii < 13; ii++) {
            int a = ap + ii * 4;
            if (a < AG) acc[ii] *= FR[a];
        }
        for (int jj = 0; jj < 64; jj++) {
            float vj = VT[jj * 64 + d];
#pragma unroll
            for (int ii = 0; ii < 13; ii++) {
                int a = ap + ii * 4;
                if (a < AG) acc[ii] += SP[a * 64 + jj] * vj;
            }
        }
    }

#pragma unroll
    for (int ii = 0; ii < 13; ii++) {
        int a = ap + ii * 4;
        if (a < AG)
            agv[(((size_t)(b * NH + h) * AG) + a) * HD + d] = acc[ii] / LR[a];
    }
}

// ---------------------------------------------------------------------------
// Query attention + fused depthwise conv -> outh (fp16)
// Block (b,h,nt) covers tokens nt*64..+63, channels h*64..h*64+63 — exactly
// the (token, c) set dwc needs, so the 3x3 depthwise sum is fused here.
// ---------------------------------------------------------------------------
__global__ __launch_bounds__(64) void qattn_kernel(
    const __half* __restrict__ qkvh, const float* __restrict__ agent_cs,
    const float* __restrict__ agv, const float* __restrict__ bias_na,
    const float* __restrict__ dwc_w, const float* __restrict__ dwc_b,
    __half* __restrict__ outh)
{
    int b = blockIdx.x, h = blockIdx.y, nt = blockIdx.z;
    __shared__ float at_s[AG * HD];
    __shared__ float av_s[AG * HD];
    __shared__ float qs[64 * 65];
    int t = threadIdx.x;

    for (int e = t; e < AG * HD; e += 64) {
        int a = e >> 6, d = e & 63;
        at_s[e] = agent_cs[(size_t)b * AGFLAT + a * IC + h * HD + d];
        av_s[e] = agv[(((size_t)(b * NH + h) * AG) + a) * HD + d];
    }
    for (int e = t; e < 64 * 64; e += 64) {
        int nn = e >> 6, d = e & 63;
        qs[nn * 65 + d] = __half2float(
            qkvh[((size_t)(b * N_TOK) + nt * 64 + nn) * NQKV + h * HD + d]);
    }
    __syncthreads();

    int n = nt * 64 + t;
    float l[AG];
#pragma unroll
    for (int a = 0; a < AG; a++) l[a] = 0.0f;

#pragma unroll
    for (int dc = 0; dc < 4; dc++) {
        float qr[16];
#pragma unroll
        for (int i = 0; i < 16; i++) qr[i] = qs[t * 65 + dc * 16 + i];
#pragma unroll
        for (int a = 0; a < AG; a++) {
            float s = 0.0f;
#pragma unroll
            for (int i = 0; i < 16; i++) s += qr[i] * at_s[a * HD + dc * 16 + i];
            l[a] += s;
        }
    }
    const float* bn = bias_na + ((size_t)(h * N_TOK) + n) * AG;
    float m = -1e30f;
#pragma unroll
    for (int a = 0; a < AG; a++) { l[a] = l[a] * 0.125f + bn[a]; m = fmaxf(m, l[a]); }
    float ssum = 0.0f;
#pragma unroll
    for (int a = 0; a < AG; a++) { l[a] = __expf(l[a] - m); ssum += l[a]; }
    float inv = 1.0f / ssum;
#pragma unroll
    for (int a = 0; a < AG; a++) qs[t * 65 + a] = l[a] * inv;
    __syncthreads();

    // depthwise weights for this thread's channel
    int c = h * HD + t;
    float w9[9];
#pragma unroll
    for (int i = 0; i < 9; i++) w9[i] = dwc_w[c * 9 + i];
    float wb = dwc_b[c];
    const __half* vbase = qkvh + (size_t)(b * N_TOK) * NQKV + 2 * IC + c;

    int d = t;
    for (int nn = 0; nn < 64; nn++) {
        float s = 0.0f;
#pragma unroll
        for (int a = 0; a < AG; a++) s += qs[nn * 65 + a] * av_s[a * HD + d];

        // fused dwc for token (nt*64+nn), channel c
        int tok = nt * 64 + nn;
        int hh = tok >> 5, wcur = tok & 31;
        float dw = wb;
#pragma unroll
        for (int ky = 0; ky < 3; ky++) {
            int y = hh + ky - 1;
            if (y < 0 || y >= HH) continue;
#pragma unroll
            for (int kx = 0; kx < 3; kx++) {
                int x = wcur + kx - 1;
                if (x < 0 || x >= WW) continue;
                dw += w9[ky * 3 + kx]
                    * __half2float(vbase[(size_t)(y * WW + x) * NQKV]);
            }
        }
        outh[((size_t)(b * N_TOK) + tok) * IC + c] = __float2half(s + dw);
    }
}

// ---------------------------------------------------------------------------
// Host launcher
// ---------------------------------------------------------------------------
extern "C" void kernel_launch(void* const* d_in, const int* in_sizes, int n_in,
                              void* d_out, int out_size)
{
    const float* x       = (const float*)d_in[0];
    const float* context = (const float*)d_in[1];
    const float* Wq      = (const float*)d_in[2];
    const float* Wkv     = (const float*)d_in[3];
    const float* conv_w  = (const float*)d_in[4];
    const float* conv_b  = (const float*)d_in[5];
    const float* dwc_w   = (const float*)d_in[6];
    const float* dwc_b   = (const float*)d_in[7];
    const float* proj_w  = (const float*)d_in[8];
    const float* proj_b  = (const float*)d_in[9];
    const float* an_bias = (const float*)d_in[10];
    const float* na_bias = (const float*)d_in[11];
    const float* ah_bias = (const float*)d_in[12];
    const float* aw_bias = (const float*)d_in[13];
    const float* ha_bias = (const float*)d_in[14];
    const float* wa_bias = (const float*)d_in[15];
    float* out = (float*)d_out;

    float  *pooled, *convp, *agent_cs, *ban, *bna, *agv;
    __half *qkvh, *xh, *whT, *wlT, *pwhT, *pwlT, *cwh, *cwl, *colh, *outh;
    cudaGetSymbolAddress((void**)&qkvh,     g_qkvh);
    cudaGetSymbolAddress((void**)&xh,       g_xh);
    cudaGetSymbolAddress((void**)&whT,      g_whT);
    cudaGetSymbolAddress((void**)&wlT,      g_wlT);
    cudaGetSymbolAddress((void**)&pwhT,     g_pwhT);
    cudaGetSymbolAddress((void**)&pwlT,     g_pwlT);
    cudaGetSymbolAddress((void**)&cwh,      g_cwh);
    cudaGetSymbolAddress((void**)&cwl,      g_cwl);
    cudaGetSymbolAddress((void**)&pooled,   g_pooled);
    cudaGetSymbolAddress((void**)&colh,     g_colh);
    cudaGetSymbolAddress((void**)&convp,    g_convp);
    cudaGetSymbolAddress((void**)&agent_cs, g_agent_cs);
    cudaGetSymbolAddress((void**)&ban,      g_bias_an);
    cudaGetSymbolAddress((void**)&bna,      g_bias_na);
    cudaGetSymbolAddress((void**)&agv,      g_agv);
    cudaGetSymbolAddress((void**)&outh,     g_outh);

    cudaFuncSetAttribute(gemm_f16a,
                         cudaFuncAttributeMaxDynamicSharedMemorySize, GSMEM);
    cudaFuncSetAttribute(agent_flash,
                         cudaFuncAttributeMaxDynamicSharedMemorySize, FLASH_SMEM);

    // 1. operand prep: x->fp16; weights -> transposed hi/lo fp16
    {
        size_t nx = (size_t)B * N_TOK * DIM;
        cvt_h_kernel<<<(int)((nx + 255) / 256), 256>>>(x, xh, nx);
    }
    transpose_split<<<dim3(IC / 32, DIM / 32), 256>>>(Wq, whT, wlT, DIM, IC);
    transpose_split<<<dim3((2 * IC) / 32, DIM / 32), 256>>>(
        Wkv, whT + (size_t)IC * DIM, wlT + (size_t)IC * DIM, DIM, 2 * IC);
    transpose_split<<<dim3(IC / 32, DIM / 32), 256>>>(proj_w, pwhT, pwlT, DIM, IC);
    {
        size_t nc = (size_t)IC * KCONV;
        split_w_kernel<<<(int)((nc + 255) / 256), 256>>>(conv_w, cwh, cwl, nc);
    }

    // 2. fused QKV GEMM -> fp16 output
    gemm_f16a<<<dim3(NQKV / 128, (B * N_TOK) / 128, 1), 256, GSMEM>>>(
        xh, DIM, whT, wlT, DIM, nullptr, nullptr, qkvh,
        B * N_TOK, NQKV, DIM, 0, 0, 0);

    // 3. adaptive pool
    pool_kernel<<<dim3(AG, B), 256>>>(qkvh, context, pooled);

    // 4. conv: im2col(fp16) + split-K GEMM (z=split) + reduce
    im2col_kernel<<<(int)(((size_t)MCONV * KCONV + 255) / 256), 256>>>(pooled, colh);
    gemm_f16a<<<dim3(IC / 128, (MCONV + 127) / 128, KSPLIT), 256, GSMEM>>>(
        colh, KCONV, cwh, cwl, KCONV, nullptr, convp, nullptr,
        MCONV, IC, KSLAB,
        (size_t)KSLAB, (size_t)KSLAB, (size_t)MCONV * IC);
    conv_reduce_tr<<<dim3(B, IC / 64), 256>>>(convp, conv_b, agent_cs);

    // 5. bias tables
    bias_an_kernel<<<(NH * AG * N_TOK + 255) / 256, 256>>>(an_bias, ah_bias, aw_bias, ban);
    bias_na_kernel<<<(NH * N_TOK * AG + 255) / 256, 256>>>(na_bias, ha_bias, wa_bias, bna);

    // 6. fused agent attention
    agent_flash<<<dim3(B, NH), 256, FLASH_SMEM>>>(qkvh, agent_cs, ban, agv);

    // 7. query attention + fused dwc -> outh (fp16)
    qattn_kernel<<<dim3(B, NH, N_TOK / 64), 64>>>(
        qkvh, agent_cs, agv, bna, dwc_w, dwc_b, outh);

    // 8. output projection
    gemm_f16a<<<dim3(IC / 128, (B * N_TOK) / 128, 1), 256, GSMEM>>>(
        outh, IC, pwhT, pwlT, DIM, proj_b, out, nullptr,
        B * N_TOK, IC, DIM, 0, 0, 0);

    (void)in_sizes; (void)n_in; (void)out_size;
}

// round 10
// speedup vs baseline: 1.1190x; 1.1190x over previous
#include <cuda_runtime.h>
#include <cuda_fp16.h>
#include <cstdint>

// ---------------------------------------------------------------------------
// Problem constants
// ---------------------------------------------------------------------------
#define B 32
#define N_TOK 1024
#define DIM 512
#define IC 512
#define CC 256
#define NH 8
#define AG 49
#define HD 64
#define HH 32
#define WW 32
#define CIN 768            // IC + CC
#define KCONV 6912         // 768*9
#define MCONV 1568         // B*49
#define NQKV 1536          // IC + 2*IC
#define AGFLAT 25088       // IC*AG
#define KSPLIT 4
#define KSLAB 1728         // KCONV / KSPLIT

// ---------------------------------------------------------------------------
// Scratch (static device globals; no allocation allowed)
// ---------------------------------------------------------------------------
__device__ __half g_qkvh[(size_t)B * N_TOK * NQKV];          // [q|k|v] fp16
__device__ __half g_xh[(size_t)B * N_TOK * DIM];             // x in fp16
__device__ __half g_whT[(size_t)NQKV * DIM];                 // [j][k] hi
__device__ __half g_wlT[(size_t)NQKV * DIM];                 // [j][k] lo
__device__ __half g_pwhT[(size_t)IC * DIM];
__device__ __half g_pwlT[(size_t)IC * DIM];
__device__ __half g_cwh[(size_t)IC * KCONV];
__device__ __half g_cwl[(size_t)IC * KCONV];
__device__ float  g_pooled[(size_t)B * AG * CIN];
__device__ __half g_colh[(size_t)MCONV * KCONV];
__device__ float  g_convp[(size_t)KSPLIT * MCONV * IC];
__device__ float  g_agent_cs[(size_t)B * AGFLAT];
__device__ float  g_bias_an[NH * AG * N_TOK];
__device__ float  g_bias_na[NH * N_TOK * AG];
__device__ float  g_agv[(size_t)B * NH * AG * HD];
__device__ float  g_outpre[(size_t)B * N_TOK * IC];
__device__ __half g_outh[(size_t)B * N_TOK * IC];

// ---------------------------------------------------------------------------
// PTX helpers
// ---------------------------------------------------------------------------
#define LDSM4(r0, r1, r2, r3, addr)                                      \
    asm volatile("ldmatrix.sync.aligned.m8n8.x4.shared.b16 "             \
                 "{%0,%1,%2,%3}, [%4];"                                  \
                 : "=r"(r0), "=r"(r1), "=r"(r2), "=r"(r3) : "r"(addr))

#define MMA_F16(d, a, b0, b1)                                            \
    asm volatile(                                                        \
        "mma.sync.aligned.m16n8k16.row.col.f32.f16.f16.f32 "             \
        "{%0,%1,%2,%3}, {%4,%5,%6,%7}, {%8,%9}, {%0,%1,%2,%3};"          \
        : "+f"((d)[0]), "+f"((d)[1]), "+f"((d)[2]), "+f"((d)[3])         \
        : "r"((a)[0]), "r"((a)[1]), "r"((a)[2]), "r"((a)[3]),            \
          "r"(b0), "r"(b1))

#define CP16(dst, src, bytes)                                            \
    asm volatile("cp.async.ca.shared.global [%0], [%1], 16, %2;"         \
                 :: "r"(dst), "l"(src), "r"(bytes))
#define CP_COMMIT() asm volatile("cp.async.commit_group;")
#define CP_WAIT(n)  asm volatile("cp.async.wait_group %0;" :: "n"(n))

__device__ __forceinline__ uint32_t smem_u32(const void* p) {
    uint32_t a;
    asm("{ .reg .u64 t; cvta.to.shared.u64 t, %1; cvt.u32.u64 %0, t; }"
        : "=r"(a) : "l"(p));
    return a;
}

__device__ __forceinline__ void split_h(float v, __half& h, __half& l) {
    h = __float2half(v);
    l = __float2half(v - __half2float(h));
}

// ---------------------------------------------------------------------------
// fp16x2 tensor-core GEMM, cp.async 3-stage pipeline.
// C/Ch[M,N] = A[M,K] @ B'[N,K]^T (+bias).  A fp16 row-major (lda halves),
// B' pre-split hi/lo fp16 row-major (ldb halves), both K-contiguous.
// Output: fp32 to C if Ch==null, else fp16 to Ch.
// Block tile 128x128, K chunk 32, 8 warps of 64x32; 2 CTAs/SM.
// Requires N%128==0, K%32==0. M guarded. blockIdx.z adds az/bz/cz offsets.
// ---------------------------------------------------------------------------
#define TROW   40                  // padded row stride in halves (80 bytes)
#define TILEB  10240               // 128 * 80 bytes
#define STAGEB (3 * TILEB)         // Ah | Bh | Bl
#define NSTAGE 3
#define GSMEM  (NSTAGE * STAGEB)   // 92160 bytes

__global__ __launch_bounds__(256, 2) void gemm_f16a(
    const __half* __restrict__ A, int lda,
    const __half* __restrict__ Bh, const __half* __restrict__ Bl, int ldb,
    const float* __restrict__ bias, float* __restrict__ C,
    __half* __restrict__ Ch,
    int M, int N, int K,
    size_t az, size_t bz, size_t cz)
{
    extern __shared__ __half sm[];

    A  += (size_t)blockIdx.z * az;
    Bh += (size_t)blockIdx.z * bz;
    Bl += (size_t)blockIdx.z * bz;
    if (C)  C  += (size_t)blockIdx.z * cz;
    if (Ch) Ch += (size_t)blockIdx.z * cz;

    int t = threadIdx.x;
    int lane = t & 31, wid = t >> 5;
    int wm = (wid & 1) * 64, wn = (wid >> 1) * 32;
    int rr = lane & 7, j = lane >> 3;
    int m0 = blockIdx.y * 128, n0 = blockIdx.x * 128;

    float acc[4][4][4];
#pragma unroll
    for (int i = 0; i < 4; i++)
#pragma unroll
        for (int jj = 0; jj < 4; jj++)
#pragma unroll
            for (int k = 0; k < 4; k++) acc[i][jj][k] = 0.0f;

    // cp.async mapping: thread -> row t>>1, 32-byte half-row t&1
    int srow = t >> 1, shalf = t & 1;
    bool aok = (m0 + srow) < M;
    const __half* Ap  = A + (size_t)(aok ? (m0 + srow) : 0) * lda + shalf * 16;
    const __half* Bhp = Bh + (size_t)(n0 + srow) * ldb + shalf * 16;
    const __half* Blp = Bl + (size_t)(n0 + srow) * ldb + shalf * 16;
    uint32_t abytes = aok ? 16u : 0u;
    uint32_t sm_u = smem_u32(sm);
    uint32_t sdst = (uint32_t)(srow * 80 + shalf * 32);

    // LDSM fragment offsets within a tile (bytes)
    uint32_t a_off[2][4];
#pragma unroll
    for (int kk = 0; kk < 2; kk++)
#pragma unroll
        for (int mf = 0; mf < 4; mf++)
            a_off[kk][mf] = (uint32_t)(((wm + mf * 16 + rr + (j & 1) * 8) * TROW
                                        + kk * 16 + (j >> 1) * 8) * 2);
    uint32_t b_off[2][2];
#pragma unroll
    for (int kk = 0; kk < 2; kk++)
#pragma unroll
        for (int p = 0; p < 2; p++)
            b_off[kk][p] = (uint32_t)(((wn + p * 16 + rr + (j >> 1) * 8) * TROW
                                       + kk * 16 + (j & 1) * 8) * 2);

#define ISSUE(stg, kt)                                                    \
    {   uint32_t base = sm_u + (stg) * STAGEB + sdst;                     \
        const __half* as = Ap + (kt);                                     \
        CP16(base, as, abytes); CP16(base + 16, as + 8, abytes);          \
        const __half* hs = Bhp + (kt);                                    \
        CP16(base + TILEB, hs, 16u); CP16(base + TILEB + 16, hs + 8, 16u);\
        const __half* ls = Blp + (kt);                                    \
        CP16(base + 2 * TILEB, ls, 16u);                                  \
        CP16(base + 2 * TILEB + 16, ls + 8, 16u);                         \
        CP_COMMIT(); }

    int NC = K / 32;
    ISSUE(0, 0);
    if (NC > 1) ISSUE(1, 32);

    for (int c = 0; c < NC; c++) {
        if (c + 1 < NC) { CP_WAIT(1); } else { CP_WAIT(0); }
        __syncthreads();
        if (c + 2 < NC) ISSUE((c + 2) % NSTAGE, (c + 2) * 32);

        uint32_t bb = sm_u + (c % NSTAGE) * STAGEB;
#pragma unroll
        for (int kk = 0; kk < 2; kk++) {
            uint32_t bhf[8], blf[8];
            LDSM4(bhf[0], bhf[1], bhf[2], bhf[3], bb + TILEB + b_off[kk][0]);
            LDSM4(bhf[4], bhf[5], bhf[6], bhf[7], bb + TILEB + b_off[kk][1]);
            LDSM4(blf[0], blf[1], blf[2], blf[3], bb + 2 * TILEB + b_off[kk][0]);
            LDSM4(blf[4], blf[5], blf[6], blf[7], bb + 2 * TILEB + b_off[kk][1]);
#pragma unroll
            for (int mf = 0; mf < 4; mf++) {
                uint32_t ahf[4];
                LDSM4(ahf[0], ahf[1], ahf[2], ahf[3], bb + a_off[kk][mf]);
#pragma unroll
                for (int nf = 0; nf < 4; nf++) {
                    MMA_F16(acc[mf][nf], ahf, bhf[nf * 2], bhf[nf * 2 + 1]);
                    MMA_F16(acc[mf][nf], ahf, blf[nf * 2], blf[nf * 2 + 1]);
                }
            }
        }
        __syncthreads();
    }

    // epilogue
    int er = lane >> 2, ec = (lane & 3) * 2;
#pragma unroll
    for (int nf = 0; nf < 4; nf++) {
        int col = n0 + wn + nf * 8 + ec;
        float bb0 = bias ? bias[col] : 0.0f;
        float bb1 = bias ? bias[col + 1] : 0.0f;
#pragma unroll
        for (int mf = 0; mf < 4; mf++) {
            int row = m0 + wm + mf * 16 + er;
            if (row < M) {
                float v0 = acc[mf][nf][0] + bb0, v1 = acc[mf][nf][1] + bb1;
                if (Ch)
                    *(__half2*)&Ch[(size_t)row * N + col]
                        = __halves2half2(__float2half(v0), __float2half(v1));
                else
                    *(float2*)&C[(size_t)row * N + col] = make_float2(v0, v1);
            }
            if (row + 8 < M) {
                float v0 = acc[mf][nf][2] + bb0, v1 = acc[mf][nf][3] + bb1;
                if (Ch)
                    *(__half2*)&Ch[(size_t)(row + 8) * N + col]
                        = __halves2half2(__float2half(v0), __float2half(v1));
                else
                    *(float2*)&C[(size_t)(row + 8) * N + col] = make_float2(v0, v1);
            }
        }
    }
}

// ---------------------------------------------------------------------------
// Pre-convert kernels
// ---------------------------------------------------------------------------
__global__ void cvt_h_kernel(const float* __restrict__ src,
                             __half* __restrict__ dst, size_t n)
{
    size_t i = (size_t)blockIdx.x * blockDim.x + threadIdx.x;
    if (i < n) dst[i] = __float2half(src[i]);
}

__global__ void split_w_kernel(const float* __restrict__ src,
                               __half* __restrict__ h, __half* __restrict__ l,
                               size_t n)
{
    size_t i = (size_t)blockIdx.x * blockDim.x + threadIdx.x;
    if (i < n) { __half hh, ll; split_h(src[i], hh, ll); h[i] = hh; l[i] = ll; }
}

// Tiled transpose + split: dstH/L[c*R + r] = split(src[r*C + c])
__global__ __launch_bounds__(256) void transpose_split(
    const float* __restrict__ src, __half* __restrict__ dh,
    __half* __restrict__ dl, int R, int C)
{
    __shared__ float tile[32][33];
    int cb = blockIdx.x * 32, rb = blockIdx.y * 32;
    int tx = threadIdx.x & 31, ty = threadIdx.x >> 5;
    for (int i = ty; i < 32; i += 8) {
        int r = rb + i, c = cb + tx;
        if (r < R && c < C) tile[i][tx] = src[(size_t)r * C + c];
    }
    __syncthreads();
    for (int i = ty; i < 32; i += 8) {
        int c = cb + i, r = rb + tx;
        if (c < C && r < R) {
            __half hh, ll; split_h(tile[tx][i], hh, ll);
            dh[(size_t)c * R + r] = hh;
            dl[(size_t)c * R + r] = ll;
        }
    }
}

// ---------------------------------------------------------------------------
// Adaptive pooling -> pooled[b][a*768 + c].  One block per (a, b).
// ---------------------------------------------------------------------------
__global__ __launch_bounds__(256) void pool_kernel(
    const __half* __restrict__ qkvh, const float* __restrict__ context,
    float* __restrict__ pooled)
{
    int a = blockIdx.x, b = blockIdx.y;
    int p = a / 7, q = a % 7;
    int sh = p * 32 / 7, eh = ((p + 1) * 32 + 6) / 7;
    int sw = q * 32 / 7, ew = ((q + 1) * 32 + 6) / 7;
    float inv = 1.0f / (float)((eh - sh) * (ew - sw));
    for (int c = threadIdx.x; c < CIN; c += 256) {
        float s = 0.0f;
        if (c < IC) {
            for (int hh = sh; hh < eh; hh++) {
                const __half* row = qkvh + ((size_t)(b * N_TOK) + hh * WW) * NQKV + c;
                for (int ww = sw; ww < ew; ww++)
                    s += __half2float(row[(size_t)ww * NQKV]);
            }
        } else {
            for (int hh = sh; hh < eh; hh++) {
                const float* row = context + ((size_t)(b * N_TOK) + hh * WW) * CC + (c - IC);
                for (int ww = sw; ww < ew; ww++) s += row[(size_t)ww * CC];
            }
        }
        pooled[((size_t)b * AG + a) * CIN + c] = s * inv;
    }
}

// im2col (fp16 out): col[(b*49+p)][ci*9+k9] = pooled[b][ci*49 + sy*7+sx]
__global__ void im2col_kernel(const float* __restrict__ pooled,
                              __half* __restrict__ col)
{
    size_t idx = (size_t)blockIdx.x * blockDim.x + threadIdx.x;
    if (idx >= (size_t)MCONV * KCONV) return;
    int ck = idx % KCONV;
    int row = idx / KCONV;
    int ci = ck / 9, k9 = ck % 9;
    int ky = k9 / 3, kx = k9 % 3;
    int b = row / AG, p = row % AG;
    int py = p / 7, px = p % 7;
    int sy = py + ky - 1, sx = px + kx - 1;
    float v = 0.0f;
    if (sy >= 0 && sy < 7 && sx >= 0 && sx < 7)
        v = pooled[(size_t)b * (AG * CIN) + ci * AG + sy * 7 + sx];
    col[idx] = __float2half(v);
}

// Reduce split-K partials + conv bias, transpose to agent_cs[b][c*49+s]
__global__ __launch_bounds__(256) void conv_reduce_tr(
    const float* __restrict__ parts, const float* __restrict__ conv_b,
    float* __restrict__ out)
{
    int b = blockIdx.x, cb = blockIdx.y * 64;
    __shared__ float tile[64][50];
    int t = threadIdx.x;
    for (int e = t; e < 64 * AG; e += 256) {
        int c = e & 63, s = e >> 6;
        float v = conv_b[cb + c];
#pragma unroll
        for (int p = 0; p < KSPLIT; p++)
            v += parts[(size_t)p * MCONV * IC + ((size_t)b * AG + s) * IC + cb + c];
        tile[c][s] = v;
    }
    __syncthreads();
    for (int e = t; e < 64 * AG; e += 256) {
        int s = e % AG, c = e / AG;
        out[(size_t)b * AGFLAT + (cb + c) * AG + s] = tile[c][s];
    }
}

// ---------------------------------------------------------------------------
// Bias tables
// ---------------------------------------------------------------------------
__device__ __forceinline__ float bilin7(const float* __restrict__ src, int yi, int xi)
{
    float fy = (yi + 0.5f) * (7.0f / 32.0f) - 0.5f;
    float fx = (xi + 0.5f) * (7.0f / 32.0f) - 0.5f;
    int y0 = (int)floorf(fy); float wy = fy - (float)y0;
    int x0 = (int)floorf(fx); float wx = fx - (float)x0;
    int y0c = max(y0, 0), y1c = min(y0 + 1, 6);
    int x0c = max(x0, 0), x1c = min(x0 + 1, 6);
    float v00 = src[y0c * 7 + x0c], v01 = src[y0c * 7 + x1c];
    float v10 = src[y1c * 7 + x0c], v11 = src[y1c * 7 + x1c];
    return (1.f - wy) * ((1.f - wx) * v00 + wx * v01)
         + wy * ((1.f - wx) * v10 + wx * v11);
}

__global__ void bias_an_kernel(const float* __restrict__ an_bias,
                               const float* __restrict__ ah_bias,
                               const float* __restrict__ aw_bias,
                               float* __restrict__ out)
{
    int idx = blockIdx.x * blockDim.x + threadIdx.x;
    if (idx >= NH * AG * N_TOK) return;
    int n = idx % N_TOK;
    int r = idx / N_TOK;
    int a = r % AG, h = r / AG;
    int hi = n >> 5, wi = n & 31;
    const float* src = an_bias + (size_t)(h * AG + a) * 49;
    float v = bilin7(src, hi, wi)
            + ah_bias[(h * AG + a) * 32 + hi]
            + aw_bias[(h * AG + a) * 32 + wi];
    out[idx] = v;
}

__global__ void bias_na_kernel(const float* __restrict__ na_bias,
                               const float* __restrict__ ha_bias,
                               const float* __restrict__ wa_bias,
                               float* __restrict__ out)
{
    int idx = blockIdx.x * blockDim.x + threadIdx.x;
    if (idx >= NH * N_TOK * AG) return;
    int a = idx % AG;
    int r = idx / AG;
    int n = r % N_TOK, h = r / N_TOK;
    int hi = n >> 5, wi = n & 31;
    const float* src = na_bias + (size_t)(h * AG + a) * 49;
    float v = bilin7(src, hi, wi)
            + ha_bias[(h * 32 + hi) * AG + a]
            + wa_bias[(h * 32 + wi) * AG + a];
    out[idx] = v;
}

// ---------------------------------------------------------------------------
// Fused agent attention: logits + online softmax + P@V in one kernel.
// One block per (b,h); 256 threads.
// ---------------------------------------------------------------------------
#define FO_AT 0
#define FO_KT 3136
#define FO_VT 7296
#define FO_SP 11392
#define FO_MR 14528
#define FO_LR 14577
#define FO_FR 14626
#define FO_PM 14675
#define FO_PS 14871
#define FLASH_SMEM ((FO_PS + 196) * 4)

__global__ __launch_bounds__(256) void agent_flash(
    const __half* __restrict__ qkvh, const float* __restrict__ agent_cs,
    const float* __restrict__ bias_an, float* __restrict__ agv)
{
    extern __shared__ float fs[];
    float* AT = fs + FO_AT;
    float* KT = fs + FO_KT;
    float* VT = fs + FO_VT;
    float* SP = fs + FO_SP;
    float* MR = fs + FO_MR;
    float* LR = fs + FO_LR;
    float* FR = fs + FO_FR;
    float* PM = fs + FO_PM;
    float* PS = fs + FO_PS;

    int b = blockIdx.x, h = blockIdx.y, t = threadIdx.x;
    int d = t & 63, ap = t >> 6;
    int rid = t >> 2, seg = t & 3;

    for (int e = t; e < AG * HD; e += 256) {
        int a = e >> 6, dd = e & 63;
        AT[e] = agent_cs[(size_t)b * AGFLAT + a * IC + h * HD + dd];
    }
    if (t < AG) { MR[t] = -1e30f; LR[t] = 0.0f; }

    float acc[13];
#pragma unroll
    for (int i = 0; i < 13; i++) acc[i] = 0.0f;

    for (int jt = 0; jt < N_TOK; jt += 64) {
        __syncthreads();
        for (int e = t; e < 64 * 64; e += 256) {
            int jj = e >> 6, dd = e & 63;
            const __half* row = qkvh + ((size_t)(b * N_TOK + jt + jj)) * NQKV + h * HD + dd;
            KT[jj * 65 + dd] = __half2float(row[IC]);
            VT[jj * 64 + dd] = __half2float(row[2 * IC]);
        }
        __syncthreads();

        {
            float part[13];
#pragma unroll
            for (int i = 0; i < 13; i++) part[i] = 0.0f;
#pragma unroll
            for (int dc = 0; dc < 4; dc++) {
                float kr[16];
#pragma unroll
                for (int i = 0; i < 16; i++) kr[i] = KT[d * 65 + dc * 16 + i];
#pragma unroll
                for (int ii = 0; ii < 13; ii++) {
                    int a = ap + ii * 4;
                    if (a < AG) {
                        float s = 0.0f;
#pragma unroll
                        for (int i = 0; i < 16; i++)
                            s += AT[a * 64 + dc * 16 + i] * kr[i];
                        part[ii] += s;
                    }
                }
            }
#pragma unroll
            for (int ii = 0; ii < 13; ii++) {
                int a = ap + ii * 4;
                if (a < AG)
                    SP[a * 64 + d] = part[ii] * 0.125f
                                   + bias_an[(h * AG + a) * N_TOK + jt + d];
            }
        }
        __syncthreads();

        if (rid < AG) {
            float pm = -1e30f;
            for (int jj = seg * 16; jj < seg * 16 + 16; jj++)
                pm = fmaxf(pm, SP[rid * 64 + jj]);
            PM[rid * 4 + seg] = pm;
        }
        __syncthreads();
        if (t < AG) {
            float mnew = fmaxf(fmaxf(PM[t * 4], PM[t * 4 + 1]),
                               fmaxf(PM[t * 4 + 2], PM[t * 4 + 3]));
            mnew = fmaxf(MR[t], mnew);
            FR[t] = __expf(MR[t] - mnew);
            MR[t] = mnew;
        }
        __syncthreads();
        if (rid < AG) {
            float m = MR[rid], ps = 0.0f;
            for (int jj = seg * 16; jj < seg * 16 + 16; jj++) {
                float e = __expf(SP[rid * 64 + jj] - m);
                SP[rid * 64 + jj] = e;
                ps += e;
            }
            PS[rid * 4 + seg] = ps;
        }
        __syncthreads();
        if (t < AG)
            LR[t] = LR[t] * FR[t]
                  + PS[t * 4] + PS[t * 4 + 1] + PS[t * 4 + 2] + PS[t * 4 + 3];
        __syncthreads();

#pragma unroll
        for (int ii = 0; ii < 13; ii++) {
            int a = ap + ii * 4;
            if (a < AG) acc[ii] *= FR[a];
        }
        for (int jj = 0; jj < 64; jj++) {
            float vj = VT[jj * 64 + d];
#pragma unroll
            for (int ii = 0; ii < 13; ii++) {
                int a = ap + ii * 4;
                if (a < AG) acc[ii] += SP[a * 64 + jj] * vj;
            }
        }
    }

#pragma unroll
    for (int ii = 0; ii < 13; ii++) {
        int a = ap + ii * 4;
        if (a < AG)
            agv[(((size_t)(b * NH + h) * AG) + a) * HD + d] = acc[ii] / LR[a];
    }
}

// ---------------------------------------------------------------------------
// Query attention -> outpre (fp32)
// ---------------------------------------------------------------------------
__global__ __launch_bounds__(64) void qattn_kernel(
    const __half* __restrict__ qkvh, const float* __restrict__ agent_cs,
    const float* __restrict__ agv, const float* __restrict__ bias_na,
    float* __restrict__ outpre)
{
    int b = blockIdx.x, h = blockIdx.y, nt = blockIdx.z;
    __shared__ float at_s[AG * HD];
    __shared__ float av_s[AG * HD];
    __shared__ float qs[64 * 65];
    int t = threadIdx.x;

    for (int e = t; e < AG * HD; e += 64) {
        int a = e >> 6, d = e & 63;
        at_s[e] = agent_cs[(size_t)b * AGFLAT + a * IC + h * HD + d];
        av_s[e] = agv[(((size_t)(b * NH + h) * AG) + a) * HD + d];
    }
    for (int e = t; e < 64 * 64; e += 64) {
        int nn = e >> 6, d = e & 63;
        qs[nn * 65 + d] = __half2float(
            qkvh[((size_t)(b * N_TOK) + nt * 64 + nn) * NQKV + h * HD + d]);
    }
    __syncthreads();

    int n = nt * 64 + t;
    float l[AG];
#pragma unroll
    for (int a = 0; a < AG; a++) l[a] = 0.0f;

#pragma unroll
    for (int dc = 0; dc < 4; dc++) {
        float qr[16];
#pragma unroll
        for (int i = 0; i < 16; i++) qr[i] = qs[t * 65 + dc * 16 + i];
#pragma unroll
        for (int a = 0; a < AG; a++) {
            float s = 0.0f;
#pragma unroll
            for (int i = 0; i < 16; i++) s += qr[i] * at_s[a * HD + dc * 16 + i];
            l[a] += s;
        }
    }
    const float* bn = bias_na + ((size_t)(h * N_TOK) + n) * AG;
    float m = -1e30f;
#pragma unroll
    for (int a = 0; a < AG; a++) { l[a] = l[a] * 0.125f + bn[a]; m = fmaxf(m, l[a]); }
    float ssum = 0.0f;
#pragma unroll
    for (int a = 0; a < AG; a++) { l[a] = __expf(l[a] - m); ssum += l[a]; }
    float inv = 1.0f / ssum;
#pragma unroll
    for (int a = 0; a < AG; a++) qs[t * 65 + a] = l[a] * inv;
    __syncthreads();

    int d = t;
    for (int nn = 0; nn < 64; nn++) {
        float s = 0.0f;
#pragma unroll
        for (int a = 0; a < AG; a++) s += qs[nn * 65 + a] * av_s[a * HD + d];
        outpre[((size_t)(b * N_TOK) + nt * 64 + nn) * IC + h * HD + d] = s;
    }
}

// Depthwise 3x3 conv on v image (fp16), fused add + fp16 convert -> outh.
__global__ void dwc_kernel(const __half* __restrict__ qkvh,
                           const float* __restrict__ dwc_w,
                           const float* __restrict__ dwc_b,
                           const float* __restrict__ outpre,
                           __half* __restrict__ outh)
{
    int n = blockIdx.x;
    int b = blockIdx.y;
    int c = blockIdx.z * 128 + threadIdx.x;
    int hh = n >> 5, wcur = n & 31;
    float s = dwc_b[c];
#pragma unroll
    for (int ky = 0; ky < 3; ky++) {
        int y = hh + ky - 1;
        if (y < 0 || y >= HH) continue;
#pragma unroll
        for (int kx = 0; kx < 3; kx++) {
            int x = wcur + kx - 1;
            if (x < 0 || x >= WW) continue;
            s += dwc_w[c * 9 + ky * 3 + kx]
               * __half2float(
                     qkvh[((size_t)(b * N_TOK) + y * WW + x) * NQKV + 2 * IC + c]);
        }
    }
    size_t i = ((size_t)(b * N_TOK) + n) * IC + c;
    outh[i] = __float2half(outpre[i] + s);
}

// ---------------------------------------------------------------------------
// Host launcher
// ---------------------------------------------------------------------------
extern "C" void kernel_launch(void* const* d_in, const int* in_sizes, int n_in,
                              void* d_out, int out_size)
{
    const float* x       = (const float*)d_in[0];
    const float* context = (const float*)d_in[1];
    const float* Wq      = (const float*)d_in[2];
    const float* Wkv     = (const float*)d_in[3];
    const float* conv_w  = (const float*)d_in[4];
    const float* conv_b  = (const float*)d_in[5];
    const float* dwc_w   = (const float*)d_in[6];
    const float* dwc_b   = (const float*)d_in[7];
    const float* proj_w  = (const float*)d_in[8];
    const float* proj_b  = (const float*)d_in[9];
    const float* an_bias = (const float*)d_in[10];
    const float* na_bias = (const float*)d_in[11];
    const float* ah_bias = (const float*)d_in[12];
    const float* aw_bias = (const float*)d_in[13];
    const float* ha_bias = (const float*)d_in[14];
    const float* wa_bias = (const float*)d_in[15];
    float* out = (float*)d_out;

    float  *pooled, *convp, *agent_cs, *ban, *bna, *agv, *outpre;
    __half *qkvh, *xh, *whT, *wlT, *pwhT, *pwlT, *cwh, *cwl, *colh, *outh;
    cudaGetSymbolAddress((void**)&qkvh,     g_qkvh);
    cudaGetSymbolAddress((void**)&xh,       g_xh);
    cudaGetSymbolAddress((void**)&whT,      g_whT);
    cudaGetSymbolAddress((void**)&wlT,      g_wlT);
    cudaGetSymbolAddress((void**)&pwhT,     g_pwhT);
    cudaGetSymbolAddress((void**)&pwlT,     g_pwlT);
    cudaGetSymbolAddress((void**)&cwh,      g_cwh);
    cudaGetSymbolAddress((void**)&cwl,      g_cwl);
    cudaGetSymbolAddress((void**)&pooled,   g_pooled);
    cudaGetSymbolAddress((void**)&colh,     g_colh);
    cudaGetSymbolAddress((void**)&convp,    g_convp);
    cudaGetSymbolAddress((void**)&agent_cs, g_agent_cs);
    cudaGetSymbolAddress((void**)&ban,      g_bias_an);
    cudaGetSymbolAddress((void**)&bna,      g_bias_na);
    cudaGetSymbolAddress((void**)&agv,      g_agv);
    cudaGetSymbolAddress((void**)&outpre,   g_outpre);
    cudaGetSymbolAddress((void**)&outh,     g_outh);

    cudaFuncSetAttribute(gemm_f16a,
                         cudaFuncAttributeMaxDynamicSharedMemorySize, GSMEM);
    cudaFuncSetAttribute(agent_flash,
                         cudaFuncAttributeMaxDynamicSharedMemorySize, FLASH_SMEM);

    // 1. operand prep: x->fp16; weights -> transposed hi/lo fp16
    {
        size_t nx = (size_t)B * N_TOK * DIM;
        cvt_h_kernel<<<(int)((nx + 255) / 256), 256>>>(x, xh, nx);
    }
    transpose_split<<<dim3(IC / 32, DIM / 32), 256>>>(Wq, whT, wlT, DIM, IC);
    transpose_split<<<dim3((2 * IC) / 32, DIM / 32), 256>>>(
        Wkv, whT + (size_t)IC * DIM, wlT + (size_t)IC * DIM, DIM, 2 * IC);
    transpose_split<<<dim3(IC / 32, DIM / 32), 256>>>(proj_w, pwhT, pwlT, DIM, IC);
    {
        size_t nc = (size_t)IC * KCONV;
        split_w_kernel<<<(int)((nc + 255) / 256), 256>>>(conv_w, cwh, cwl, nc);
    }

    // 2. fused QKV GEMM -> fp16 output
    gemm_f16a<<<dim3(NQKV / 128, (B * N_TOK) / 128, 1), 256, GSMEM>>>(
        xh, DIM, whT, wlT, DIM, nullptr, nullptr, qkvh,
        B * N_TOK, NQKV, DIM, 0, 0, 0);

    // 3. adaptive pool
    pool_kernel<<<dim3(AG, B), 256>>>(qkvh, context, pooled);

    // 4. conv: im2col(fp16) + split-K GEMM (z=split) + reduce
    im2col_kernel<<<(int)(((size_t)MCONV * KCONV + 255) / 256), 256>>>(pooled, colh);
    gemm_f16a<<<dim3(IC / 128, (MCONV + 127) / 128, KSPLIT), 256, GSMEM>>>(
        colh, KCONV, cwh, cwl, KCONV, nullptr, convp, nullptr,
        MCONV, IC, KSLAB,
        (size_t)KSLAB, (size_t)KSLAB, (size_t)MCONV * IC);
    conv_reduce_tr<<<dim3(B, IC / 64), 256>>>(convp, conv_b, agent_cs);

    // 5. bias tables
    bias_an_kernel<<<(NH * AG * N_TOK + 255) / 256, 256>>>(an_bias, ah_bias, aw_bias, ban);
    bias_na_kernel<<<(NH * N_TOK * AG + 255) / 256, 256>>>(na_bias, ha_bias, wa_bias, bna);

    // 6. fused agent attention
    agent_flash<<<dim3(B, NH), 256, FLASH_SMEM>>>(qkvh, agent_cs, ban, agv);

    // 7. query attention -> outpre (fp32)
    qattn_kernel<<<dim3(B, NH, N_TOK / 64), 64>>>(qkvh, agent_cs, agv, bna, outpre);

    // 8. depthwise conv residual (separate, high-parallelism) -> outh (fp16)
    dwc_kernel<<<dim3(N_TOK, B, IC / 128), 128>>>(qkvh, dwc_w, dwc_b, outpre, outh);

    // 9. output projection
    gemm_f16a<<<dim3(IC / 128, (B * N_TOK) / 128, 1), 256, GSMEM>>>(
        outh, IC, pwhT, pwlT, DIM, proj_b, out, nullptr,
        B * N_TOK, IC, DIM, 0, 0, 0);

    (void)in_sizes; (void)n_in; (void)out_size;
}

// round 11
// speedup vs baseline: 1.4680x; 1.3119x over previous
#include <cuda_runtime.h>
#include <cuda_fp16.h>
#include <cstdint>

// ---------------------------------------------------------------------------
// Problem constants
// ---------------------------------------------------------------------------
#define B 32
#define N_TOK 1024
#define DIM 512
#define IC 512
#define CC 256
#define NH 8
#define AG 49
#define HD 64
#define HH 32
#define WW 32
#define CIN 768            // IC + CC
#define KCONV 6912         // 768*9
#define MCONV 1568         // B*49
#define NQKV 1536          // IC + 2*IC
#define AGFLAT 25088       // IC*AG
#define KSPLIT 4
#define KSLAB 1728         // KCONV / KSPLIT

// ---------------------------------------------------------------------------
// Scratch (static device globals; no allocation allowed)
// ---------------------------------------------------------------------------
__device__ __half g_qkvh[(size_t)B * N_TOK * NQKV];          // [q|k|v] fp16
__device__ __half g_xh[(size_t)B * N_TOK * DIM];             // x in fp16
__device__ __half g_whT[(size_t)NQKV * DIM];                 // [j][k] hi
__device__ __half g_wlT[(size_t)NQKV * DIM];                 // [j][k] lo
__device__ __half g_pwhT[(size_t)IC * DIM];
__device__ __half g_pwlT[(size_t)IC * DIM];
__device__ __half g_cwh[(size_t)IC * KCONV];
__device__ __half g_cwl[(size_t)IC * KCONV];
__device__ float  g_pooled[(size_t)B * AG * CIN];
__device__ __half g_colh[(size_t)MCONV * KCONV];
__device__ float  g_convp[(size_t)KSPLIT * MCONV * IC];
__device__ float  g_agent_cs[(size_t)B * AGFLAT];
__device__ float  g_bias_an[NH * AG * N_TOK];
__device__ float  g_bias_na[NH * N_TOK * AG];
__device__ float  g_agv[(size_t)B * NH * AG * HD];
__device__ float  g_outpre[(size_t)B * N_TOK * IC];
__device__ __half g_outh[(size_t)B * N_TOK * IC];

// ---------------------------------------------------------------------------
// PTX helpers
// ---------------------------------------------------------------------------
#define LDSM4(r0, r1, r2, r3, addr)                                      \
    asm volatile("ldmatrix.sync.aligned.m8n8.x4.shared.b16 "             \
                 "{%0,%1,%2,%3}, [%4];"                                  \
                 : "=r"(r0), "=r"(r1), "=r"(r2), "=r"(r3) : "r"(addr))

#define MMA_F16(d, a, b0, b1)                                            \
    asm volatile(                                                        \
        "mma.sync.aligned.m16n8k16.row.col.f32.f16.f16.f32 "             \
        "{%0,%1,%2,%3}, {%4,%5,%6,%7}, {%8,%9}, {%0,%1,%2,%3};"          \
        : "+f"((d)[0]), "+f"((d)[1]), "+f"((d)[2]), "+f"((d)[3])         \
        : "r"((a)[0]), "r"((a)[1]), "r"((a)[2]), "r"((a)[3]),            \
          "r"(b0), "r"(b1))

#define CP16(dst, src, bytes)                                            \
    asm volatile("cp.async.ca.shared.global [%0], [%1], 16, %2;"         \
                 :: "r"(dst), "l"(src), "r"(bytes))
#define CP_COMMIT() asm volatile("cp.async.commit_group;")
#define CP_WAIT(n)  asm volatile("cp.async.wait_group %0;" :: "n"(n))

__device__ __forceinline__ uint32_t smem_u32(const void* p) {
    uint32_t a;
    asm("{ .reg .u64 t; cvta.to.shared.u64 t, %1; cvt.u32.u64 %0, t; }"
        : "=r"(a) : "l"(p));
    return a;
}

__device__ __forceinline__ void split_h(float v, __half& h, __half& l) {
    h = __float2half(v);
    l = __float2half(v - __half2float(h));
}

// ---------------------------------------------------------------------------
// fp16x2 tensor-core GEMM, cp.async 3-stage pipeline (unchanged from R8).
// ---------------------------------------------------------------------------
#define TROW   40
#define TILEB  10240
#define STAGEB (3 * TILEB)
#define NSTAGE 3
#define GSMEM  (NSTAGE * STAGEB)

__global__ __launch_bounds__(256, 2) void gemm_f16a(
    const __half* __restrict__ A, int lda,
    const __half* __restrict__ Bh, const __half* __restrict__ Bl, int ldb,
    const float* __restrict__ bias, float* __restrict__ C,
    __half* __restrict__ Ch,
    int M, int N, int K,
    size_t az, size_t bz, size_t cz)
{
    extern __shared__ __half sm[];

    A  += (size_t)blockIdx.z * az;
    Bh += (size_t)blockIdx.z * bz;
    Bl += (size_t)blockIdx.z * bz;
    if (C)  C  += (size_t)blockIdx.z * cz;
    if (Ch) Ch += (size_t)blockIdx.z * cz;

    int t = threadIdx.x;
    int lane = t & 31, wid = t >> 5;
    int wm = (wid & 1) * 64, wn = (wid >> 1) * 32;
    int rr = lane & 7, j = lane >> 3;
    int m0 = blockIdx.y * 128, n0 = blockIdx.x * 128;

    float acc[4][4][4];
#pragma unroll
    for (int i = 0; i < 4; i++)
#pragma unroll
        for (int jj = 0; jj < 4; jj++)
#pragma unroll
            for (int k = 0; k < 4; k++) acc[i][jj][k] = 0.0f;

    int srow = t >> 1, shalf = t & 1;
    bool aok = (m0 + srow) < M;
    const __half* Ap  = A + (size_t)(aok ? (m0 + srow) : 0) * lda + shalf * 16;
    const __half* Bhp = Bh + (size_t)(n0 + srow) * ldb + shalf * 16;
    const __half* Blp = Bl + (size_t)(n0 + srow) * ldb + shalf * 16;
    uint32_t abytes = aok ? 16u : 0u;
    uint32_t sm_u = smem_u32(sm);
    uint32_t sdst = (uint32_t)(srow * 80 + shalf * 32);

    uint32_t a_off[2][4];
#pragma unroll
    for (int kk = 0; kk < 2; kk++)
#pragma unroll
        for (int mf = 0; mf < 4; mf++)
            a_off[kk][mf] = (uint32_t)(((wm + mf * 16 + rr + (j & 1) * 8) * TROW
                                        + kk * 16 + (j >> 1) * 8) * 2);
    uint32_t b_off[2][2];
#pragma unroll
    for (int kk = 0; kk < 2; kk++)
#pragma unroll
        for (int p = 0; p < 2; p++)
            b_off[kk][p] = (uint32_t)(((wn + p * 16 + rr + (j >> 1) * 8) * TROW
                                       + kk * 16 + (j & 1) * 8) * 2);

#define ISSUE(stg, kt)                                                    \
    {   uint32_t base = sm_u + (stg) * STAGEB + sdst;                     \
        const __half* as = Ap + (kt);                                     \
        CP16(base, as, abytes); CP16(base + 16, as + 8, abytes);          \
        const __half* hs = Bhp + (kt);                                    \
        CP16(base + TILEB, hs, 16u); CP16(base + TILEB + 16, hs + 8, 16u);\
        const __half* ls = Blp + (kt);                                    \
        CP16(base + 2 * TILEB, ls, 16u);                                  \
        CP16(base + 2 * TILEB + 16, ls + 8, 16u);                         \
        CP_COMMIT(); }

    int NC = K / 32;
    ISSUE(0, 0);
    if (NC > 1) ISSUE(1, 32);

    for (int c = 0; c < NC; c++) {
        if (c + 1 < NC) { CP_WAIT(1); } else { CP_WAIT(0); }
        __syncthreads();
        if (c + 2 < NC) ISSUE((c + 2) % NSTAGE, (c + 2) * 32);

        uint32_t bb = sm_u + (c % NSTAGE) * STAGEB;
#pragma unroll
        for (int kk = 0; kk < 2; kk++) {
            uint32_t bhf[8], blf[8];
            LDSM4(bhf[0], bhf[1], bhf[2], bhf[3], bb + TILEB + b_off[kk][0]);
            LDSM4(bhf[4], bhf[5], bhf[6], bhf[7], bb + TILEB + b_off[kk][1]);
            LDSM4(blf[0], blf[1], blf[2], blf[3], bb + 2 * TILEB + b_off[kk][0]);
            LDSM4(blf[4], blf[5], blf[6], blf[7], bb + 2 * TILEB + b_off[kk][1]);
#pragma unroll
            for (int mf = 0; mf < 4; mf++) {
                uint32_t ahf[4];
                LDSM4(ahf[0], ahf[1], ahf[2], ahf[3], bb + a_off[kk][mf]);
#pragma unroll
                for (int nf = 0; nf < 4; nf++) {
                    MMA_F16(acc[mf][nf], ahf, bhf[nf * 2], bhf[nf * 2 + 1]);
                    MMA_F16(acc[mf][nf], ahf, blf[nf * 2], blf[nf * 2 + 1]);
                }
            }
        }
        __syncthreads();
    }

    int er = lane >> 2, ec = (lane & 3) * 2;
#pragma unroll
    for (int nf = 0; nf < 4; nf++) {
        int col = n0 + wn + nf * 8 + ec;
        float bb0 = bias ? bias[col] : 0.0f;
        float bb1 = bias ? bias[col + 1] : 0.0f;
#pragma unroll
        for (int mf = 0; mf < 4; mf++) {
            int row = m0 + wm + mf * 16 + er;
            if (row < M) {
                float v0 = acc[mf][nf][0] + bb0, v1 = acc[mf][nf][1] + bb1;
                if (Ch)
                    *(__half2*)&Ch[(size_t)row * N + col]
                        = __halves2half2(__float2half(v0), __float2half(v1));
                else
                    *(float2*)&C[(size_t)row * N + col] = make_float2(v0, v1);
            }
            if (row + 8 < M) {
                float v0 = acc[mf][nf][2] + bb0, v1 = acc[mf][nf][3] + bb1;
                if (Ch)
                    *(__half2*)&Ch[(size_t)(row + 8) * N + col]
                        = __halves2half2(__float2half(v0), __float2half(v1));
                else
                    *(float2*)&C[(size_t)(row + 8) * N + col] = make_float2(v0, v1);
            }
        }
    }
}

// ---------------------------------------------------------------------------
// Pre-convert kernels
// ---------------------------------------------------------------------------
__global__ void cvt_h_kernel(const float* __restrict__ src,
                             __half* __restrict__ dst, size_t n)
{
    size_t i = (size_t)blockIdx.x * blockDim.x + threadIdx.x;
    if (i < n) dst[i] = __float2half(src[i]);
}

__global__ void split_w_kernel(const float* __restrict__ src,
                               __half* __restrict__ h, __half* __restrict__ l,
                               size_t n)
{
    size_t i = (size_t)blockIdx.x * blockDim.x + threadIdx.x;
    if (i < n) { __half hh, ll; split_h(src[i], hh, ll); h[i] = hh; l[i] = ll; }
}

__global__ __launch_bounds__(256) void transpose_split(
    const float* __restrict__ src, __half* __restrict__ dh,
    __half* __restrict__ dl, int R, int C)
{
    __shared__ float tile[32][33];
    int cb = blockIdx.x * 32, rb = blockIdx.y * 32;
    int tx = threadIdx.x & 31, ty = threadIdx.x >> 5;
    for (int i = ty; i < 32; i += 8) {
        int r = rb + i, c = cb + tx;
        if (r < R && c < C) tile[i][tx] = src[(size_t)r * C + c];
    }
    __syncthreads();
    for (int i = ty; i < 32; i += 8) {
        int c = cb + i, r = rb + tx;
        if (c < C && r < R) {
            __half hh, ll; split_h(tile[tx][i], hh, ll);
            dh[(size_t)c * R + r] = hh;
            dl[(size_t)c * R + r] = ll;
        }
    }
}

// ---------------------------------------------------------------------------
// Adaptive pooling -> pooled[b][a*768 + c].  One block per (a, b).
// ---------------------------------------------------------------------------
__global__ __launch_bounds__(256) void pool_kernel(
    const __half* __restrict__ qkvh, const float* __restrict__ context,
    float* __restrict__ pooled)
{
    int a = blockIdx.x, b = blockIdx.y;
    int p = a / 7, q = a % 7;
    int sh = p * 32 / 7, eh = ((p + 1) * 32 + 6) / 7;
    int sw = q * 32 / 7, ew = ((q + 1) * 32 + 6) / 7;
    float inv = 1.0f / (float)((eh - sh) * (ew - sw));
    for (int c = threadIdx.x; c < CIN; c += 256) {
        float s = 0.0f;
        if (c < IC) {
            for (int hh = sh; hh < eh; hh++) {
                const __half* row = qkvh + ((size_t)(b * N_TOK) + hh * WW) * NQKV + c;
                for (int ww = sw; ww < ew; ww++)
                    s += __half2float(row[(size_t)ww * NQKV]);
            }
        } else {
            for (int hh = sh; hh < eh; hh++) {
                const float* row = context + ((size_t)(b * N_TOK) + hh * WW) * CC + (c - IC);
                for (int ww = sw; ww < ew; ww++) s += row[(size_t)ww * CC];
            }
        }
        pooled[((size_t)b * AG + a) * CIN + c] = s * inv;
    }
}

// im2col (fp16 out)
__global__ void im2col_kernel(const float* __restrict__ pooled,
                              __half* __restrict__ col)
{
    size_t idx = (size_t)blockIdx.x * blockDim.x + threadIdx.x;
    if (idx >= (size_t)MCONV * KCONV) return;
    int ck = idx % KCONV;
    int row = idx / KCONV;
    int ci = ck / 9, k9 = ck % 9;
    int ky = k9 / 3, kx = k9 % 3;
    int b = row / AG, p = row % AG;
    int py = p / 7, px = p % 7;
    int sy = py + ky - 1, sx = px + kx - 1;
    float v = 0.0f;
    if (sy >= 0 && sy < 7 && sx >= 0 && sx < 7)
        v = pooled[(size_t)b * (AG * CIN) + ci * AG + sy * 7 + sx];
    col[idx] = __float2half(v);
}

// Reduce split-K partials + conv bias, transpose to agent_cs[b][c*49+s]
__global__ __launch_bounds__(256) void conv_reduce_tr(
    const float* __restrict__ parts, const float* __restrict__ conv_b,
    float* __restrict__ out)
{
    int b = blockIdx.x, cb = blockIdx.y * 64;
    __shared__ float tile[64][50];
    int t = threadIdx.x;
    for (int e = t; e < 64 * AG; e += 256) {
        int c = e & 63, s = e >> 6;
        float v = conv_b[cb + c];
#pragma unroll
        for (int p = 0; p < KSPLIT; p++)
            v += parts[(size_t)p * MCONV * IC + ((size_t)b * AG + s) * IC + cb + c];
        tile[c][s] = v;
    }
    __syncthreads();
    for (int e = t; e < 64 * AG; e += 256) {
        int s = e % AG, c = e / AG;
        out[(size_t)b * AGFLAT + (cb + c) * AG + s] = tile[c][s];
    }
}

// ---------------------------------------------------------------------------
// Bias tables
// ---------------------------------------------------------------------------
__device__ __forceinline__ float bilin7(const float* __restrict__ src, int yi, int xi)
{
    float fy = (yi + 0.5f) * (7.0f / 32.0f) - 0.5f;
    float fx = (xi + 0.5f) * (7.0f / 32.0f) - 0.5f;
    int y0 = (int)floorf(fy); float wy = fy - (float)y0;
    int x0 = (int)floorf(fx); float wx = fx - (float)x0;
    int y0c = max(y0, 0), y1c = min(y0 + 1, 6);
    int x0c = max(x0, 0), x1c = min(x0 + 1, 6);
    float v00 = src[y0c * 7 + x0c], v01 = src[y0c * 7 + x1c];
    float v10 = src[y1c * 7 + x0c], v11 = src[y1c * 7 + x1c];
    return (1.f - wy) * ((1.f - wx) * v00 + wx * v01)
         + wy * ((1.f - wx) * v10 + wx * v11);
}

__global__ void bias_an_kernel(const float* __restrict__ an_bias,
                               const float* __restrict__ ah_bias,
                               const float* __restrict__ aw_bias,
                               float* __restrict__ out)
{
    int idx = blockIdx.x * blockDim.x + threadIdx.x;
    if (idx >= NH * AG * N_TOK) return;
    int n = idx % N_TOK;
    int r = idx / N_TOK;
    int a = r % AG, h = r / AG;
    int hi = n >> 5, wi = n & 31;
    const float* src = an_bias + (size_t)(h * AG + a) * 49;
    float v = bilin7(src, hi, wi)
            + ah_bias[(h * AG + a) * 32 + hi]
            + aw_bias[(h * AG + a) * 32 + wi];
    out[idx] = v;
}

__global__ void bias_na_kernel(const float* __restrict__ na_bias,
                               const float* __restrict__ ha_bias,
                               const float* __restrict__ wa_bias,
                               float* __restrict__ out)
{
    int idx = blockIdx.x * blockDim.x + threadIdx.x;
    if (idx >= NH * N_TOK * AG) return;
    int a = idx % AG;
    int r = idx / AG;
    int n = r % N_TOK, h = r / N_TOK;
    int hi = n >> 5, wi = n & 31;
    const float* src = na_bias + (size_t)(h * AG + a) * 49;
    float v = bilin7(src, hi, wi)
            + ha_bias[(h * 32 + hi) * AG + a]
            + wa_bias[(h * 32 + wi) * AG + a];
    out[idx] = v;
}

// ---------------------------------------------------------------------------
// Agent attention (flash, tensor-core).  One block per (b,h), 256 threads.
// mma1: S[64x128] = AT(64x64) @ K_tile^T ; online softmax ; mma2: acc += P @ V^T
// smem (bytes):
//   SS  f32 [64*133]      @0       34048
//   AT  f16 [64*72]       @34048    9216
//   KS  f16 [128*72]      @43264   18432
//   VT  f16 [64*136]      @61696   17408
//   PS  f16 [64*136]      @79104   17408
//   MR/LR/FR f32[64]x3    @96512
//   PM/PX f32[256]x2      @97280
// ---------------------------------------------------------------------------
#define FL_SS 0
#define FL_AT 34048
#define FL_KS 43264
#define FL_VT 61696
#define FL_PS 79104
#define FL_MR 96512
#define FL_LR 96768
#define FL_FR 97024
#define FL_PM 97280
#define FL_PX 98304
#define FL_SMEM 99328

__global__ __launch_bounds__(256) void agent_flash_mma(
    const __half* __restrict__ qkvh, const float* __restrict__ agent_cs,
    const float* __restrict__ bias_an, float* __restrict__ agv)
{
    extern __shared__ char fsm[];
    float*  SS = (float*)(fsm + FL_SS);      // stride 133
    __half* AT = (__half*)(fsm + FL_AT);     // stride 72
    __half* KS = (__half*)(fsm + FL_KS);     // stride 72
    __half* VT = (__half*)(fsm + FL_VT);     // stride 136
    __half* PS = (__half*)(fsm + FL_PS);     // stride 136
    float*  MR = (float*)(fsm + FL_MR);
    float*  LR = (float*)(fsm + FL_LR);
    float*  FR = (float*)(fsm + FL_FR);
    float*  PM = (float*)(fsm + FL_PM);
    float*  PX = (float*)(fsm + FL_PX);

    int b = blockIdx.x, h = blockIdx.y, t = threadIdx.x;
    int lane = t & 31, wid = t >> 5;
    int rr = lane & 7, j = lane >> 3;
    int er = lane >> 2, ec = (lane & 3) * 2;
    int rid = t >> 2, seg = t & 3;

    uint32_t at_u = smem_u32(AT), ks_u = smem_u32(KS);
    uint32_t vt_u = smem_u32(VT), ps_u = smem_u32(PS);

    // mma1 warp layout: 2 (m) x 4 (n);  mma2: 4 (m) x 2 (n)
    int wm1 = (wid & 1) * 32, wn1 = (wid >> 1) * 32;
    int wm2 = (wid & 3) * 16, wn2 = (wid >> 2) * 32;

    // load AT (agents, fp16, zero-padded rows 49..63)
    for (int e = t; e < 64 * 64; e += 256) {
        int a = e >> 6, d = e & 63;
        AT[a * 72 + d] = (a < AG)
            ? __float2half(agent_cs[(size_t)b * AGFLAT + a * IC + h * HD + d])
            : __half(0.0f);
    }
    if (t < 64) { MR[t] = -1e30f; LR[t] = 0.0f; }

    float acc2[4][4];
#pragma unroll
    for (int nf = 0; nf < 4; nf++)
#pragma unroll
        for (int k = 0; k < 4; k++) acc2[nf][k] = 0.0f;

    // LDSM offsets
    uint32_t a1_off[4][2], b1_off[4][2];
#pragma unroll
    for (int kk = 0; kk < 4; kk++) {
#pragma unroll
        for (int mf = 0; mf < 2; mf++)
            a1_off[kk][mf] = (uint32_t)(((wm1 + mf * 16 + rr + (j & 1) * 8) * 72
                                         + kk * 16 + (j >> 1) * 8) * 2);
#pragma unroll
        for (int p = 0; p < 2; p++)
            b1_off[kk][p] = (uint32_t)(((wn1 + p * 16 + rr + (j >> 1) * 8) * 72
                                        + kk * 16 + (j & 1) * 8) * 2);
    }
    uint32_t a2_off[8], b2_off[8][2];
#pragma unroll
    for (int kk = 0; kk < 8; kk++) {
        a2_off[kk] = (uint32_t)(((wm2 + rr + (j & 1) * 8) * 136
                                 + kk * 16 + (j >> 1) * 8) * 2);
#pragma unroll
        for (int p = 0; p < 2; p++)
            b2_off[kk][p] = (uint32_t)(((wn2 + p * 16 + rr + (j >> 1) * 8) * 136
                                        + kk * 16 + (j & 1) * 8) * 2);
    }

    for (int jt = 0; jt < N_TOK; jt += 128) {
        __syncthreads();   // protect KS/VT/PS from previous iteration
        // load K tile (vectorized) and V tile (transposed)
        for (int e = t; e < 1024; e += 256) {
            int jj = e >> 3, ch = e & 7;
            *(float4*)(KS + jj * 72 + ch * 8) = *(const float4*)(
                qkvh + ((size_t)(b * N_TOK + jt + jj)) * NQKV + IC + h * HD + ch * 8);
        }
        for (int e = t; e < 8192; e += 256) {
            int d = e & 63, jj = e >> 6;
            VT[d * 136 + jj] =
                qkvh[((size_t)(b * N_TOK + jt + jj)) * NQKV + 2 * IC + h * HD + d];
        }
        __syncthreads();

        // mma1: S = AT @ K^T
        float acc1[2][4][4];
#pragma unroll
        for (int mf = 0; mf < 2; mf++)
#pragma unroll
            for (int nf = 0; nf < 4; nf++)
#pragma unroll
                for (int k = 0; k < 4; k++) acc1[mf][nf][k] = 0.0f;
#pragma unroll
        for (int kk = 0; kk < 4; kk++) {
            uint32_t bf[8];
            LDSM4(bf[0], bf[1], bf[2], bf[3], ks_u + b1_off[kk][0]);
            LDSM4(bf[4], bf[5], bf[6], bf[7], ks_u + b1_off[kk][1]);
#pragma unroll
            for (int mf = 0; mf < 2; mf++) {
                uint32_t af[4];
                LDSM4(af[0], af[1], af[2], af[3], at_u + a1_off[kk][mf]);
#pragma unroll
                for (int nf = 0; nf < 4; nf++)
                    MMA_F16(acc1[mf][nf], af, bf[nf * 2], bf[nf * 2 + 1]);
            }
        }
        // epilogue -> SS (+bias, padded agents = -1e30)
#pragma unroll
        for (int mf = 0; mf < 2; mf++) {
            int a0 = wm1 + mf * 16 + er, a1 = a0 + 8;
            const float* bb0 = (a0 < AG) ? bias_an + (size_t)(h * AG + a0) * N_TOK + jt : nullptr;
            const float* bb1 = (a1 < AG) ? bias_an + (size_t)(h * AG + a1) * N_TOK + jt : nullptr;
#pragma unroll
            for (int nf = 0; nf < 4; nf++) {
                int jc = wn1 + nf * 8 + ec;
                if (bb0) {
                    SS[a0 * 133 + jc]     = acc1[mf][nf][0] * 0.125f + bb0[jc];
                    SS[a0 * 133 + jc + 1] = acc1[mf][nf][1] * 0.125f + bb0[jc + 1];
                } else {
                    SS[a0 * 133 + jc] = -1e30f; SS[a0 * 133 + jc + 1] = -1e30f;
                }
                if (bb1) {
                    SS[a1 * 133 + jc]     = acc1[mf][nf][2] * 0.125f + bb1[jc];
                    SS[a1 * 133 + jc + 1] = acc1[mf][nf][3] * 0.125f + bb1[jc + 1];
                } else {
                    SS[a1 * 133 + jc] = -1e30f; SS[a1 * 133 + jc + 1] = -1e30f;
                }
            }
        }
        __syncthreads();

        // per-row max partials (64 rows x 4 segs of 32)
        {
            float pm = -1e30f;
            const float* row = SS + rid * 133 + seg * 32;
            for (int i = 0; i < 32; i++) pm = fmaxf(pm, row[i]);
            PM[rid * 4 + seg] = pm;
        }
        __syncthreads();
        if (t < 64) {
            float mnew = fmaxf(fmaxf(PM[t * 4], PM[t * 4 + 1]),
                               fmaxf(PM[t * 4 + 2], PM[t * 4 + 3]));
            mnew = fmaxf(MR[t], mnew);
            FR[t] = __expf(MR[t] - mnew);
            MR[t] = mnew;
        }
        __syncthreads();
        // exp -> PS (fp16) + partial sums
        {
            float m = MR[rid], ps = 0.0f;
            const float* row = SS + rid * 133 + seg * 32;
            __half* prow = PS + rid * 136 + seg * 32;
            for (int i = 0; i < 32; i++) {
                float e = __expf(row[i] - m);
                prow[i] = __float2half(e);
                ps += e;
            }
            PX[rid * 4 + seg] = ps;
        }
        __syncthreads();
        if (t < 64)
            LR[t] = LR[t] * FR[t]
                  + PX[t * 4] + PX[t * 4 + 1] + PX[t * 4 + 2] + PX[t * 4 + 3];

        // rescale acc2 by FR (rows = agents)
        {
            float f0 = FR[wm2 + er], f1 = FR[wm2 + er + 8];
#pragma unroll
            for (int nf = 0; nf < 4; nf++) {
                acc2[nf][0] *= f0; acc2[nf][1] *= f0;
                acc2[nf][2] *= f1; acc2[nf][3] *= f1;
            }
        }
        // mma2: acc2 += P @ V^T   (K = 128)
#pragma unroll
        for (int kk = 0; kk < 8; kk++) {
            uint32_t bf[8];
            LDSM4(bf[0], bf[1], bf[2], bf[3], vt_u + b2_off[kk][0]);
            LDSM4(bf[4], bf[5], bf[6], bf[7], vt_u + b2_off[kk][1]);
            uint32_t af[4];
            LDSM4(af[0], af[1], af[2], af[3], ps_u + a2_off[kk]);
#pragma unroll
            for (int nf = 0; nf < 4; nf++)
                MMA_F16(acc2[nf], af, bf[nf * 2], bf[nf * 2 + 1]);
        }
    }

    __syncthreads();
    // output: agv[b,h,a,d] = acc2 / LR[a]
    {
        int a0 = wm2 + er, a1 = a0 + 8;
        float i0 = (a0 < AG) ? 1.0f / LR[a0] : 0.0f;
        float i1 = (a1 < AG) ? 1.0f / LR[a1] : 0.0f;
#pragma unroll
        for (int nf = 0; nf < 4; nf++) {
            int d = wn2 + nf * 8 + ec;
            if (a0 < AG)
                *(float2*)&agv[(((size_t)(b * NH + h) * AG) + a0) * HD + d]
                    = make_float2(acc2[nf][0] * i0, acc2[nf][1] * i0);
            if (a1 < AG)
                *(float2*)&agv[(((size_t)(b * NH + h) * AG) + a1) * HD + d]
                    = make_float2(acc2[nf][2] * i1, acc2[nf][3] * i1);
        }
    }
}

// ---------------------------------------------------------------------------
// Query attention (tensor-core).  Block (b,h,nt=64 tokens), 128 threads.
// mma1: S[64x64] = Q @ AT^T ; softmax(49) ; mma2: O = P @ AV^T -> outpre.
// smem: SS f32[64*65]@0 (16640) | QS f16[64*72]@16640 | ATS/AVT f16@25856
//       | PS f16@35072 ; total 44288
// ---------------------------------------------------------------------------
#define QA_SS 0
#define QA_QS 16640
#define QA_AT 25856
#define QA_PS 35072
#define QA_SMEM 44288

__global__ __launch_bounds__(128) void qattn_mma(
    const __half* __restrict__ qkvh, const float* __restrict__ agent_cs,
    const float* __restrict__ agv, const float* __restrict__ bias_na,
    float* __restrict__ outpre)
{
    extern __shared__ char qsm[];
    float*  SS  = (float*)(qsm + QA_SS);     // stride 65
    __half* QS  = (__half*)(qsm + QA_QS);    // stride 72
    __half* ATS = (__half*)(qsm + QA_AT);    // stride 72 (aliased with AVT)
    __half* PS  = (__half*)(qsm + QA_PS);    // stride 72

    int b = blockIdx.x, h = blockIdx.y, nt = blockIdx.z;
    int t = threadIdx.x;
    int lane = t & 31, wid = t >> 5;
    int rr = lane & 7, j = lane >> 3;
    int er = lane >> 2, ec = (lane & 3) * 2;
    int wm = (wid & 1) * 32, wn = (wid >> 1) * 32;

    uint32_t qs_u = smem_u32(QS), at_u = smem_u32(ATS), ps_u = smem_u32(PS);

    // load Q tile (vectorized) + AT (fp16, zero-padded)
    for (int e = t; e < 512; e += 128) {
        int nn = e >> 3, ch = e & 7;
        *(float4*)(QS + nn * 72 + ch * 8) = *(const float4*)(
            qkvh + ((size_t)(b * N_TOK) + nt * 64 + nn) * NQKV + h * HD + ch * 8);
    }
    for (int e = t; e < 64 * 64; e += 128) {
        int a = e >> 6, d = e & 63;
        ATS[a * 72 + d] = (a < AG)
            ? __float2half(agent_cs[(size_t)b * AGFLAT + a * IC + h * HD + d])
            : __half(0.0f);
    }
    __syncthreads();

    uint32_t a_off[4][2], b_off[4][2];
#pragma unroll
    for (int kk = 0; kk < 4; kk++) {
#pragma unroll
        for (int mf = 0; mf < 2; mf++)
            a_off[kk][mf] = (uint32_t)(((wm + mf * 16 + rr + (j & 1) * 8) * 72
                                        + kk * 16 + (j >> 1) * 8) * 2);
#pragma unroll
        for (int p = 0; p < 2; p++)
            b_off[kk][p] = (uint32_t)(((wn + p * 16 + rr + (j >> 1) * 8) * 72
                                       + kk * 16 + (j & 1) * 8) * 2);
    }

    float acc[2][4][4];
#pragma unroll
    for (int mf = 0; mf < 2; mf++)
#pragma unroll
        for (int nf = 0; nf < 4; nf++)
#pragma unroll
            for (int k = 0; k < 4; k++) acc[mf][nf][k] = 0.0f;

    // mma1: S = Q @ AT^T
#pragma unroll
    for (int kk = 0; kk < 4; kk++) {
        uint32_t bf[8];
        LDSM4(bf[0], bf[1], bf[2], bf[3], at_u + b_off[kk][0]);
        LDSM4(bf[4], bf[5], bf[6], bf[7], at_u + b_off[kk][1]);
#pragma unroll
        for (int mf = 0; mf < 2; mf++) {
            uint32_t af[4];
            LDSM4(af[0], af[1], af[2], af[3], qs_u + a_off[kk][mf]);
#pragma unroll
            for (int nf = 0; nf < 4; nf++)
                MMA_F16(acc[mf][nf], af, bf[nf * 2], bf[nf * 2 + 1]);
        }
    }
    // epilogue -> SS (+bias; padded agents = -1e30)
#pragma unroll
    for (int mf = 0; mf < 2; mf++) {
        int tok0 = wm + mf * 16 + er, tok1 = tok0 + 8;
        const float* bn0 = bias_na + ((size_t)(h * N_TOK) + nt * 64 + tok0) * AG;
        const float* bn1 = bias_na + ((size_t)(h * N_TOK) + nt * 64 + tok1) * AG;
#pragma unroll
        for (int nf = 0; nf < 4; nf++) {
            int a = wn + nf * 8 + ec;
            SS[tok0 * 65 + a]     = (a < AG)     ? acc[mf][nf][0] * 0.125f + bn0[a]     : -1e30f;
            SS[tok0 * 65 + a + 1] = (a + 1 < AG) ? acc[mf][nf][1] * 0.125f + bn0[a + 1] : -1e30f;
            SS[tok1 * 65 + a]     = (a < AG)     ? acc[mf][nf][2] * 0.125f + bn1[a]     : -1e30f;
            SS[tok1 * 65 + a + 1] = (a + 1 < AG) ? acc[mf][nf][3] * 0.125f + bn1[a + 1] : -1e30f;
        }
    }
    __syncthreads();

    // softmax (threads 0-63, one token each) ; threads 64-127 load AVT
    if (t < 64) {
        const float* row = SS + t * 65;
        float m = -1e30f;
        for (int a = 0; a < 64; a++) m = fmaxf(m, row[a]);
        float s = 0.0f;
        float e[64];
        for (int a = 0; a < 64; a++) { e[a] = __expf(row[a] - m); s += e[a]; }
        float inv = 1.0f / s;
        __half* prow = PS + t * 72;
        for (int a = 0; a < 64; a++) prow[a] = __float2half(e[a] * inv);
    } else {
        int d = t - 64;   // AVT[d][a] = agv[b,h,a,d] (0 for padded a)
        __half* vrow = ATS + d * 72;   // alias: ATS no longer needed
        const float* ga = agv + ((size_t)(b * NH + h) * AG) * HD + d;
        for (int a = 0; a < AG; a++) vrow[a] = __float2half(ga[(size_t)a * HD]);
        for (int a = AG; a < 64; a++) vrow[a] = __half(0.0f);
    }
    __syncthreads();

    // mma2: O = P @ AVT^T
#pragma unroll
    for (int mf = 0; mf < 2; mf++)
#pragma unroll
        for (int nf = 0; nf < 4; nf++)
#pragma unroll
            for (int k = 0; k < 4; k++) acc[mf][nf][k] = 0.0f;
#pragma unroll
    for (int kk = 0; kk < 4; kk++) {
        uint32_t bf[8];
        LDSM4(bf[0], bf[1], bf[2], bf[3], at_u + b_off[kk][0]);
        LDSM4(bf[4], bf[5], bf[6], bf[7], at_u + b_off[kk][1]);
#pragma unroll
        for (int mf = 0; mf < 2; mf++) {
            uint32_t af[4];
            LDSM4(af[0], af[1], af[2], af[3], ps_u + a_off[kk][mf]);
#pragma unroll
            for (int nf = 0; nf < 4; nf++)
                MMA_F16(acc[mf][nf], af, bf[nf * 2], bf[nf * 2 + 1]);
        }
    }
    // epilogue -> outpre
#pragma unroll
    for (int mf = 0; mf < 2; mf++) {
        int tok0 = nt * 64 + wm + mf * 16 + er;
#pragma unroll
        for (int nf = 0; nf < 4; nf++) {
            int d = wn + nf * 8 + ec;
            *(float2*)&outpre[((size_t)(b * N_TOK) + tok0) * IC + h * HD + d]
                = make_float2(acc[mf][nf][0], acc[mf][nf][1]);
            *(float2*)&outpre[((size_t)(b * N_TOK) + tok0 + 8) * IC + h * HD + d]
                = make_float2(acc[mf][nf][2], acc[mf][nf][3]);
        }
    }
}

// Depthwise 3x3 conv on v image (fp16), fused add + fp16 convert -> outh.
__global__ void dwc_kernel(const __half* __restrict__ qkvh,
                           const float* __restrict__ dwc_w,
                           const float* __restrict__ dwc_b,
                           const float* __restrict__ outpre,
                           __half* __restrict__ outh)
{
    int n = blockIdx.x;
    int b = blockIdx.y;
    int c = blockIdx.z * 128 + threadIdx.x;
    int hh = n >> 5, wcur = n & 31;
    float s = dwc_b[c];
#pragma unroll
    for (int ky = 0; ky < 3; ky++) {
        int y = hh + ky - 1;
        if (y < 0 || y >= HH) continue;
#pragma unroll
        for (int kx = 0; kx < 3; kx++) {
            int x = wcur + kx - 1;
            if (x < 0 || x >= WW) continue;
            s += dwc_w[c * 9 + ky * 3 + kx]
               * __half2float(
                     qkvh[((size_t)(b * N_TOK) + y * WW + x) * NQKV + 2 * IC + c]);
        }
    }
    size_t i = ((size_t)(b * N_TOK) + n) * IC + c;
    outh[i] = __float2half(outpre[i] + s);
}

// ---------------------------------------------------------------------------
// Host launcher
// ---------------------------------------------------------------------------
extern "C" void kernel_launch(void* const* d_in, const int* in_sizes, int n_in,
                              void* d_out, int out_size)
{
    const float* x       = (const float*)d_in[0];
    const float* context = (const float*)d_in[1];
    const float* Wq      = (const float*)d_in[2];
    const float* Wkv     = (const float*)d_in[3];
    const float* conv_w  = (const float*)d_in[4];
    const float* conv_b  = (const float*)d_in[5];
    const float* dwc_w   = (const float*)d_in[6];
    const float* dwc_b   = (const float*)d_in[7];
    const float* proj_w  = (const float*)d_in[8];
    const float* proj_b  = (const float*)d_in[9];
    const float* an_bias = (const float*)d_in[10];
    const float* na_bias = (const float*)d_in[11];
    const float* ah_bias = (const float*)d_in[12];
    const float* aw_bias = (const float*)d_in[13];
    const float* ha_bias = (const float*)d_in[14];
    const float* wa_bias = (const float*)d_in[15];
    float* out = (float*)d_out;

    float  *pooled, *convp, *agent_cs, *ban, *bna, *agv, *outpre;
    __half *qkvh, *xh, *whT, *wlT, *pwhT, *pwlT, *cwh, *cwl, *colh, *outh;
    cudaGetSymbolAddress((void**)&qkvh,     g_qkvh);
    cudaGetSymbolAddress((void**)&xh,       g_xh);
    cudaGetSymbolAddress((void**)&whT,      g_whT);
    cudaGetSymbolAddress((void**)&wlT,      g_wlT);
    cudaGetSymbolAddress((void**)&pwhT,     g_pwhT);
    cudaGetSymbolAddress((void**)&pwlT,     g_pwlT);
    cudaGetSymbolAddress((void**)&cwh,      g_cwh);
    cudaGetSymbolAddress((void**)&cwl,      g_cwl);
    cudaGetSymbolAddress((void**)&pooled,   g_pooled);
    cudaGetSymbolAddress((void**)&colh,     g_colh);
    cudaGetSymbolAddress((void**)&convp,    g_convp);
    cudaGetSymbolAddress((void**)&agent_cs, g_agent_cs);
    cudaGetSymbolAddress((void**)&ban,      g_bias_an);
    cudaGetSymbolAddress((void**)&bna,      g_bias_na);
    cudaGetSymbolAddress((void**)&agv,      g_agv);
    cudaGetSymbolAddress((void**)&outpre,   g_outpre);
    cudaGetSymbolAddress((void**)&outh,     g_outh);

    cudaFuncSetAttribute(gemm_f16a,
                         cudaFuncAttributeMaxDynamicSharedMemorySize, GSMEM);
    cudaFuncSetAttribute(agent_flash_mma,
                         cudaFuncAttributeMaxDynamicSharedMemorySize, FL_SMEM);
    cudaFuncSetAttribute(qattn_mma,
                         cudaFuncAttributeMaxDynamicSharedMemorySize, QA_SMEM);

    // 1. operand prep
    {
        size_t nx = (size_t)B * N_TOK * DIM;
        cvt_h_kernel<<<(int)((nx + 255) / 256), 256>>>(x, xh, nx);
    }
    transpose_split<<<dim3(IC / 32, DIM / 32), 256>>>(Wq, whT, wlT, DIM, IC);
    transpose_split<<<dim3((2 * IC) / 32, DIM / 32), 256>>>(
        Wkv, whT + (size_t)IC * DIM, wlT + (size_t)IC * DIM, DIM, 2 * IC);
    transpose_split<<<dim3(IC / 32, DIM / 32), 256>>>(proj_w, pwhT, pwlT, DIM, IC);
    {
        size_t nc = (size_t)IC * KCONV;
        split_w_kernel<<<(int)((nc + 255) / 256), 256>>>(conv_w, cwh, cwl, nc);
    }

    // 2. fused QKV GEMM -> fp16
    gemm_f16a<<<dim3(NQKV / 128, (B * N_TOK) / 128, 1), 256, GSMEM>>>(
        xh, DIM, whT, wlT, DIM, nullptr, nullptr, qkvh,
        B * N_TOK, NQKV, DIM, 0, 0, 0);

    // 3. adaptive pool
    pool_kernel<<<dim3(AG, B), 256>>>(qkvh, context, pooled);

    // 4. conv: im2col(fp16) + split-K GEMM + reduce
    im2col_kernel<<<(int)(((size_t)MCONV * KCONV + 255) / 256), 256>>>(pooled, colh);
    gemm_f16a<<<dim3(IC / 128, (MCONV + 127) / 128, KSPLIT), 256, GSMEM>>>(
        colh, KCONV, cwh, cwl, KCONV, nullptr, convp, nullptr,
        MCONV, IC, KSLAB,
        (size_t)KSLAB, (size_t)KSLAB, (size_t)MCONV * IC);
    conv_reduce_tr<<<dim3(B, IC / 64), 256>>>(convp, conv_b, agent_cs);

    // 5. bias tables
    bias_an_kernel<<<(NH * AG * N_TOK + 255) / 256, 256>>>(an_bias, ah_bias, aw_bias, ban);
    bias_na_kernel<<<(NH * N_TOK * AG + 255) / 256, 256>>>(na_bias, ha_bias, wa_bias, bna);

    // 6. agent attention (tensor-core flash)
    agent_flash_mma<<<dim3(B, NH), 256, FL_SMEM>>>(qkvh, agent_cs, ban, agv);

    // 7. query attention (tensor-core) -> outpre
    qattn_mma<<<dim3(B, NH, N_TOK / 64), 128, QA_SMEM>>>(
        qkvh, agent_cs, agv, bna, outpre);

    // 8. depthwise conv residual -> outh (fp16)
    dwc_kernel<<<dim3(N_TOK, B, IC / 128), 128>>>(qkvh, dwc_w, dwc_b, outpre, outh);

    // 9. output projection
    gemm_f16a<<<dim3(IC / 128, (B * N_TOK) / 128, 1), 256, GSMEM>>>(
        outh, IC, pwhT, pwlT, DIM, proj_b, out, nullptr,
        B * N_TOK, IC, DIM, 0, 0, 0);

    (void)in_sizes; (void)n_in; (void)out_size;
}

// round 12
// speedup vs baseline: 1.5855x; 1.0801x over previous
#include <cuda_runtime.h>
#include <cuda_fp16.h>
#include <cstdint>

// ---------------------------------------------------------------------------
// Problem constants
// ---------------------------------------------------------------------------
#define B 32
#define N_TOK 1024
#define DIM 512
#define IC 512
#define CC 256
#define NH 8
#define AG 49
#define HD 64
#define HH 32
#define WW 32
#define CIN 768            // IC + CC
#define KCONV 6912         // 768*9
#define MCONV 1568         // B*49
#define NQKV 1536          // IC + 2*IC
#define AGFLAT 25088       // IC*AG
#define KSPLIT 4
#define KSLAB 1728         // KCONV / KSPLIT

// ---------------------------------------------------------------------------
// Scratch (static device globals; no allocation allowed)
// ---------------------------------------------------------------------------
__device__ __half g_qkvh[(size_t)B * N_TOK * NQKV];          // [q|k|v] fp16
__device__ __half g_xh[(size_t)B * N_TOK * DIM];             // x in fp16
__device__ __half g_whT[(size_t)NQKV * DIM];                 // [j][k] hi
__device__ __half g_wlT[(size_t)NQKV * DIM];                 // [j][k] lo (unused for qkv now)
__device__ __half g_pwhT[(size_t)IC * DIM];
__device__ __half g_pwlT[(size_t)IC * DIM];
__device__ __half g_cwh[(size_t)IC * KCONV];
__device__ float  g_pooled[(size_t)B * AG * CIN];
__device__ __half g_colh[(size_t)MCONV * KCONV];
__device__ float  g_convp[(size_t)KSPLIT * MCONV * IC];
__device__ float  g_agent_cs[(size_t)B * AGFLAT];
__device__ float  g_bias_an[NH * AG * N_TOK];
__device__ float  g_bias_na[NH * N_TOK * AG];
__device__ float  g_agv[(size_t)B * NH * AG * HD];
__device__ float  g_outpre[(size_t)B * N_TOK * IC];
__device__ __half g_outh[(size_t)B * N_TOK * IC];

// ---------------------------------------------------------------------------
// PTX helpers
// ---------------------------------------------------------------------------
#define LDSM4(r0, r1, r2, r3, addr)                                      \
    asm volatile("ldmatrix.sync.aligned.m8n8.x4.shared.b16 "             \
                 "{%0,%1,%2,%3}, [%4];"                                  \
                 : "=r"(r0), "=r"(r1), "=r"(r2), "=r"(r3) : "r"(addr))

#define MMA_F16(d, a, b0, b1)                                            \
    asm volatile(                                                        \
        "mma.sync.aligned.m16n8k16.row.col.f32.f16.f16.f32 "             \
        "{%0,%1,%2,%3}, {%4,%5,%6,%7}, {%8,%9}, {%0,%1,%2,%3};"          \
        : "+f"((d)[0]), "+f"((d)[1]), "+f"((d)[2]), "+f"((d)[3])         \
        : "r"((a)[0]), "r"((a)[1]), "r"((a)[2]), "r"((a)[3]),            \
          "r"(b0), "r"(b1))

#define CP16(dst, src, bytes)                                            \
    asm volatile("cp.async.ca.shared.global [%0], [%1], 16, %2;"         \
                 :: "r"(dst), "l"(src), "r"(bytes))
#define CP_COMMIT() asm volatile("cp.async.commit_group;")
#define CP_WAIT(n)  asm volatile("cp.async.wait_group %0;" :: "n"(n))

__device__ __forceinline__ uint32_t smem_u32(const void* p) {
    uint32_t a;
    asm("{ .reg .u64 t; cvta.to.shared.u64 t, %1; cvt.u32.u64 %0, t; }"
        : "=r"(a) : "l"(p));
    return a;
}

__device__ __forceinline__ void split_h(float v, __half& h, __half& l) {
    h = __float2half(v);
    l = __float2half(v - __half2float(h));
}

// ---------------------------------------------------------------------------
// fp16 tensor-core GEMM, cp.async 3-stage pipeline.
// C/Ch[M,N] = A[M,K] @ B'[N,K]^T (+bias).  A fp16 row-major (lda halves),
// B' fp16 row-major (ldb halves); optional lo-weight Bl for a 2nd correction
// product (Bl == nullptr -> single product).
// Block tile 128x128, K chunk 32, 8 warps of 64x32; 2 CTAs/SM.
// Requires N%128==0, K%32==0. M guarded. blockIdx.z adds az/bz/cz offsets.
// ---------------------------------------------------------------------------
#define TROW   40
#define TILEB  10240
#define STAGEB (3 * TILEB)
#define NSTAGE 3
#define GSMEM  (NSTAGE * STAGEB)

__global__ __launch_bounds__(256, 2) void gemm_f16a(
    const __half* __restrict__ A, int lda,
    const __half* __restrict__ Bh, const __half* __restrict__ Bl, int ldb,
    const float* __restrict__ bias, float* __restrict__ C,
    __half* __restrict__ Ch,
    int M, int N, int K,
    size_t az, size_t bz, size_t cz)
{
    extern __shared__ __half sm[];

    bool hasBl = (Bl != nullptr);
    A  += (size_t)blockIdx.z * az;
    Bh += (size_t)blockIdx.z * bz;
    if (hasBl) Bl += (size_t)blockIdx.z * bz;
    if (C)  C  += (size_t)blockIdx.z * cz;
    if (Ch) Ch += (size_t)blockIdx.z * cz;

    int t = threadIdx.x;
    int lane = t & 31, wid = t >> 5;
    int wm = (wid & 1) * 64, wn = (wid >> 1) * 32;
    int rr = lane & 7, j = lane >> 3;
    int m0 = blockIdx.y * 128, n0 = blockIdx.x * 128;

    float acc[4][4][4];
#pragma unroll
    for (int i = 0; i < 4; i++)
#pragma unroll
        for (int jj = 0; jj < 4; jj++)
#pragma unroll
            for (int k = 0; k < 4; k++) acc[i][jj][k] = 0.0f;

    int srow = t >> 1, shalf = t & 1;
    bool aok = (m0 + srow) < M;
    const __half* Ap  = A + (size_t)(aok ? (m0 + srow) : 0) * lda + shalf * 16;
    const __half* Bhp = Bh + (size_t)(n0 + srow) * ldb + shalf * 16;
    const __half* Blp = hasBl ? Bl + (size_t)(n0 + srow) * ldb + shalf * 16 : Bhp;
    uint32_t abytes = aok ? 16u : 0u;
    uint32_t sm_u = smem_u32(sm);
    uint32_t sdst = (uint32_t)(srow * 80 + shalf * 32);

    uint32_t a_off[2][4];
#pragma unroll
    for (int kk = 0; kk < 2; kk++)
#pragma unroll
        for (int mf = 0; mf < 4; mf++)
            a_off[kk][mf] = (uint32_t)(((wm + mf * 16 + rr + (j & 1) * 8) * TROW
                                        + kk * 16 + (j >> 1) * 8) * 2);
    uint32_t b_off[2][2];
#pragma unroll
    for (int kk = 0; kk < 2; kk++)
#pragma unroll
        for (int p = 0; p < 2; p++)
            b_off[kk][p] = (uint32_t)(((wn + p * 16 + rr + (j >> 1) * 8) * TROW
                                       + kk * 16 + (j & 1) * 8) * 2);

#define ISSUE(stg, kt)                                                    \
    {   uint32_t base = sm_u + (stg) * STAGEB + sdst;                     \
        const __half* as = Ap + (kt);                                     \
        CP16(base, as, abytes); CP16(base + 16, as + 8, abytes);          \
        const __half* hs = Bhp + (kt);                                    \
        CP16(base + TILEB, hs, 16u); CP16(base + TILEB + 16, hs + 8, 16u);\
        if (hasBl) {                                                      \
            const __half* ls = Blp + (kt);                                \
            CP16(base + 2 * TILEB, ls, 16u);                              \
            CP16(base + 2 * TILEB + 16, ls + 8, 16u);                     \
        }                                                                 \
        CP_COMMIT(); }

    int NC = K / 32;
    ISSUE(0, 0);
    if (NC > 1) ISSUE(1, 32);

    for (int c = 0; c < NC; c++) {
        if (c + 1 < NC) { CP_WAIT(1); } else { CP_WAIT(0); }
        __syncthreads();
        if (c + 2 < NC) ISSUE((c + 2) % NSTAGE, (c + 2) * 32);

        uint32_t bb = sm_u + (c % NSTAGE) * STAGEB;
#pragma unroll
        for (int kk = 0; kk < 2; kk++) {
            uint32_t bhf[8], blf[8];
            LDSM4(bhf[0], bhf[1], bhf[2], bhf[3], bb + TILEB + b_off[kk][0]);
            LDSM4(bhf[4], bhf[5], bhf[6], bhf[7], bb + TILEB + b_off[kk][1]);
            if (hasBl) {
                LDSM4(blf[0], blf[1], blf[2], blf[3], bb + 2 * TILEB + b_off[kk][0]);
                LDSM4(blf[4], blf[5], blf[6], blf[7], bb + 2 * TILEB + b_off[kk][1]);
            }
#pragma unroll
            for (int mf = 0; mf < 4; mf++) {
                uint32_t ahf[4];
                LDSM4(ahf[0], ahf[1], ahf[2], ahf[3], bb + a_off[kk][mf]);
#pragma unroll
                for (int nf = 0; nf < 4; nf++) {
                    MMA_F16(acc[mf][nf], ahf, bhf[nf * 2], bhf[nf * 2 + 1]);
                    if (hasBl)
                        MMA_F16(acc[mf][nf], ahf, blf[nf * 2], blf[nf * 2 + 1]);
                }
            }
        }
        __syncthreads();
    }

    int er = lane >> 2, ec = (lane & 3) * 2;
#pragma unroll
    for (int nf = 0; nf < 4; nf++) {
        int col = n0 + wn + nf * 8 + ec;
        float bb0 = bias ? bias[col] : 0.0f;
        float bb1 = bias ? bias[col + 1] : 0.0f;
#pragma unroll
        for (int mf = 0; mf < 4; mf++) {
            int row = m0 + wm + mf * 16 + er;
            if (row < M) {
                float v0 = acc[mf][nf][0] + bb0, v1 = acc[mf][nf][1] + bb1;
                if (Ch)
                    *(__half2*)&Ch[(size_t)row * N + col]
                        = __halves2half2(__float2half(v0), __float2half(v1));
                else
                    *(float2*)&C[(size_t)row * N + col] = make_float2(v0, v1);
            }
            if (row + 8 < M) {
                float v0 = acc[mf][nf][2] + bb0, v1 = acc[mf][nf][3] + bb1;
                if (Ch)
                    *(__half2*)&Ch[(size_t)(row + 8) * N + col]
                        = __halves2half2(__float2half(v0), __float2half(v1));
                else
                    *(float2*)&C[(size_t)(row + 8) * N + col] = make_float2(v0, v1);
            }
        }
    }
}

// ---------------------------------------------------------------------------
// Pre-convert kernels
// ---------------------------------------------------------------------------
__global__ void cvt_h_kernel(const float* __restrict__ src,
                             __half* __restrict__ dst, size_t n)
{
    size_t i = (size_t)blockIdx.x * blockDim.x + threadIdx.x;
    if (i < n) dst[i] = __float2half(src[i]);
}

__global__ __launch_bounds__(256) void transpose_split(
    const float* __restrict__ src, __half* __restrict__ dh,
    __half* __restrict__ dl, int R, int C)
{
    __shared__ float tile[32][33];
    int cb = blockIdx.x * 32, rb = blockIdx.y * 32;
    int tx = threadIdx.x & 31, ty = threadIdx.x >> 5;
    for (int i = ty; i < 32; i += 8) {
        int r = rb + i, c = cb + tx;
        if (r < R && c < C) tile[i][tx] = src[(size_t)r * C + c];
    }
    __syncthreads();
    for (int i = ty; i < 32; i += 8) {
        int c = cb + i, r = rb + tx;
        if (c < C && r < R) {
            __half hh, ll; split_h(tile[tx][i], hh, ll);
            dh[(size_t)c * R + r] = hh;
            if (dl) dl[(size_t)c * R + r] = ll;
        }
    }
}

// ---------------------------------------------------------------------------
// Adaptive pooling -> pooled[b][a*768 + c].  One block per (a, b).
// ---------------------------------------------------------------------------
__global__ __launch_bounds__(256) void pool_kernel(
    const __half* __restrict__ qkvh, const float* __restrict__ context,
    float* __restrict__ pooled)
{
    int a = blockIdx.x, b = blockIdx.y;
    int p = a / 7, q = a % 7;
    int sh = p * 32 / 7, eh = ((p + 1) * 32 + 6) / 7;
    int sw = q * 32 / 7, ew = ((q + 1) * 32 + 6) / 7;
    float inv = 1.0f / (float)((eh - sh) * (ew - sw));
    for (int c = threadIdx.x; c < CIN; c += 256) {
        float s = 0.0f;
        if (c < IC) {
            for (int hh = sh; hh < eh; hh++) {
                const __half* row = qkvh + ((size_t)(b * N_TOK) + hh * WW) * NQKV + c;
                for (int ww = sw; ww < ew; ww++)
                    s += __half2float(row[(size_t)ww * NQKV]);
            }
        } else {
            for (int hh = sh; hh < eh; hh++) {
                const float* row = context + ((size_t)(b * N_TOK) + hh * WW) * CC + (c - IC);
                for (int ww = sw; ww < ew; ww++) s += row[(size_t)ww * CC];
            }
        }
        pooled[((size_t)b * AG + a) * CIN + c] = s * inv;
    }
}

// im2col (fp16 out)
__global__ void im2col_kernel(const float* __restrict__ pooled,
                              __half* __restrict__ col)
{
    size_t idx = (size_t)blockIdx.x * blockDim.x + threadIdx.x;
    if (idx >= (size_t)MCONV * KCONV) return;
    int ck = idx % KCONV;
    int row = idx / KCONV;
    int ci = ck / 9, k9 = ck % 9;
    int ky = k9 / 3, kx = k9 % 3;
    int b = row / AG, p = row % AG;
    int py = p / 7, px = p % 7;
    int sy = py + ky - 1, sx = px + kx - 1;
    float v = 0.0f;
    if (sy >= 0 && sy < 7 && sx >= 0 && sx < 7)
        v = pooled[(size_t)b * (AG * CIN) + ci * AG + sy * 7 + sx];
    col[idx] = __float2half(v);
}

// Reduce split-K partials + conv bias, transpose to agent_cs[b][c*49+s]
__global__ __launch_bounds__(256) void conv_reduce_tr(
    const float* __restrict__ parts, const float* __restrict__ conv_b,
    float* __restrict__ out)
{
    int b = blockIdx.x, cb = blockIdx.y * 64;
    __shared__ float tile[64][50];
    int t = threadIdx.x;
    for (int e = t; e < 64 * AG; e += 256) {
        int c = e & 63, s = e >> 6;
        float v = conv_b[cb + c];
#pragma unroll
        for (int p = 0; p < KSPLIT; p++)
            v += parts[(size_t)p * MCONV * IC + ((size_t)b * AG + s) * IC + cb + c];
        tile[c][s] = v;
    }
    __syncthreads();
    for (int e = t; e < 64 * AG; e += 256) {
        int s = e % AG, c = e / AG;
        out[(size_t)b * AGFLAT + (cb + c) * AG + s] = tile[c][s];
    }
}

// ---------------------------------------------------------------------------
// Bias tables
// ---------------------------------------------------------------------------
__device__ __forceinline__ float bilin7(const float* __restrict__ src, int yi, int xi)
{
    float fy = (yi + 0.5f) * (7.0f / 32.0f) - 0.5f;
    float fx = (xi + 0.5f) * (7.0f / 32.0f) - 0.5f;
    int y0 = (int)floorf(fy); float wy = fy - (float)y0;
    int x0 = (int)floorf(fx); float wx = fx - (float)x0;
    int y0c = max(y0, 0), y1c = min(y0 + 1, 6);
    int x0c = max(x0, 0), x1c = min(x0 + 1, 6);
    float v00 = src[y0c * 7 + x0c], v01 = src[y0c * 7 + x1c];
    float v10 = src[y1c * 7 + x0c], v11 = src[y1c * 7 + x1c];
    return (1.f - wy) * ((1.f - wx) * v00 + wx * v01)
         + wy * ((1.f - wx) * v10 + wx * v11);
}

__global__ void bias_an_kernel(const float* __restrict__ an_bias,
                               const float* __restrict__ ah_bias,
                               const float* __restrict__ aw_bias,
                               float* __restrict__ out)
{
    int idx = blockIdx.x * blockDim.x + threadIdx.x;
    if (idx >= NH * AG * N_TOK) return;
    int n = idx % N_TOK;
    int r = idx / N_TOK;
    int a = r % AG, h = r / AG;
    int hi = n >> 5, wi = n & 31;
    const float* src = an_bias + (size_t)(h * AG + a) * 49;
    float v = bilin7(src, hi, wi)
            + ah_bias[(h * AG + a) * 32 + hi]
            + aw_bias[(h * AG + a) * 32 + wi];
    out[idx] = v;
}

__global__ void bias_na_kernel(const float* __restrict__ na_bias,
                               const float* __restrict__ ha_bias,
                               const float* __restrict__ wa_bias,
                               float* __restrict__ out)
{
    int idx = blockIdx.x * blockDim.x + threadIdx.x;
    if (idx >= NH * N_TOK * AG) return;
    int a = idx % AG;
    int r = idx / AG;
    int n = r % N_TOK, h = r / N_TOK;
    int hi = n >> 5, wi = n & 31;
    const float* src = na_bias + (size_t)(h * AG + a) * 49;
    float v = bilin7(src, hi, wi)
            + ha_bias[(h * 32 + hi) * AG + a]
            + wa_bias[(h * 32 + wi) * AG + a];
    out[idx] = v;
}

// ---------------------------------------------------------------------------
// Agent attention (flash, tensor-core).  One block per (b,h), 256 threads.
// ---------------------------------------------------------------------------
#define FL_SS 0
#define FL_AT 34048
#define FL_KS 43264
#define FL_VT 61696
#define FL_PS 79104
#define FL_MR 96512
#define FL_LR 96768
#define FL_FR 97024
#define FL_PM 97280
#define FL_PX 98304
#define FL_SMEM 99328

__global__ __launch_bounds__(256) void agent_flash_mma(
    const __half* __restrict__ qkvh, const float* __restrict__ agent_cs,
    const float* __restrict__ bias_an, float* __restrict__ agv)
{
    extern __shared__ char fsm[];
    float*  SS = (float*)(fsm + FL_SS);      // stride 133
    __half* AT = (__half*)(fsm + FL_AT);     // stride 72
    __half* KS = (__half*)(fsm + FL_KS);     // stride 72
    __half* VT = (__half*)(fsm + FL_VT);     // stride 136
    __half* PS = (__half*)(fsm + FL_PS);     // stride 136
    float*  MR = (float*)(fsm + FL_MR);
    float*  LR = (float*)(fsm + FL_LR);
    float*  FR = (float*)(fsm + FL_FR);
    float*  PM = (float*)(fsm + FL_PM);
    float*  PX = (float*)(fsm + FL_PX);

    int b = blockIdx.x, h = blockIdx.y, t = threadIdx.x;
    int lane = t & 31, wid = t >> 5;
    int rr = lane & 7, j = lane >> 3;
    int er = lane >> 2, ec = (lane & 3) * 2;
    int rid = t >> 2, seg = t & 3;

    uint32_t at_u = smem_u32(AT), ks_u = smem_u32(KS);
    uint32_t vt_u = smem_u32(VT), ps_u = smem_u32(PS);

    int wm1 = (wid & 1) * 32, wn1 = (wid >> 1) * 32;
    int wm2 = (wid & 3) * 16, wn2 = (wid >> 2) * 32;

    for (int e = t; e < 64 * 64; e += 256) {
        int a = e >> 6, d = e & 63;
        AT[a * 72 + d] = (a < AG)
            ? __float2half(agent_cs[(size_t)b * AGFLAT + a * IC + h * HD + d])
            : __half(0.0f);
    }
    if (t < 64) { MR[t] = -1e30f; LR[t] = 0.0f; }

    float acc2[4][4];
#pragma unroll
    for (int nf = 0; nf < 4; nf++)
#pragma unroll
        for (int k = 0; k < 4; k++) acc2[nf][k] = 0.0f;

    uint32_t a1_off[4][2], b1_off[4][2];
#pragma unroll
    for (int kk = 0; kk < 4; kk++) {
#pragma unroll
        for (int mf = 0; mf < 2; mf++)
            a1_off[kk][mf] = (uint32_t)(((wm1 + mf * 16 + rr + (j & 1) * 8) * 72
                                         + kk * 16 + (j >> 1) * 8) * 2);
#pragma unroll
        for (int p = 0; p < 2; p++)
            b1_off[kk][p] = (uint32_t)(((wn1 + p * 16 + rr + (j >> 1) * 8) * 72
                                        + kk * 16 + (j & 1) * 8) * 2);
    }
    uint32_t a2_off[8], b2_off[8][2];
#pragma unroll
    for (int kk = 0; kk < 8; kk++) {
        a2_off[kk] = (uint32_t)(((wm2 + rr + (j & 1) * 8) * 136
                                 + kk * 16 + (j >> 1) * 8) * 2);
#pragma unroll
        for (int p = 0; p < 2; p++)
            b2_off[kk][p] = (uint32_t)(((wn2 + p * 16 + rr + (j >> 1) * 8) * 136
                                        + kk * 16 + (j & 1) * 8) * 2);
    }

    for (int jt = 0; jt < N_TOK; jt += 128) {
        __syncthreads();
        for (int e = t; e < 1024; e += 256) {
            int jj = e >> 3, ch = e & 7;
            *(float4*)(KS + jj * 72 + ch * 8) = *(const float4*)(
                qkvh + ((size_t)(b * N_TOK + jt + jj)) * NQKV + IC + h * HD + ch * 8);
        }
        for (int e = t; e < 8192; e += 256) {
            int d = e & 63, jj = e >> 6;
            VT[d * 136 + jj] =
                qkvh[((size_t)(b * N_TOK + jt + jj)) * NQKV + 2 * IC + h * HD + d];
        }
        __syncthreads();

        float acc1[2][4][4];
#pragma unroll
        for (int mf = 0; mf < 2; mf++)
#pragma unroll
            for (int nf = 0; nf < 4; nf++)
#pragma unroll
                for (int k = 0; k < 4; k++) acc1[mf][nf][k] = 0.0f;
#pragma unroll
        for (int kk = 0; kk < 4; kk++) {
            uint32_t bf[8];
            LDSM4(bf[0], bf[1], bf[2], bf[3], ks_u + b1_off[kk][0]);
            LDSM4(bf[4], bf[5], bf[6], bf[7], ks_u + b1_off[kk][1]);
#pragma unroll
            for (int mf = 0; mf < 2; mf++) {
                uint32_t af[4];
                LDSM4(af[0], af[1], af[2], af[3], at_u + a1_off[kk][mf]);
#pragma unroll
                for (int nf = 0; nf < 4; nf++)
                    MMA_F16(acc1[mf][nf], af, bf[nf * 2], bf[nf * 2 + 1]);
            }
        }
#pragma unroll
        for (int mf = 0; mf < 2; mf++) {
            int a0 = wm1 + mf * 16 + er, a1 = a0 + 8;
            const float* bb0 = (a0 < AG) ? bias_an + (size_t)(h * AG + a0) * N_TOK + jt : nullptr;
            const float* bb1 = (a1 < AG) ? bias_an + (size_t)(h * AG + a1) * N_TOK + jt : nullptr;
#pragma unroll
            for (int nf = 0; nf < 4; nf++) {
                int jc = wn1 + nf * 8 + ec;
                if (bb0) {
                    SS[a0 * 133 + jc]     = acc1[mf][nf][0] * 0.125f + bb0[jc];
                    SS[a0 * 133 + jc + 1] = acc1[mf][nf][1] * 0.125f + bb0[jc + 1];
                } else {
                    SS[a0 * 133 + jc] = -1e30f; SS[a0 * 133 + jc + 1] = -1e30f;
                }
                if (bb1) {
                    SS[a1 * 133 + jc]     = acc1[mf][nf][2] * 0.125f + bb1[jc];
                    SS[a1 * 133 + jc + 1] = acc1[mf][nf][3] * 0.125f + bb1[jc + 1];
                } else {
                    SS[a1 * 133 + jc] = -1e30f; SS[a1 * 133 + jc + 1] = -1e30f;
                }
            }
        }
        __syncthreads();

        {
            float pm = -1e30f;
            const float* row = SS + rid * 133 + seg * 32;
            for (int i = 0; i < 32; i++) pm = fmaxf(pm, row[i]);
            PM[rid * 4 + seg] = pm;
        }
        __syncthreads();
        if (t < 64) {
            float mnew = fmaxf(fmaxf(PM[t * 4], PM[t * 4 + 1]),
                               fmaxf(PM[t * 4 + 2], PM[t * 4 + 3]));
            mnew = fmaxf(MR[t], mnew);
            FR[t] = __expf(MR[t] - mnew);
            MR[t] = mnew;
        }
        __syncthreads();
        {
            float m = MR[rid], ps = 0.0f;
            const float* row = SS + rid * 133 + seg * 32;
            __half* prow = PS + rid * 136 + seg * 32;
            for (int i = 0; i < 32; i++) {
                float e = __expf(row[i] - m);
                prow[i] = __float2half(e);
                ps += e;
            }
            PX[rid * 4 + seg] = ps;
        }
        __syncthreads();
        if (t < 64)
            LR[t] = LR[t] * FR[t]
                  + PX[t * 4] + PX[t * 4 + 1] + PX[t * 4 + 2] + PX[t * 4 + 3];

        {
            float f0 = FR[wm2 + er], f1 = FR[wm2 + er + 8];
#pragma unroll
            for (int nf = 0; nf < 4; nf++) {
                acc2[nf][0] *= f0; acc2[nf][1] *= f0;
                acc2[nf][2] *= f1; acc2[nf][3] *= f1;
            }
        }
#pragma unroll
        for (int kk = 0; kk < 8; kk++) {
            uint32_t bf[8];
            LDSM4(bf[0], bf[1], bf[2], bf[3], vt_u + b2_off[kk][0]);
            LDSM4(bf[4], bf[5], bf[6], bf[7], vt_u + b2_off[kk][1]);
            uint32_t af[4];
            LDSM4(af[0], af[1], af[2], af[3], ps_u + a2_off[kk]);
#pragma unroll
            for (int nf = 0; nf < 4; nf++)
                MMA_F16(acc2[nf], af, bf[nf * 2], bf[nf * 2 + 1]);
        }
    }

    __syncthreads();
    {
        int a0 = wm2 + er, a1 = a0 + 8;
        float i0 = (a0 < AG) ? 1.0f / LR[a0] : 0.0f;
        float i1 = (a1 < AG) ? 1.0f / LR[a1] : 0.0f;
#pragma unroll
        for (int nf = 0; nf < 4; nf++) {
            int d = wn2 + nf * 8 + ec;
            if (a0 < AG)
                *(float2*)&agv[(((size_t)(b * NH + h) * AG) + a0) * HD + d]
                    = make_float2(acc2[nf][0] * i0, acc2[nf][1] * i0);
            if (a1 < AG)
                *(float2*)&agv[(((size_t)(b * NH + h) * AG) + a1) * HD + d]
                    = make_float2(acc2[nf][2] * i1, acc2[nf][3] * i1);
        }
    }
}

// ---------------------------------------------------------------------------
// Query attention (tensor-core).  Block (b,h,nt), 128 threads.
// ---------------------------------------------------------------------------
#define QA_SS 0
#define QA_QS 16640
#define QA_AT 25856
#define QA_PS 35072
#define QA_SMEM 44288

__global__ __launch_bounds__(128) void qattn_mma(
    const __half* __restrict__ qkvh, const float* __restrict__ agent_cs,
    const float* __restrict__ agv, const float* __restrict__ bias_na,
    float* __restrict__ outpre)
{
    extern __shared__ char qsm[];
    float*  SS  = (float*)(qsm + QA_SS);
    __half* QS  = (__half*)(qsm + QA_QS);
    __half* ATS = (__half*)(qsm + QA_AT);
    __half* PS  = (__half*)(qsm + QA_PS);

    int b = blockIdx.x, h = blockIdx.y, nt = blockIdx.z;
    int t = threadIdx.x;
    int lane = t & 31, wid = t >> 5;
    int rr = lane & 7, j = lane >> 3;
    int er = lane >> 2, ec = (lane & 3) * 2;
    int wm = (wid & 1) * 32, wn = (wid >> 1) * 32;

    uint32_t qs_u = smem_u32(QS), at_u = smem_u32(ATS), ps_u = smem_u32(PS);

    for (int e = t; e < 512; e += 128) {
        int nn = e >> 3, ch = e & 7;
        *(float4*)(QS + nn * 72 + ch * 8) = *(const float4*)(
            qkvh + ((size_t)(b * N_TOK) + nt * 64 + nn) * NQKV + h * HD + ch * 8);
    }
    for (int e = t; e < 64 * 64; e += 128) {
        int a = e >> 6, d = e & 63;
        ATS[a * 72 + d] = (a < AG)
            ? __float2half(agent_cs[(size_t)b * AGFLAT + a * IC + h * HD + d])
            : __half(0.0f);
    }
    __syncthreads();

    uint32_t a_off[4][2], b_off[4][2];
#pragma unroll
    for (int kk = 0; kk < 4; kk++) {
#pragma unroll
        for (int mf = 0; mf < 2; mf++)
            a_off[kk][mf] = (uint32_t)(((wm + mf * 16 + rr + (j & 1) * 8) * 72
                                        + kk * 16 + (j >> 1) * 8) * 2);
#pragma unroll
        for (int p = 0; p < 2; p++)
            b_off[kk][p] = (uint32_t)(((wn + p * 16 + rr + (j >> 1) * 8) * 72
                                       + kk * 16 + (j & 1) * 8) * 2);
    }

    float acc[2][4][4];
#pragma unroll
    for (int mf = 0; mf < 2; mf++)
#pragma unroll
        for (int nf = 0; nf < 4; nf++)
#pragma unroll
            for (int k = 0; k < 4; k++) acc[mf][nf][k] = 0.0f;

#pragma unroll
    for (int kk = 0; kk < 4; kk++) {
        uint32_t bf[8];
        LDSM4(bf[0], bf[1], bf[2], bf[3], at_u + b_off[kk][0]);
        LDSM4(bf[4], bf[5], bf[6], bf[7], at_u + b_off[kk][1]);
#pragma unroll
        for (int mf = 0; mf < 2; mf++) {
            uint32_t af[4];
            LDSM4(af[0], af[1], af[2], af[3], qs_u + a_off[kk][mf]);
#pragma unroll
            for (int nf = 0; nf < 4; nf++)
                MMA_F16(acc[mf][nf], af, bf[nf * 2], bf[nf * 2 + 1]);
        }
    }
#pragma unroll
    for (int mf = 0; mf < 2; mf++) {
        int tok0 = wm + mf * 16 + er, tok1 = tok0 + 8;
        const float* bn0 = bias_na + ((size_t)(h * N_TOK) + nt * 64 + tok0) * AG;
        const float* bn1 = bias_na + ((size_t)(h * N_TOK) + nt * 64 + tok1) * AG;
#pragma unroll
        for (int nf = 0; nf < 4; nf++) {
            int a = wn + nf * 8 + ec;
            SS[tok0 * 65 + a]     = (a < AG)     ? acc[mf][nf][0] * 0.125f + bn0[a]     : -1e30f;
            SS[tok0 * 65 + a + 1] = (a + 1 < AG) ? acc[mf][nf][1] * 0.125f + bn0[a + 1] : -1e30f;
            SS[tok1 * 65 + a]     = (a < AG)     ? acc[mf][nf][2] * 0.125f + bn1[a]     : -1e30f;
            SS[tok1 * 65 + a + 1] = (a + 1 < AG) ? acc[mf][nf][3] * 0.125f + bn1[a + 1] : -1e30f;
        }
    }
    __syncthreads();

    if (t < 64) {
        const float* row = SS + t * 65;
        float m = -1e30f;
        for (int a = 0; a < 64; a++) m = fmaxf(m, row[a]);
        float s = 0.0f;
        float e[64];
        for (int a = 0; a < 64; a++) { e[a] = __expf(row[a] - m); s += e[a]; }
        float inv = 1.0f / s;
        __half* prow = PS + t * 72;
        for (int a = 0; a < 64; a++) prow[a] = __float2half(e[a] * inv);
    } else {
        int d = t - 64;
        __half* vrow = ATS + d * 72;
        const float* ga = agv + ((size_t)(b * NH + h) * AG) * HD + d;
        for (int a = 0; a < AG; a++) vrow[a] = __float2half(ga[(size_t)a * HD]);
        for (int a = AG; a < 64; a++) vrow[a] = __half(0.0f);
    }
    __syncthreads();

#pragma unroll
    for (int mf = 0; mf < 2; mf++)
#pragma unroll
        for (int nf = 0; nf < 4; nf++)
#pragma unroll
            for (int k = 0; k < 4; k++) acc[mf][nf][k] = 0.0f;
#pragma unroll
    for (int kk = 0; kk < 4; kk++) {
        uint32_t bf[8];
        LDSM4(bf[0], bf[1], bf[2], bf[3], at_u + b_off[kk][0]);
        LDSM4(bf[4], bf[5], bf[6], bf[7], at_u + b_off[kk][1]);
#pragma unroll
        for (int mf = 0; mf < 2; mf++) {
            uint32_t af[4];
            LDSM4(af[0], af[1], af[2], af[3], ps_u + a_off[kk][mf]);
#pragma unroll
            for (int nf = 0; nf < 4; nf++)
                MMA_F16(acc[mf][nf], af, bf[nf * 2], bf[nf * 2 + 1]);
        }
    }
#pragma unroll
    for (int mf = 0; mf < 2; mf++) {
        int tok0 = nt * 64 + wm + mf * 16 + er;
#pragma unroll
        for (int nf = 0; nf < 4; nf++) {
            int d = wn + nf * 8 + ec;
            *(float2*)&outpre[((size_t)(b * N_TOK) + tok0) * IC + h * HD + d]
                = make_float2(acc[mf][nf][0], acc[mf][nf][1]);
            *(float2*)&outpre[((size_t)(b * N_TOK) + tok0 + 8) * IC + h * HD + d]
                = make_float2(acc[mf][nf][2], acc[mf][nf][3]);
        }
    }
}

// Depthwise 3x3 conv on v image (fp16), fused add + fp16 convert -> outh.
__global__ void dwc_kernel(const __half* __restrict__ qkvh,
                           const float* __restrict__ dwc_w,
                           const float* __restrict__ dwc_b,
                           const float* __restrict__ outpre,
                           __half* __restrict__ outh)
{
    int n = blockIdx.x;
    int b = blockIdx.y;
    int c = blockIdx.z * 128 + threadIdx.x;
    int hh = n >> 5, wcur = n & 31;
    float s = dwc_b[c];
#pragma unroll
    for (int ky = 0; ky < 3; ky++) {
        int y = hh + ky - 1;
        if (y < 0 || y >= HH) continue;
#pragma unroll
        for (int kx = 0; kx < 3; kx++) {
            int x = wcur + kx - 1;
            if (x < 0 || x >= WW) continue;
            s += dwc_w[c * 9 + ky * 3 + kx]
               * __half2float(
                     qkvh[((size_t)(b * N_TOK) + y * WW + x) * NQKV + 2 * IC + c]);
        }
    }
    size_t i = ((size_t)(b * N_TOK) + n) * IC + c;
    outh[i] = __float2half(outpre[i] + s);
}

// ---------------------------------------------------------------------------
// Host launcher
// ---------------------------------------------------------------------------
extern "C" void kernel_launch(void* const* d_in, const int* in_sizes, int n_in,
                              void* d_out, int out_size)
{
    const float* x       = (const float*)d_in[0];
    const float* context = (const float*)d_in[1];
    const float* Wq      = (const float*)d_in[2];
    const float* Wkv     = (const float*)d_in[3];
    const float* conv_w  = (const float*)d_in[4];
    const float* conv_b  = (const float*)d_in[5];
    const float* dwc_w   = (const float*)d_in[6];
    const float* dwc_b   = (const float*)d_in[7];
    const float* proj_w  = (const float*)d_in[8];
    const float* proj_b  = (const float*)d_in[9];
    const float* an_bias = (const float*)d_in[10];
    const float* na_bias = (const float*)d_in[11];
    const float* ah_bias = (const float*)d_in[12];
    const float* aw_bias = (const float*)d_in[13];
    const float* ha_bias = (const float*)d_in[14];
    const float* wa_bias = (const float*)d_in[15];
    float* out = (float*)d_out;

    float  *pooled, *convp, *agent_cs, *ban, *bna, *agv, *outpre;
    __half *qkvh, *xh, *whT, *wlT, *pwhT, *pwlT, *cwh, *colh, *outh;
    cudaGetSymbolAddress((void**)&qkvh,     g_qkvh);
    cudaGetSymbolAddress((void**)&xh,       g_xh);
    cudaGetSymbolAddress((void**)&whT,      g_whT);
    cudaGetSymbolAddress((void**)&wlT,      g_wlT);
    cudaGetSymbolAddress((void**)&pwhT,     g_pwhT);
    cudaGetSymbolAddress((void**)&pwlT,     g_pwlT);
    cudaGetSymbolAddress((void**)&cwh,      g_cwh);
    cudaGetSymbolAddress((void**)&pooled,   g_pooled);
    cudaGetSymbolAddress((void**)&colh,     g_colh);
    cudaGetSymbolAddress((void**)&convp,    g_convp);
    cudaGetSymbolAddress((void**)&agent_cs, g_agent_cs);
    cudaGetSymbolAddress((void**)&ban,      g_bias_an);
    cudaGetSymbolAddress((void**)&bna,      g_bias_na);
    cudaGetSymbolAddress((void**)&agv,      g_agv);
    cudaGetSymbolAddress((void**)&outpre,   g_outpre);
    cudaGetSymbolAddress((void**)&outh,     g_outh);

    cudaFuncSetAttribute(gemm_f16a,
                         cudaFuncAttributeMaxDynamicSharedMemorySize, GSMEM);
    cudaFuncSetAttribute(agent_flash_mma,
                         cudaFuncAttributeMaxDynamicSharedMemorySize, FL_SMEM);
    cudaFuncSetAttribute(qattn_mma,
                         cudaFuncAttributeMaxDynamicSharedMemorySize, QA_SMEM);

    // 1. operand prep
    {
        size_t nx = (size_t)B * N_TOK * DIM;
        cvt_h_kernel<<<(int)((nx + 255) / 256), 256>>>(x, xh, nx);
    }
    transpose_split<<<dim3(IC / 32, DIM / 32), 256>>>(Wq, whT, nullptr, DIM, IC);
    transpose_split<<<dim3((2 * IC) / 32, DIM / 32), 256>>>(
        Wkv, whT + (size_t)IC * DIM, nullptr, DIM, 2 * IC);
    transpose_split<<<dim3(IC / 32, DIM / 32), 256>>>(proj_w, pwhT, pwlT, DIM, IC);
    {
        size_t nc = (size_t)IC * KCONV;
        cvt_h_kernel<<<(int)((nc + 255) / 256), 256>>>(conv_w, cwh, nc);
    }

    // 2. fused QKV GEMM (single fp16 product) -> fp16
    gemm_f16a<<<dim3(NQKV / 128, (B * N_TOK) / 128, 1), 256, GSMEM>>>(
        xh, DIM, whT, nullptr, DIM, nullptr, nullptr, qkvh,
        B * N_TOK, NQKV, DIM, 0, 0, 0);

    // 3. adaptive pool
    pool_kernel<<<dim3(AG, B), 256>>>(qkvh, context, pooled);

    // 4. conv: im2col(fp16) + split-K GEMM (single product) + reduce
    im2col_kernel<<<(int)(((size_t)MCONV * KCONV + 255) / 256), 256>>>(pooled, colh);
    gemm_f16a<<<dim3(IC / 128, (MCONV + 127) / 128, KSPLIT), 256, GSMEM>>>(
        colh, KCONV, cwh, nullptr, KCONV, nullptr, convp, nullptr,
        MCONV, IC, KSLAB,
        (size_t)KSLAB, (size_t)KSLAB, (size_t)MCONV * IC);
    conv_reduce_tr<<<dim3(B, IC / 64), 256>>>(convp, conv_b, agent_cs);

    // 5. bias tables
    bias_an_kernel<<<(NH * AG * N_TOK + 255) / 256, 256>>>(an_bias, ah_bias, aw_bias, ban);
    bias_na_kernel<<<(NH * N_TOK * AG + 255) / 256, 256>>>(na_bias, ha_bias, wa_bias, bna);

    // 6. agent attention (tensor-core flash)
    agent_flash_mma<<<dim3(B, NH), 256, FL_SMEM>>>(qkvh, agent_cs, ban, agv);

    // 7. query attention (tensor-core) -> outpre
    qattn_mma<<<dim3(B, NH, N_TOK / 64), 128, QA_SMEM>>>(
        qkvh, agent_cs, agv, bna, outpre);

    // 8. depthwise conv residual -> outh (fp16)
    dwc_kernel<<<dim3(N_TOK, B, IC / 128), 128>>>(qkvh, dwc_w, dwc_b, outpre, outh);

    // 9. output projection (keeps hi/lo weights for accuracy)
    gemm_f16a<<<dim3(IC / 128, (B * N_TOK) / 128, 1), 256, GSMEM>>>(
        outh, IC, pwhT, pwlT, DIM, proj_b, out, nullptr,
        B * N_TOK, IC, DIM, 0, 0, 0);

    (void)in_sizes; (void)n_in; (void)out_size;
}

// round 13
// speedup vs baseline: 1.8063x; 1.1393x over previous
#include <cuda_runtime.h>
#include <cuda_fp16.h>
#include <cstdint>

// ---------------------------------------------------------------------------
// Problem constants
// ---------------------------------------------------------------------------
#define B 32
#define N_TOK 1024
#define DIM 512
#define IC 512
#define CC 256
#define NH 8
#define AG 49
#define HD 64
#define HH 32
#define WW 32
#define CIN 768            // IC + CC
#define KCONV 6912         // 768*9
#define MCONV 1568         // B*49
#define NQKV 1536          // IC + 2*IC
#define AGFLAT 25088       // IC*AG
#define KSPLIT 4
#define KSLAB 1728         // KCONV / KSPLIT

// ---------------------------------------------------------------------------
// Scratch (static device globals; no allocation allowed)
// ---------------------------------------------------------------------------
__device__ __half g_qkvh[(size_t)B * N_TOK * NQKV];          // [q|k|v] fp16
__device__ __half g_xh[(size_t)B * N_TOK * DIM];             // x in fp16
__device__ __half g_whT[(size_t)NQKV * DIM];                 // [j][k]
__device__ __half g_pwhT[(size_t)IC * DIM];
__device__ __half g_cwh[(size_t)IC * KCONV];
__device__ float  g_pooled[(size_t)B * AG * CIN];
__device__ __half g_colh[(size_t)MCONV * KCONV];
__device__ float  g_convp[(size_t)KSPLIT * MCONV * IC];
__device__ float  g_agent_cs[(size_t)B * AGFLAT];
__device__ float  g_bias_an[NH * AG * N_TOK];
__device__ float  g_bias_na[NH * N_TOK * AG];
__device__ float  g_agv[(size_t)B * NH * AG * HD];
__device__ __half g_outh[(size_t)B * N_TOK * IC];

// ---------------------------------------------------------------------------
// PTX helpers
// ---------------------------------------------------------------------------
#define LDSM4(r0, r1, r2, r3, addr)                                      \
    asm volatile("ldmatrix.sync.aligned.m8n8.x4.shared.b16 "             \
                 "{%0,%1,%2,%3}, [%4];"                                  \
                 : "=r"(r0), "=r"(r1), "=r"(r2), "=r"(r3) : "r"(addr))

#define MMA_F16(d, a, b0, b1)                                            \
    asm volatile(                                                        \
        "mma.sync.aligned.m16n8k16.row.col.f32.f16.f16.f32 "             \
        "{%0,%1,%2,%3}, {%4,%5,%6,%7}, {%8,%9}, {%0,%1,%2,%3};"          \
        : "+f"((d)[0]), "+f"((d)[1]), "+f"((d)[2]), "+f"((d)[3])         \
        : "r"((a)[0]), "r"((a)[1]), "r"((a)[2]), "r"((a)[3]),            \
          "r"(b0), "r"(b1))

#define CP16(dst, src, bytes)                                            \
    asm volatile("cp.async.ca.shared.global [%0], [%1], 16, %2;"         \
                 :: "r"(dst), "l"(src), "r"(bytes))
#define CP_COMMIT() asm volatile("cp.async.commit_group;")
#define CP_WAIT(n)  asm volatile("cp.async.wait_group %0;" :: "n"(n))

__device__ __forceinline__ uint32_t smem_u32(const void* p) {
    uint32_t a;
    asm("{ .reg .u64 t; cvta.to.shared.u64 t, %1; cvt.u32.u64 %0, t; }"
        : "=r"(a) : "l"(p));
    return a;
}

// ---------------------------------------------------------------------------
// fp16 tensor-core GEMM, cp.async 3-stage pipeline (single product).
// C/Ch[M,N] = A[M,K] @ B'[N,K]^T (+bias).
// Block tile 128x128, K chunk 32, 8 warps of 64x32; 2 CTAs/SM.
// Requires N%128==0, K%32==0. M guarded. blockIdx.z adds az/bz/cz offsets.
// ---------------------------------------------------------------------------
#define TROW   40
#define TILEB  10240
#define STAGEB (2 * TILEB)           // A | Bh
#define NSTAGE 3
#define GSMEM  (NSTAGE * STAGEB)     // 61440

__global__ __launch_bounds__(256, 2) void gemm_f16a(
    const __half* __restrict__ A, int lda,
    const __half* __restrict__ Bh, int ldb,
    const float* __restrict__ bias, float* __restrict__ C,
    __half* __restrict__ Ch,
    int M, int N, int K,
    size_t az, size_t bz, size_t cz)
{
    extern __shared__ __half sm[];

    A  += (size_t)blockIdx.z * az;
    Bh += (size_t)blockIdx.z * bz;
    if (C)  C  += (size_t)blockIdx.z * cz;
    if (Ch) Ch += (size_t)blockIdx.z * cz;

    int t = threadIdx.x;
    int lane = t & 31, wid = t >> 5;
    int wm = (wid & 1) * 64, wn = (wid >> 1) * 32;
    int rr = lane & 7, j = lane >> 3;
    int m0 = blockIdx.y * 128, n0 = blockIdx.x * 128;

    float acc[4][4][4];
#pragma unroll
    for (int i = 0; i < 4; i++)
#pragma unroll
        for (int jj = 0; jj < 4; jj++)
#pragma unroll
            for (int k = 0; k < 4; k++) acc[i][jj][k] = 0.0f;

    int srow = t >> 1, shalf = t & 1;
    bool aok = (m0 + srow) < M;
    const __half* Ap  = A + (size_t)(aok ? (m0 + srow) : 0) * lda + shalf * 16;
    const __half* Bhp = Bh + (size_t)(n0 + srow) * ldb + shalf * 16;
    uint32_t abytes = aok ? 16u : 0u;
    uint32_t sm_u = smem_u32(sm);
    uint32_t sdst = (uint32_t)(srow * 80 + shalf * 32);

    uint32_t a_off[2][4];
#pragma unroll
    for (int kk = 0; kk < 2; kk++)
#pragma unroll
        for (int mf = 0; mf < 4; mf++)
            a_off[kk][mf] = (uint32_t)(((wm + mf * 16 + rr + (j & 1) * 8) * TROW
                                        + kk * 16 + (j >> 1) * 8) * 2);
    uint32_t b_off[2][2];
#pragma unroll
    for (int kk = 0; kk < 2; kk++)
#pragma unroll
        for (int p = 0; p < 2; p++)
            b_off[kk][p] = (uint32_t)(((wn + p * 16 + rr + (j >> 1) * 8) * TROW
                                       + kk * 16 + (j & 1) * 8) * 2);

#define ISSUE(stg, kt)                                                    \
    {   uint32_t base = sm_u + (stg) * STAGEB + sdst;                     \
        const __half* as = Ap + (kt);                                     \
        CP16(base, as, abytes); CP16(base + 16, as + 8, abytes);          \
        const __half* hs = Bhp + (kt);                                    \
        CP16(base + TILEB, hs, 16u); CP16(base + TILEB + 16, hs + 8, 16u);\
        CP_COMMIT(); }

    int NC = K / 32;
    ISSUE(0, 0);
    if (NC > 1) ISSUE(1, 32);

    for (int c = 0; c < NC; c++) {
        if (c + 1 < NC) { CP_WAIT(1); } else { CP_WAIT(0); }
        __syncthreads();
        if (c + 2 < NC) ISSUE((c + 2) % NSTAGE, (c + 2) * 32);

        uint32_t bb = sm_u + (c % NSTAGE) * STAGEB;
#pragma unroll
        for (int kk = 0; kk < 2; kk++) {
            uint32_t bhf[8];
            LDSM4(bhf[0], bhf[1], bhf[2], bhf[3], bb + TILEB + b_off[kk][0]);
            LDSM4(bhf[4], bhf[5], bhf[6], bhf[7], bb + TILEB + b_off[kk][1]);
#pragma unroll
            for (int mf = 0; mf < 4; mf++) {
                uint32_t ahf[4];
                LDSM4(ahf[0], ahf[1], ahf[2], ahf[3], bb + a_off[kk][mf]);
#pragma unroll
                for (int nf = 0; nf < 4; nf++)
                    MMA_F16(acc[mf][nf], ahf, bhf[nf * 2], bhf[nf * 2 + 1]);
            }
        }
        __syncthreads();
    }

    int er = lane >> 2, ec = (lane & 3) * 2;
#pragma unroll
    for (int nf = 0; nf < 4; nf++) {
        int col = n0 + wn + nf * 8 + ec;
        float bb0 = bias ? bias[col] : 0.0f;
        float bb1 = bias ? bias[col + 1] : 0.0f;
#pragma unroll
        for (int mf = 0; mf < 4; mf++) {
            int row = m0 + wm + mf * 16 + er;
            if (row < M) {
                float v0 = acc[mf][nf][0] + bb0, v1 = acc[mf][nf][1] + bb1;
                if (Ch)
                    *(__half2*)&Ch[(size_t)row * N + col]
                        = __halves2half2(__float2half(v0), __float2half(v1));
                else
                    *(float2*)&C[(size_t)row * N + col] = make_float2(v0, v1);
            }
            if (row + 8 < M) {
                float v0 = acc[mf][nf][2] + bb0, v1 = acc[mf][nf][3] + bb1;
                if (Ch)
                    *(__half2*)&Ch[(size_t)(row + 8) * N + col]
                        = __halves2half2(__float2half(v0), __float2half(v1));
                else
                    *(float2*)&C[(size_t)(row + 8) * N + col] = make_float2(v0, v1);
            }
        }
    }
}

// ---------------------------------------------------------------------------
// Pre-convert kernels
// ---------------------------------------------------------------------------
__global__ void cvt_h_kernel(const float* __restrict__ src,
                             __half* __restrict__ dst, size_t n)
{
    size_t i = (size_t)blockIdx.x * blockDim.x + threadIdx.x;
    if (i < n) dst[i] = __float2half(src[i]);
}

__global__ __launch_bounds__(256) void transpose_h(
    const float* __restrict__ src, __half* __restrict__ dh, int R, int C)
{
    __shared__ float tile[32][33];
    int cb = blockIdx.x * 32, rb = blockIdx.y * 32;
    int tx = threadIdx.x & 31, ty = threadIdx.x >> 5;
    for (int i = ty; i < 32; i += 8) {
        int r = rb + i, c = cb + tx;
        if (r < R && c < C) tile[i][tx] = src[(size_t)r * C + c];
    }
    __syncthreads();
    for (int i = ty; i < 32; i += 8) {
        int c = cb + i, r = rb + tx;
        if (c < C && r < R)
            dh[(size_t)c * R + r] = __float2half(tile[tx][i]);
    }
}

// ---------------------------------------------------------------------------
// Adaptive pooling -> pooled[b][a*768 + c].  One block per (a, b).
// ---------------------------------------------------------------------------
__global__ __launch_bounds__(256) void pool_kernel(
    const __half* __restrict__ qkvh, const float* __restrict__ context,
    float* __restrict__ pooled)
{
    int a = blockIdx.x, b = blockIdx.y;
    int p = a / 7, q = a % 7;
    int sh = p * 32 / 7, eh = ((p + 1) * 32 + 6) / 7;
    int sw = q * 32 / 7, ew = ((q + 1) * 32 + 6) / 7;
    float inv = 1.0f / (float)((eh - sh) * (ew - sw));
    for (int c = threadIdx.x; c < CIN; c += 256) {
        float s = 0.0f;
        if (c < IC) {
            for (int hh = sh; hh < eh; hh++) {
                const __half* row = qkvh + ((size_t)(b * N_TOK) + hh * WW) * NQKV + c;
                for (int ww = sw; ww < ew; ww++)
                    s += __half2float(row[(size_t)ww * NQKV]);
            }
        } else {
            for (int hh = sh; hh < eh; hh++) {
                const float* row = context + ((size_t)(b * N_TOK) + hh * WW) * CC + (c - IC);
                for (int ww = sw; ww < ew; ww++) s += row[(size_t)ww * CC];
            }
        }
        pooled[((size_t)b * AG + a) * CIN + c] = s * inv;
    }
}

// im2col (fp16 out)
__global__ void im2col_kernel(const float* __restrict__ pooled,
                              __half* __restrict__ col)
{
    size_t idx = (size_t)blockIdx.x * blockDim.x + threadIdx.x;
    if (idx >= (size_t)MCONV * KCONV) return;
    int ck = idx % KCONV;
    int row = idx / KCONV;
    int ci = ck / 9, k9 = ck % 9;
    int ky = k9 / 3, kx = k9 % 3;
    int b = row / AG, p = row % AG;
    int py = p / 7, px = p % 7;
    int sy = py + ky - 1, sx = px + kx - 1;
    float v = 0.0f;
    if (sy >= 0 && sy < 7 && sx >= 0 && sx < 7)
        v = pooled[(size_t)b * (AG * CIN) + ci * AG + sy * 7 + sx];
    col[idx] = __float2half(v);
}

// Reduce split-K partials + conv bias, transpose to agent_cs[b][c*49+s]
__global__ __launch_bounds__(256) void conv_reduce_tr(
    const float* __restrict__ parts, const float* __restrict__ conv_b,
    float* __restrict__ out)
{
    int b = blockIdx.x, cb = blockIdx.y * 64;
    __shared__ float tile[64][50];
    int t = threadIdx.x;
    for (int e = t; e < 64 * AG; e += 256) {
        int c = e & 63, s = e >> 6;
        float v = conv_b[cb + c];
#pragma unroll
        for (int p = 0; p < KSPLIT; p++)
            v += parts[(size_t)p * MCONV * IC + ((size_t)b * AG + s) * IC + cb + c];
        tile[c][s] = v;
    }
    __syncthreads();
    for (int e = t; e < 64 * AG; e += 256) {
        int s = e % AG, c = e / AG;
        out[(size_t)b * AGFLAT + (cb + c) * AG + s] = tile[c][s];
    }
}

// ---------------------------------------------------------------------------
// Bias tables
// ---------------------------------------------------------------------------
__device__ __forceinline__ float bilin7(const float* __restrict__ src, int yi, int xi)
{
    float fy = (yi + 0.5f) * (7.0f / 32.0f) - 0.5f;
    float fx = (xi + 0.5f) * (7.0f / 32.0f) - 0.5f;
    int y0 = (int)floorf(fy); float wy = fy - (float)y0;
    int x0 = (int)floorf(fx); float wx = fx - (float)x0;
    int y0c = max(y0, 0), y1c = min(y0 + 1, 6);
    int x0c = max(x0, 0), x1c = min(x0 + 1, 6);
    float v00 = src[y0c * 7 + x0c], v01 = src[y0c * 7 + x1c];
    float v10 = src[y1c * 7 + x0c], v11 = src[y1c * 7 + x1c];
    return (1.f - wy) * ((1.f - wx) * v00 + wx * v01)
         + wy * ((1.f - wx) * v10 + wx * v11);
}

__global__ void bias_an_kernel(const float* __restrict__ an_bias,
                               const float* __restrict__ ah_bias,
                               const float* __restrict__ aw_bias,
                               float* __restrict__ out)
{
    int idx = blockIdx.x * blockDim.x + threadIdx.x;
    if (idx >= NH * AG * N_TOK) return;
    int n = idx % N_TOK;
    int r = idx / N_TOK;
    int a = r % AG, h = r / AG;
    int hi = n >> 5, wi = n & 31;
    const float* src = an_bias + (size_t)(h * AG + a) * 49;
    float v = bilin7(src, hi, wi)
            + ah_bias[(h * AG + a) * 32 + hi]
            + aw_bias[(h * AG + a) * 32 + wi];
    out[idx] = v;
}

__global__ void bias_na_kernel(const float* __restrict__ na_bias,
                               const float* __restrict__ ha_bias,
                               const float* __restrict__ wa_bias,
                               float* __restrict__ out)
{
    int idx = blockIdx.x * blockDim.x + threadIdx.x;
    if (idx >= NH * N_TOK * AG) return;
    int a = idx % AG;
    int r = idx / AG;
    int n = r % N_TOK, h = r / N_TOK;
    int hi = n >> 5, wi = n & 31;
    const float* src = na_bias + (size_t)(h * AG + a) * 49;
    float v = bilin7(src, hi, wi)
            + ha_bias[(h * 32 + hi) * AG + a]
            + wa_bias[(h * 32 + wi) * AG + a];
    out[idx] = v;
}

// ---------------------------------------------------------------------------
// Agent attention (flash, tensor-core).  One block per (b,h), 256 threads.
// ---------------------------------------------------------------------------
#define FL_SS 0
#define FL_AT 34048
#define FL_KS 43264
#define FL_VT 61696
#define FL_PS 79104
#define FL_MR 96512
#define FL_LR 96768
#define FL_FR 97024
#define FL_PM 97280
#define FL_PX 98304
#define FL_SMEM 99328

__global__ __launch_bounds__(256) void agent_flash_mma(
    const __half* __restrict__ qkvh, const float* __restrict__ agent_cs,
    const float* __restrict__ bias_an, float* __restrict__ agv)
{
    extern __shared__ char fsm[];
    float*  SS = (float*)(fsm + FL_SS);      // stride 133
    __half* AT = (__half*)(fsm + FL_AT);     // stride 72
    __half* KS = (__half*)(fsm + FL_KS);     // stride 72
    __half* VT = (__half*)(fsm + FL_VT);     // stride 136
    __half* PS = (__half*)(fsm + FL_PS);     // stride 136
    float*  MR = (float*)(fsm + FL_MR);
    float*  LR = (float*)(fsm + FL_LR);
    float*  FR = (float*)(fsm + FL_FR);
    float*  PM = (float*)(fsm + FL_PM);
    float*  PX = (float*)(fsm + FL_PX);

    int b = blockIdx.x, h = blockIdx.y, t = threadIdx.x;
    int lane = t & 31, wid = t >> 5;
    int rr = lane & 7, j = lane >> 3;
    int er = lane >> 2, ec = (lane & 3) * 2;
    int rid = t >> 2, seg = t & 3;

    uint32_t at_u = smem_u32(AT), ks_u = smem_u32(KS);
    uint32_t vt_u = smem_u32(VT), ps_u = smem_u32(PS);

    int wm1 = (wid & 1) * 32, wn1 = (wid >> 1) * 32;
    int wm2 = (wid & 3) * 16, wn2 = (wid >> 2) * 32;

    for (int e = t; e < 64 * 64; e += 256) {
        int a = e >> 6, d = e & 63;
        AT[a * 72 + d] = (a < AG)
            ? __float2half(agent_cs[(size_t)b * AGFLAT + a * IC + h * HD + d])
            : __half(0.0f);
    }
    if (t < 64) { MR[t] = -1e30f; LR[t] = 0.0f; }

    float acc2[4][4];
#pragma unroll
    for (int nf = 0; nf < 4; nf++)
#pragma unroll
        for (int k = 0; k < 4; k++) acc2[nf][k] = 0.0f;

    uint32_t a1_off[4][2], b1_off[4][2];
#pragma unroll
    for (int kk = 0; kk < 4; kk++) {
#pragma unroll
        for (int mf = 0; mf < 2; mf++)
            a1_off[kk][mf] = (uint32_t)(((wm1 + mf * 16 + rr + (j & 1) * 8) * 72
                                         + kk * 16 + (j >> 1) * 8) * 2);
#pragma unroll
        for (int p = 0; p < 2; p++)
            b1_off[kk][p] = (uint32_t)(((wn1 + p * 16 + rr + (j >> 1) * 8) * 72
                                        + kk * 16 + (j & 1) * 8) * 2);
    }
    uint32_t a2_off[8], b2_off[8][2];
#pragma unroll
    for (int kk = 0; kk < 8; kk++) {
        a2_off[kk] = (uint32_t)(((wm2 + rr + (j & 1) * 8) * 136
                                 + kk * 16 + (j >> 1) * 8) * 2);
#pragma unroll
        for (int p = 0; p < 2; p++)
            b2_off[kk][p] = (uint32_t)(((wn2 + p * 16 + rr + (j >> 1) * 8) * 136
                                        + kk * 16 + (j & 1) * 8) * 2);
    }

    for (int jt = 0; jt < N_TOK; jt += 128) {
        __syncthreads();
        for (int e = t; e < 1024; e += 256) {
            int jj = e >> 3, ch = e & 7;
            *(float4*)(KS + jj * 72 + ch * 8) = *(const float4*)(
                qkvh + ((size_t)(b * N_TOK + jt + jj)) * NQKV + IC + h * HD + ch * 8);
        }
        for (int e = t; e < 8192; e += 256) {
            int d = e & 63, jj = e >> 6;
            VT[d * 136 + jj] =
                qkvh[((size_t)(b * N_TOK + jt + jj)) * NQKV + 2 * IC + h * HD + d];
        }
        __syncthreads();

        float acc1[2][4][4];
#pragma unroll
        for (int mf = 0; mf < 2; mf++)
#pragma unroll
            for (int nf = 0; nf < 4; nf++)
#pragma unroll
                for (int k = 0; k < 4; k++) acc1[mf][nf][k] = 0.0f;
#pragma unroll
        for (int kk = 0; kk < 4; kk++) {
            uint32_t bf[8];
            LDSM4(bf[0], bf[1], bf[2], bf[3], ks_u + b1_off[kk][0]);
            LDSM4(bf[4], bf[5], bf[6], bf[7], ks_u + b1_off[kk][1]);
#pragma unroll
            for (int mf = 0; mf < 2; mf++) {
                uint32_t af[4];
                LDSM4(af[0], af[1], af[2], af[3], at_u + a1_off[kk][mf]);
#pragma unroll
                for (int nf = 0; nf < 4; nf++)
                    MMA_F16(acc1[mf][nf], af, bf[nf * 2], bf[nf * 2 + 1]);
            }
        }
#pragma unroll
        for (int mf = 0; mf < 2; mf++) {
            int a0 = wm1 + mf * 16 + er, a1 = a0 + 8;
            const float* bb0 = (a0 < AG) ? bias_an + (size_t)(h * AG + a0) * N_TOK + jt : nullptr;
            const float* bb1 = (a1 < AG) ? bias_an + (size_t)(h * AG + a1) * N_TOK + jt : nullptr;
#pragma unroll
            for (int nf = 0; nf < 4; nf++) {
                int jc = wn1 + nf * 8 + ec;
                if (bb0) {
                    SS[a0 * 133 + jc]     = acc1[mf][nf][0] * 0.125f + bb0[jc];
                    SS[a0 * 133 + jc + 1] = acc1[mf][nf][1] * 0.125f + bb0[jc + 1];
                } else {
                    SS[a0 * 133 + jc] = -1e30f; SS[a0 * 133 + jc + 1] = -1e30f;
                }
                if (bb1) {
                    SS[a1 * 133 + jc]     = acc1[mf][nf][2] * 0.125f + bb1[jc];
                    SS[a1 * 133 + jc + 1] = acc1[mf][nf][3] * 0.125f + bb1[jc + 1];
                } else {
                    SS[a1 * 133 + jc] = -1e30f; SS[a1 * 133 + jc + 1] = -1e30f;
                }
            }
        }
        __syncthreads();

        {
            float pm = -1e30f;
            const float* row = SS + rid * 133 + seg * 32;
            for (int i = 0; i < 32; i++) pm = fmaxf(pm, row[i]);
            PM[rid * 4 + seg] = pm;
        }
        __syncthreads();
        if (t < 64) {
            float mnew = fmaxf(fmaxf(PM[t * 4], PM[t * 4 + 1]),
                               fmaxf(PM[t * 4 + 2], PM[t * 4 + 3]));
            mnew = fmaxf(MR[t], mnew);
            FR[t] = __expf(MR[t] - mnew);
            MR[t] = mnew;
        }
        __syncthreads();
        {
            float m = MR[rid], ps = 0.0f;
            const float* row = SS + rid * 133 + seg * 32;
            __half* prow = PS + rid * 136 + seg * 32;
            for (int i = 0; i < 32; i++) {
                float e = __expf(row[i] - m);
                prow[i] = __float2half(e);
                ps += e;
            }
            PX[rid * 4 + seg] = ps;
        }
        __syncthreads();
        if (t < 64)
            LR[t] = LR[t] * FR[t]
                  + PX[t * 4] + PX[t * 4 + 1] + PX[t * 4 + 2] + PX[t * 4 + 3];

        {
            float f0 = FR[wm2 + er], f1 = FR[wm2 + er + 8];
#pragma unroll
            for (int nf = 0; nf < 4; nf++) {
                acc2[nf][0] *= f0; acc2[nf][1] *= f0;
                acc2[nf][2] *= f1; acc2[nf][3] *= f1;
            }
        }
#pragma unroll
        for (int kk = 0; kk < 8; kk++) {
            uint32_t bf[8];
            LDSM4(bf[0], bf[1], bf[2], bf[3], vt_u + b2_off[kk][0]);
            LDSM4(bf[4], bf[5], bf[6], bf[7], vt_u + b2_off[kk][1]);
            uint32_t af[4];
            LDSM4(af[0], af[1], af[2], af[3], ps_u + a2_off[kk]);
#pragma unroll
            for (int nf = 0; nf < 4; nf++)
                MMA_F16(acc2[nf], af, bf[nf * 2], bf[nf * 2 + 1]);
        }
    }

    __syncthreads();
    {
        int a0 = wm2 + er, a1 = a0 + 8;
        float i0 = (a0 < AG) ? 1.0f / LR[a0] : 0.0f;
        float i1 = (a1 < AG) ? 1.0f / LR[a1] : 0.0f;
#pragma unroll
        for (int nf = 0; nf < 4; nf++) {
            int d = wn2 + nf * 8 + ec;
            if (a0 < AG)
                *(float2*)&agv[(((size_t)(b * NH + h) * AG) + a0) * HD + d]
                    = make_float2(acc2[nf][0] * i0, acc2[nf][1] * i0);
            if (a1 < AG)
                *(float2*)&agv[(((size_t)(b * NH + h) * AG) + a1) * HD + d]
                    = make_float2(acc2[nf][2] * i1, acc2[nf][3] * i1);
        }
    }
}

// ---------------------------------------------------------------------------
// Query attention (tensor-core) -> outh (fp16).  Block (b,h,nt), 128 threads.
// ---------------------------------------------------------------------------
#define QA_SS 0
#define QA_QS 16640
#define QA_AT 25856
#define QA_PS 35072
#define QA_SMEM 44288

__global__ __launch_bounds__(128) void qattn_mma(
    const __half* __restrict__ qkvh, const float* __restrict__ agent_cs,
    const float* __restrict__ agv, const float* __restrict__ bias_na,
    __half* __restrict__ outh)
{
    extern __shared__ char qsm[];
    float*  SS  = (float*)(qsm + QA_SS);
    __half* QS  = (__half*)(qsm + QA_QS);
    __half* ATS = (__half*)(qsm + QA_AT);
    __half* PS  = (__half*)(qsm + QA_PS);

    int b = blockIdx.x, h = blockIdx.y, nt = blockIdx.z;
    int t = threadIdx.x;
    int lane = t & 31, wid = t >> 5;
    int rr = lane & 7, j = lane >> 3;
    int er = lane >> 2, ec = (lane & 3) * 2;
    int wm = (wid & 1) * 32, wn = (wid >> 1) * 32;

    uint32_t qs_u = smem_u32(QS), at_u = smem_u32(ATS), ps_u = smem_u32(PS);

    for (int e = t; e < 512; e += 128) {
        int nn = e >> 3, ch = e & 7;
        *(float4*)(QS + nn * 72 + ch * 8) = *(const float4*)(
            qkvh + ((size_t)(b * N_TOK) + nt * 64 + nn) * NQKV + h * HD + ch * 8);
    }
    for (int e = t; e < 64 * 64; e += 128) {
        int a = e >> 6, d = e & 63;
        ATS[a * 72 + d] = (a < AG)
            ? __float2half(agent_cs[(size_t)b * AGFLAT + a * IC + h * HD + d])
            : __half(0.0f);
    }
    __syncthreads();

    uint32_t a_off[4][2], b_off[4][2];
#pragma unroll
    for (int kk = 0; kk < 4; kk++) {
#pragma unroll
        for (int mf = 0; mf < 2; mf++)
            a_off[kk][mf] = (uint32_t)(((wm + mf * 16 + rr + (j & 1) * 8) * 72
                                        + kk * 16 + (j >> 1) * 8) * 2);
#pragma unroll
        for (int p = 0; p < 2; p++)
            b_off[kk][p] = (uint32_t)(((wn + p * 16 + rr + (j >> 1) * 8) * 72
                                       + kk * 16 + (j & 1) * 8) * 2);
    }

    float acc[2][4][4];
#pragma unroll
    for (int mf = 0; mf < 2; mf++)
#pragma unroll
        for (int nf = 0; nf < 4; nf++)
#pragma unroll
            for (int k = 0; k < 4; k++) acc[mf][nf][k] = 0.0f;

#pragma unroll
    for (int kk = 0; kk < 4; kk++) {
        uint32_t bf[8];
        LDSM4(bf[0], bf[1], bf[2], bf[3], at_u + b_off[kk][0]);
        LDSM4(bf[4], bf[5], bf[6], bf[7], at_u + b_off[kk][1]);
#pragma unroll
        for (int mf = 0; mf < 2; mf++) {
            uint32_t af[4];
            LDSM4(af[0], af[1], af[2], af[3], qs_u + a_off[kk][mf]);
#pragma unroll
            for (int nf = 0; nf < 4; nf++)
                MMA_F16(acc[mf][nf], af, bf[nf * 2], bf[nf * 2 + 1]);
        }
    }
#pragma unroll
    for (int mf = 0; mf < 2; mf++) {
        int tok0 = wm + mf * 16 + er, tok1 = tok0 + 8;
        const float* bn0 = bias_na + ((size_t)(h * N_TOK) + nt * 64 + tok0) * AG;
        const float* bn1 = bias_na + ((size_t)(h * N_TOK) + nt * 64 + tok1) * AG;
#pragma unroll
        for (int nf = 0; nf < 4; nf++) {
            int a = wn + nf * 8 + ec;
            SS[tok0 * 65 + a]     = (a < AG)     ? acc[mf][nf][0] * 0.125f + bn0[a]     : -1e30f;
            SS[tok0 * 65 + a + 1] = (a + 1 < AG) ? acc[mf][nf][1] * 0.125f + bn0[a + 1] : -1e30f;
            SS[tok1 * 65 + a]     = (a < AG)     ? acc[mf][nf][2] * 0.125f + bn1[a]     : -1e30f;
            SS[tok1 * 65 + a + 1] = (a + 1 < AG) ? acc[mf][nf][3] * 0.125f + bn1[a + 1] : -1e30f;
        }
    }
    __syncthreads();

    if (t < 64) {
        const float* row = SS + t * 65;
        float m = -1e30f;
        for (int a = 0; a < 64; a++) m = fmaxf(m, row[a]);
        float s = 0.0f;
        float e[64];
        for (int a = 0; a < 64; a++) { e[a] = __expf(row[a] - m); s += e[a]; }
        float inv = 1.0f / s;
        __half* prow = PS + t * 72;
        for (int a = 0; a < 64; a++) prow[a] = __float2half(e[a] * inv);
    } else {
        int d = t - 64;
        __half* vrow = ATS + d * 72;
        const float* ga = agv + ((size_t)(b * NH + h) * AG) * HD + d;
        for (int a = 0; a < AG; a++) vrow[a] = __float2half(ga[(size_t)a * HD]);
        for (int a = AG; a < 64; a++) vrow[a] = __half(0.0f);
    }
    __syncthreads();

#pragma unroll
    for (int mf = 0; mf < 2; mf++)
#pragma unroll
        for (int nf = 0; nf < 4; nf++)
#pragma unroll
            for (int k = 0; k < 4; k++) acc[mf][nf][k] = 0.0f;
#pragma unroll
    for (int kk = 0; kk < 4; kk++) {
        uint32_t bf[8];
        LDSM4(bf[0], bf[1], bf[2], bf[3], at_u + b_off[kk][0]);
        LDSM4(bf[4], bf[5], bf[6], bf[7], at_u + b_off[kk][1]);
#pragma unroll
        for (int mf = 0; mf < 2; mf++) {
            uint32_t af[4];
            LDSM4(af[0], af[1], af[2], af[3], ps_u + a_off[kk][mf]);
#pragma unroll
            for (int nf = 0; nf < 4; nf++)
                MMA_F16(acc[mf][nf], af, bf[nf * 2], bf[nf * 2 + 1]);
        }
    }
    // epilogue -> outh (fp16)
#pragma unroll
    for (int mf = 0; mf < 2; mf++) {
        int tok0 = nt * 64 + wm + mf * 16 + er;
#pragma unroll
        for (int nf = 0; nf < 4; nf++) {
            int d = wn + nf * 8 + ec;
            *(__half2*)&outh[((size_t)(b * N_TOK) + tok0) * IC + h * HD + d]
                = __halves2half2(__float2half(acc[mf][nf][0]),
                                 __float2half(acc[mf][nf][1]));
            *(__half2*)&outh[((size_t)(b * N_TOK) + tok0 + 8) * IC + h * HD + d]
                = __halves2half2(__float2half(acc[mf][nf][2]),
                                 __float2half(acc[mf][nf][3]));
        }
    }
}

// Depthwise 3x3 conv on v image (fp16), fused in-place add into outh.
__global__ void dwc_kernel(const __half* __restrict__ qkvh,
                           const float* __restrict__ dwc_w,
                           const float* __restrict__ dwc_b,
                           __half* __restrict__ outh)
{
    int n = blockIdx.x;
    int b = blockIdx.y;
    int c = blockIdx.z * 128 + threadIdx.x;
    int hh = n >> 5, wcur = n & 31;
    float s = dwc_b[c];
#pragma unroll
    for (int ky = 0; ky < 3; ky++) {
        int y = hh + ky - 1;
        if (y < 0 || y >= HH) continue;
#pragma unroll
        for (int kx = 0; kx < 3; kx++) {
            int x = wcur + kx - 1;
            if (x < 0 || x >= WW) continue;
            s += dwc_w[c * 9 + ky * 3 + kx]
               * __half2float(
                     qkvh[((size_t)(b * N_TOK) + y * WW + x) * NQKV + 2 * IC + c]);
        }
    }
    size_t i = ((size_t)(b * N_TOK) + n) * IC + c;
    outh[i] = __float2half(__half2float(outh[i]) + s);
}

// ---------------------------------------------------------------------------
// Host launcher
// ---------------------------------------------------------------------------
extern "C" void kernel_launch(void* const* d_in, const int* in_sizes, int n_in,
                              void* d_out, int out_size)
{
    const float* x       = (const float*)d_in[0];
    const float* context = (const float*)d_in[1];
    const float* Wq      = (const float*)d_in[2];
    const float* Wkv     = (const float*)d_in[3];
    const float* conv_w  = (const float*)d_in[4];
    const float* conv_b  = (const float*)d_in[5];
    const float* dwc_w   = (const float*)d_in[6];
    const float* dwc_b   = (const float*)d_in[7];
    const float* proj_w  = (const float*)d_in[8];
    const float* proj_b  = (const float*)d_in[9];
    const float* an_bias = (const float*)d_in[10];
    const float* na_bias = (const float*)d_in[11];
    const float* ah_bias = (const float*)d_in[12];
    const float* aw_bias = (const float*)d_in[13];
    const float* ha_bias = (const float*)d_in[14];
    const float* wa_bias = (const float*)d_in[15];
    float* out = (float*)d_out;

    float  *pooled, *convp, *agent_cs, *ban, *bna, *agv;
    __half *qkvh, *xh, *whT, *pwhT, *cwh, *colh, *outh;
    cudaGetSymbolAddress((void**)&qkvh,     g_qkvh);
    cudaGetSymbolAddress((void**)&xh,       g_xh);
    cudaGetSymbolAddress((void**)&whT,      g_whT);
    cudaGetSymbolAddress((void**)&pwhT,     g_pwhT);
    cudaGetSymbolAddress((void**)&cwh,      g_cwh);
    cudaGetSymbolAddress((void**)&pooled,   g_pooled);
    cudaGetSymbolAddress((void**)&colh,     g_colh);
    cudaGetSymbolAddress((void**)&convp,    g_convp);
    cudaGetSymbolAddress((void**)&agent_cs, g_agent_cs);
    cudaGetSymbolAddress((void**)&ban,      g_bias_an);
    cudaGetSymbolAddress((void**)&bna,      g_bias_na);
    cudaGetSymbolAddress((void**)&agv,      g_agv);
    cudaGetSymbolAddress((void**)&outh,     g_outh);

    cudaFuncSetAttribute(gemm_f16a,
                         cudaFuncAttributeMaxDynamicSharedMemorySize, GSMEM);
    cudaFuncSetAttribute(agent_flash_mma,
                         cudaFuncAttributeMaxDynamicSharedMemorySize, FL_SMEM);
    cudaFuncSetAttribute(qattn_mma,
                         cudaFuncAttributeMaxDynamicSharedMemorySize, QA_SMEM);

    // 1. operand prep
    {
        size_t nx = (size_t)B * N_TOK * DIM;
        cvt_h_kernel<<<(int)((nx + 255) / 256), 256>>>(x, xh, nx);
    }
    transpose_h<<<dim3(IC / 32, DIM / 32), 256>>>(Wq, whT, DIM, IC);
    transpose_h<<<dim3((2 * IC) / 32, DIM / 32), 256>>>(
        Wkv, whT + (size_t)IC * DIM, DIM, 2 * IC);
    transpose_h<<<dim3(IC / 32, DIM / 32), 256>>>(proj_w, pwhT, DIM, IC);
    {
        size_t nc = (size_t)IC * KCONV;
        cvt_h_kernel<<<(int)((nc + 255) / 256), 256>>>(conv_w, cwh, nc);
    }

    // 2. fused QKV GEMM -> fp16
    gemm_f16a<<<dim3(NQKV / 128, (B * N_TOK) / 128, 1), 256, GSMEM>>>(
        xh, DIM, whT, DIM, nullptr, nullptr, qkvh,
        B * N_TOK, NQKV, DIM, 0, 0, 0);

    // 3. adaptive pool
    pool_kernel<<<dim3(AG, B), 256>>>(qkvh, context, pooled);

    // 4. conv: im2col(fp16) + split-K GEMM + reduce
    im2col_kernel<<<(int)(((size_t)MCONV * KCONV + 255) / 256), 256>>>(pooled, colh);
    gemm_f16a<<<dim3(IC / 128, (MCONV + 127) / 128, KSPLIT), 256, GSMEM>>>(
        colh, KCONV, cwh, KCONV, nullptr, convp, nullptr,
        MCONV, IC, KSLAB,
        (size_t)KSLAB, (size_t)KSLAB, (size_t)MCONV * IC);
    conv_reduce_tr<<<dim3(B, IC / 64), 256>>>(convp, conv_b, agent_cs);

    // 5. bias tables
    bias_an_kernel<<<(NH * AG * N_TOK + 255) / 256, 256>>>(an_bias, ah_bias, aw_bias, ban);
    bias_na_kernel<<<(NH * N_TOK * AG + 255) / 256, 256>>>(na_bias, ha_bias, wa_bias, bna);

    // 6. agent attention (tensor-core flash)
    agent_flash_mma<<<dim3(B, NH), 256, FL_SMEM>>>(qkvh, agent_cs, ban, agv);

    // 7. query attention (tensor-core) -> outh (fp16)
    qattn_mma<<<dim3(B, NH, N_TOK / 64), 128, QA_SMEM>>>(
        qkvh, agent_cs, agv, bna, outh);

    // 8. depthwise conv residual, fused in-place into outh
    dwc_kernel<<<dim3(N_TOK, B, IC / 128), 128>>>(qkvh, dwc_w, dwc_b, outh);

    // 9. output projection
    gemm_f16a<<<dim3(IC / 128, (B * N_TOK) / 128, 1), 256, GSMEM>>>(
        outh, IC, pwhT, DIM, proj_b, out, nullptr,
        B * N_TOK, IC, DIM, 0, 0, 0);

    (void)in_sizes; (void)n_in; (void)out_size;
}

// round 14
// speedup vs baseline: 1.9442x; 1.0763x over previous
#include <cuda_runtime.h>
#include <cuda_fp16.h>
#include <cstdint>

// ---------------------------------------------------------------------------
// Problem constants
// ---------------------------------------------------------------------------
#define B 32
#define N_TOK 1024
#define DIM 512
#define IC 512
#define CC 256
#define NH 8
#define AG 49
#define HD 64
#define HH 32
#define WW 32
#define CIN 768            // IC + CC
#define KCONV 6912         // 768*9
#define MCONV 1568         // B*49
#define NQKV 1536          // IC + 2*IC
#define AGFLAT 25088       // IC*AG
#define KSPLIT 4
#define KSLAB 1728         // KCONV / KSPLIT

// ---------------------------------------------------------------------------
// Scratch (static device globals; no allocation allowed)
// ---------------------------------------------------------------------------
__device__ __half g_qkvh[(size_t)B * N_TOK * NQKV];          // [q|k|v] fp16
__device__ __half g_xh[(size_t)B * N_TOK * DIM];             // x in fp16
__device__ __half g_whT[(size_t)NQKV * DIM];                 // [j][k]
__device__ __half g_pwhT[(size_t)IC * DIM];
__device__ __half g_cwh[(size_t)IC * KCONV];
__device__ float  g_pooled[(size_t)B * AG * CIN];
__device__ __half g_colh[(size_t)MCONV * KCONV];
__device__ float  g_convp[(size_t)KSPLIT * MCONV * IC];
__device__ float  g_agent_cs[(size_t)B * AGFLAT];
__device__ float  g_bias_an[NH * AG * N_TOK];
__device__ float  g_bias_na[NH * N_TOK * AG];
__device__ float  g_agv[(size_t)B * NH * AG * HD];
__device__ __half g_outh[(size_t)B * N_TOK * IC];

// ---------------------------------------------------------------------------
// PTX helpers
// ---------------------------------------------------------------------------
#define LDSM4(r0, r1, r2, r3, addr)                                      \
    asm volatile("ldmatrix.sync.aligned.m8n8.x4.shared.b16 "             \
                 "{%0,%1,%2,%3}, [%4];"                                  \
                 : "=r"(r0), "=r"(r1), "=r"(r2), "=r"(r3) : "r"(addr))

#define MMA_F16(d, a, b0, b1)                                            \
    asm volatile(                                                        \
        "mma.sync.aligned.m16n8k16.row.col.f32.f16.f16.f32 "             \
        "{%0,%1,%2,%3}, {%4,%5,%6,%7}, {%8,%9}, {%0,%1,%2,%3};"          \
        : "+f"((d)[0]), "+f"((d)[1]), "+f"((d)[2]), "+f"((d)[3])         \
        : "r"((a)[0]), "r"((a)[1]), "r"((a)[2]), "r"((a)[3]),            \
          "r"(b0), "r"(b1))

#define CP16(dst, src, bytes)                                            \
    asm volatile("cp.async.ca.shared.global [%0], [%1], 16, %2;"         \
                 :: "r"(dst), "l"(src), "r"(bytes))
#define CP_COMMIT() asm volatile("cp.async.commit_group;")
#define CP_WAIT(n)  asm volatile("cp.async.wait_group %0;" :: "n"(n))

__device__ __forceinline__ uint32_t smem_u32(const void* p) {
    uint32_t a;
    asm("{ .reg .u64 t; cvta.to.shared.u64 t, %1; cvt.u32.u64 %0, t; }"
        : "=r"(a) : "l"(p));
    return a;
}

// ---------------------------------------------------------------------------
// fp16 tensor-core GEMM, cp.async 3-stage pipeline (single product).
// ---------------------------------------------------------------------------
#define TROW   40
#define TILEB  10240
#define STAGEB (2 * TILEB)
#define NSTAGE 3
#define GSMEM  (NSTAGE * STAGEB)

__global__ __launch_bounds__(256, 2) void gemm_f16a(
    const __half* __restrict__ A, int lda,
    const __half* __restrict__ Bh, int ldb,
    const float* __restrict__ bias, float* __restrict__ C,
    __half* __restrict__ Ch,
    int M, int N, int K,
    size_t az, size_t bz, size_t cz)
{
    extern __shared__ __half sm[];

    A  += (size_t)blockIdx.z * az;
    Bh += (size_t)blockIdx.z * bz;
    if (C)  C  += (size_t)blockIdx.z * cz;
    if (Ch) Ch += (size_t)blockIdx.z * cz;

    int t = threadIdx.x;
    int lane = t & 31, wid = t >> 5;
    int wm = (wid & 1) * 64, wn = (wid >> 1) * 32;
    int rr = lane & 7, j = lane >> 3;
    int m0 = blockIdx.y * 128, n0 = blockIdx.x * 128;

    float acc[4][4][4];
#pragma unroll
    for (int i = 0; i < 4; i++)
#pragma unroll
        for (int jj = 0; jj < 4; jj++)
#pragma unroll
            for (int k = 0; k < 4; k++) acc[i][jj][k] = 0.0f;

    int srow = t >> 1, shalf = t & 1;
    bool aok = (m0 + srow) < M;
    const __half* Ap  = A + (size_t)(aok ? (m0 + srow) : 0) * lda + shalf * 16;
    const __half* Bhp = Bh + (size_t)(n0 + srow) * ldb + shalf * 16;
    uint32_t abytes = aok ? 16u : 0u;
    uint32_t sm_u = smem_u32(sm);
    uint32_t sdst = (uint32_t)(srow * 80 + shalf * 32);

    uint32_t a_off[2][4];
#pragma unroll
    for (int kk = 0; kk < 2; kk++)
#pragma unroll
        for (int mf = 0; mf < 4; mf++)
            a_off[kk][mf] = (uint32_t)(((wm + mf * 16 + rr + (j & 1) * 8) * TROW
                                        + kk * 16 + (j >> 1) * 8) * 2);
    uint32_t b_off[2][2];
#pragma unroll
    for (int kk = 0; kk < 2; kk++)
#pragma unroll
        for (int p = 0; p < 2; p++)
            b_off[kk][p] = (uint32_t)(((wn + p * 16 + rr + (j >> 1) * 8) * TROW
                                       + kk * 16 + (j & 1) * 8) * 2);

#define ISSUE(stg, kt)                                                    \
    {   uint32_t base = sm_u + (stg) * STAGEB + sdst;                     \
        const __half* as = Ap + (kt);                                     \
        CP16(base, as, abytes); CP16(base + 16, as + 8, abytes);          \
        const __half* hs = Bhp + (kt);                                    \
        CP16(base + TILEB, hs, 16u); CP16(base + TILEB + 16, hs + 8, 16u);\
        CP_COMMIT(); }

    int NC = K / 32;
    ISSUE(0, 0);
    if (NC > 1) ISSUE(1, 32);

    for (int c = 0; c < NC; c++) {
        if (c + 1 < NC) { CP_WAIT(1); } else { CP_WAIT(0); }
        __syncthreads();
        if (c + 2 < NC) ISSUE((c + 2) % NSTAGE, (c + 2) * 32);

        uint32_t bb = sm_u + (c % NSTAGE) * STAGEB;
#pragma unroll
        for (int kk = 0; kk < 2; kk++) {
            uint32_t bhf[8];
            LDSM4(bhf[0], bhf[1], bhf[2], bhf[3], bb + TILEB + b_off[kk][0]);
            LDSM4(bhf[4], bhf[5], bhf[6], bhf[7], bb + TILEB + b_off[kk][1]);
#pragma unroll
            for (int mf = 0; mf < 4; mf++) {
                uint32_t ahf[4];
                LDSM4(ahf[0], ahf[1], ahf[2], ahf[3], bb + a_off[kk][mf]);
#pragma unroll
                for (int nf = 0; nf < 4; nf++)
                    MMA_F16(acc[mf][nf], ahf, bhf[nf * 2], bhf[nf * 2 + 1]);
            }
        }
        __syncthreads();
    }

    int er = lane >> 2, ec = (lane & 3) * 2;
#pragma unroll
    for (int nf = 0; nf < 4; nf++) {
        int col = n0 + wn + nf * 8 + ec;
        float bb0 = bias ? bias[col] : 0.0f;
        float bb1 = bias ? bias[col + 1] : 0.0f;
#pragma unroll
        for (int mf = 0; mf < 4; mf++) {
            int row = m0 + wm + mf * 16 + er;
            if (row < M) {
                float v0 = acc[mf][nf][0] + bb0, v1 = acc[mf][nf][1] + bb1;
                if (Ch)
                    *(__half2*)&Ch[(size_t)row * N + col]
                        = __halves2half2(__float2half(v0), __float2half(v1));
                else
                    *(float2*)&C[(size_t)row * N + col] = make_float2(v0, v1);
            }
            if (row + 8 < M) {
                float v0 = acc[mf][nf][2] + bb0, v1 = acc[mf][nf][3] + bb1;
                if (Ch)
                    *(__half2*)&Ch[(size_t)(row + 8) * N + col]
                        = __halves2half2(__float2half(v0), __float2half(v1));
                else
                    *(float2*)&C[(size_t)(row + 8) * N + col] = make_float2(v0, v1);
            }
        }
    }
}

// ---------------------------------------------------------------------------
// Merged pre-convert kernels
// ---------------------------------------------------------------------------
// z=0: Wq (512x512)->whT; z=1: Wkv (512x1024)->whT+IC*DIM; z=2: proj->pwhT
__global__ __launch_bounds__(256) void transpose3_h(
    const float* __restrict__ Wq, const float* __restrict__ Wkv,
    const float* __restrict__ proj_w,
    __half* __restrict__ whT, __half* __restrict__ pwhT)
{
    __shared__ float tile[32][33];
    int z = blockIdx.z;
    const float* src; __half* dst; int C;
    if (z == 0)      { src = Wq;     dst = whT;                       C = IC; }
    else if (z == 1) { src = Wkv;    dst = whT + (size_t)IC * DIM;    C = 2 * IC; }
    else             { src = proj_w; dst = pwhT;                      C = IC; }
    int cb = blockIdx.x * 32, rb = blockIdx.y * 32;
    if (cb >= C) return;
    int tx = threadIdx.x & 31, ty = threadIdx.x >> 5;
    for (int i = ty; i < 32; i += 8) {
        int r = rb + i, c = cb + tx;
        if (c < C) tile[i][tx] = src[(size_t)r * C + c];
    }
    __syncthreads();
    for (int i = ty; i < 32; i += 8) {
        int c = cb + i, r = rb + tx;
        if (c < C) dst[(size_t)c * DIM + r] = __float2half(tile[tx][i]);
    }
}

// flat cvt: x -> xh (nx elems), then conv_w -> cwh (nc elems)
__global__ void cvt2_kernel(const float* __restrict__ x,
                            const float* __restrict__ conv_w,
                            __half* __restrict__ xh, __half* __restrict__ cwh,
                            size_t nx, size_t nc)
{
    size_t i = (size_t)blockIdx.x * blockDim.x + threadIdx.x;
    if (i < nx) xh[i] = __float2half(x[i]);
    else if (i < nx + nc) cwh[i - nx] = __float2half(conv_w[i - nx]);
}

// ---------------------------------------------------------------------------
// Adaptive pooling -> pooled[b][a*768 + c].  One block per (a, b).
// ---------------------------------------------------------------------------
__global__ __launch_bounds__(256) void pool_kernel(
    const __half* __restrict__ qkvh, const float* __restrict__ context,
    float* __restrict__ pooled)
{
    int a = blockIdx.x, b = blockIdx.y;
    int p = a / 7, q = a % 7;
    int sh = p * 32 / 7, eh = ((p + 1) * 32 + 6) / 7;
    int sw = q * 32 / 7, ew = ((q + 1) * 32 + 6) / 7;
    float inv = 1.0f / (float)((eh - sh) * (ew - sw));
    for (int c = threadIdx.x; c < CIN; c += 256) {
        float s = 0.0f;
        if (c < IC) {
            for (int hh = sh; hh < eh; hh++) {
                const __half* row = qkvh + ((size_t)(b * N_TOK) + hh * WW) * NQKV + c;
                for (int ww = sw; ww < ew; ww++)
                    s += __half2float(row[(size_t)ww * NQKV]);
            }
        } else {
            for (int hh = sh; hh < eh; hh++) {
                const float* row = context + ((size_t)(b * N_TOK) + hh * WW) * CC + (c - IC);
                for (int ww = sw; ww < ew; ww++) s += row[(size_t)ww * CC];
            }
        }
        pooled[((size_t)b * AG + a) * CIN + c] = s * inv;
    }
}

// im2col (fp16 out)
__global__ void im2col_kernel(const float* __restrict__ pooled,
                              __half* __restrict__ col)
{
    size_t idx = (size_t)blockIdx.x * blockDim.x + threadIdx.x;
    if (idx >= (size_t)MCONV * KCONV) return;
    int ck = idx % KCONV;
    int row = idx / KCONV;
    int ci = ck / 9, k9 = ck % 9;
    int ky = k9 / 3, kx = k9 % 3;
    int b = row / AG, p = row % AG;
    int py = p / 7, px = p % 7;
    int sy = py + ky - 1, sx = px + kx - 1;
    float v = 0.0f;
    if (sy >= 0 && sy < 7 && sx >= 0 && sx < 7)
        v = pooled[(size_t)b * (AG * CIN) + ci * AG + sy * 7 + sx];
    col[idx] = __float2half(v);
}

// Reduce split-K partials + conv bias, transpose to agent_cs[b][c*49+s]
__global__ __launch_bounds__(256) void conv_reduce_tr(
    const float* __restrict__ parts, const float* __restrict__ conv_b,
    float* __restrict__ out)
{
    int b = blockIdx.x, cb = blockIdx.y * 64;
    __shared__ float tile[64][50];
    int t = threadIdx.x;
    for (int e = t; e < 64 * AG; e += 256) {
        int c = e & 63, s = e >> 6;
        float v = conv_b[cb + c];
#pragma unroll
        for (int p = 0; p < KSPLIT; p++)
            v += parts[(size_t)p * MCONV * IC + ((size_t)b * AG + s) * IC + cb + c];
        tile[c][s] = v;
    }
    __syncthreads();
    for (int e = t; e < 64 * AG; e += 256) {
        int s = e % AG, c = e / AG;
        out[(size_t)b * AGFLAT + (cb + c) * AG + s] = tile[c][s];
    }
}

// ---------------------------------------------------------------------------
// Bias tables (merged: blockIdx.y==0 -> an table; ==1 -> na table)
// ---------------------------------------------------------------------------
__device__ __forceinline__ float bilin7(const float* __restrict__ src, int yi, int xi)
{
    float fy = (yi + 0.5f) * (7.0f / 32.0f) - 0.5f;
    float fx = (xi + 0.5f) * (7.0f / 32.0f) - 0.5f;
    int y0 = (int)floorf(fy); float wy = fy - (float)y0;
    int x0 = (int)floorf(fx); float wx = fx - (float)x0;
    int y0c = max(y0, 0), y1c = min(y0 + 1, 6);
    int x0c = max(x0, 0), x1c = min(x0 + 1, 6);
    float v00 = src[y0c * 7 + x0c], v01 = src[y0c * 7 + x1c];
    float v10 = src[y1c * 7 + x0c], v11 = src[y1c * 7 + x1c];
    return (1.f - wy) * ((1.f - wx) * v00 + wx * v01)
         + wy * ((1.f - wx) * v10 + wx * v11);
}

__global__ void bias_both_kernel(
    const float* __restrict__ an_bias, const float* __restrict__ ah_bias,
    const float* __restrict__ aw_bias,
    const float* __restrict__ na_bias, const float* __restrict__ ha_bias,
    const float* __restrict__ wa_bias,
    float* __restrict__ out_an, float* __restrict__ out_na)
{
    int idx = blockIdx.x * blockDim.x + threadIdx.x;
    if (blockIdx.y == 0) {
        if (idx >= NH * AG * N_TOK) return;
        int n = idx % N_TOK;
        int r = idx / N_TOK;
        int a = r % AG, h = r / AG;
        int hi = n >> 5, wi = n & 31;
        const float* src = an_bias + (size_t)(h * AG + a) * 49;
        out_an[idx] = bilin7(src, hi, wi)
                    + ah_bias[(h * AG + a) * 32 + hi]
                    + aw_bias[(h * AG + a) * 32 + wi];
    } else {
        if (idx >= NH * N_TOK * AG) return;
        int a = idx % AG;
        int r = idx / AG;
        int n = r % N_TOK, h = r / N_TOK;
        int hi = n >> 5, wi = n & 31;
        const float* src = na_bias + (size_t)(h * AG + a) * 49;
        out_na[idx] = bilin7(src, hi, wi)
                    + ha_bias[(h * 32 + hi) * AG + a]
                    + wa_bias[(h * 32 + wi) * AG + a];
    }
}

// ---------------------------------------------------------------------------
// Agent attention (flash, tensor-core).  One block per (b,h), 256 threads.
// ---------------------------------------------------------------------------
#define FL_SS 0
#define FL_AT 34048
#define FL_KS 43264
#define FL_VT 61696
#define FL_PS 79104
#define FL_MR 96512
#define FL_LR 96768
#define FL_FR 97024
#define FL_PM 97280
#define FL_PX 98304
#define FL_SMEM 99328

__global__ __launch_bounds__(256) void agent_flash_mma(
    const __half* __restrict__ qkvh, const float* __restrict__ agent_cs,
    const float* __restrict__ bias_an, float* __restrict__ agv)
{
    extern __shared__ char fsm[];
    float*  SS = (float*)(fsm + FL_SS);      // stride 133
    __half* AT = (__half*)(fsm + FL_AT);     // stride 72
    __half* KS = (__half*)(fsm + FL_KS);     // stride 72
    __half* VT = (__half*)(fsm + FL_VT);     // stride 136
    __half* PS = (__half*)(fsm + FL_PS);     // stride 136
    float*  MR = (float*)(fsm + FL_MR);
    float*  LR = (float*)(fsm + FL_LR);
    float*  FR = (float*)(fsm + FL_FR);
    float*  PM = (float*)(fsm + FL_PM);
    float*  PX = (float*)(fsm + FL_PX);

    int b = blockIdx.x, h = blockIdx.y, t = threadIdx.x;
    int lane = t & 31, wid = t >> 5;
    int rr = lane & 7, j = lane >> 3;
    int er = lane >> 2, ec = (lane & 3) * 2;
    int rid = t >> 2, seg = t & 3;

    uint32_t at_u = smem_u32(AT), ks_u = smem_u32(KS);
    uint32_t vt_u = smem_u32(VT), ps_u = smem_u32(PS);

    int wm1 = (wid & 1) * 32, wn1 = (wid >> 1) * 32;
    int wm2 = (wid & 3) * 16, wn2 = (wid >> 2) * 32;

    for (int e = t; e < 64 * 64; e += 256) {
        int a = e >> 6, d = e & 63;
        AT[a * 72 + d] = (a < AG)
            ? __float2half(agent_cs[(size_t)b * AGFLAT + a * IC + h * HD + d])
            : __half(0.0f);
    }
    if (t < 64) { MR[t] = -1e30f; LR[t] = 0.0f; }

    float acc2[4][4];
#pragma unroll
    for (int nf = 0; nf < 4; nf++)
#pragma unroll
        for (int k = 0; k < 4; k++) acc2[nf][k] = 0.0f;

    uint32_t a1_off[4][2], b1_off[4][2];
#pragma unroll
    for (int kk = 0; kk < 4; kk++) {
#pragma unroll
        for (int mf = 0; mf < 2; mf++)
            a1_off[kk][mf] = (uint32_t)(((wm1 + mf * 16 + rr + (j & 1) * 8) * 72
                                         + kk * 16 + (j >> 1) * 8) * 2);
#pragma unroll
        for (int p = 0; p < 2; p++)
            b1_off[kk][p] = (uint32_t)(((wn1 + p * 16 + rr + (j >> 1) * 8) * 72
                                        + kk * 16 + (j & 1) * 8) * 2);
    }
    uint32_t a2_off[8], b2_off[8][2];
#pragma unroll
    for (int kk = 0; kk < 8; kk++) {
        a2_off[kk] = (uint32_t)(((wm2 + rr + (j & 1) * 8) * 136
                                 + kk * 16 + (j >> 1) * 8) * 2);
#pragma unroll
        for (int p = 0; p < 2; p++)
            b2_off[kk][p] = (uint32_t)(((wn2 + p * 16 + rr + (j >> 1) * 8) * 136
                                        + kk * 16 + (j & 1) * 8) * 2);
    }

    for (int jt = 0; jt < N_TOK; jt += 128) {
        __syncthreads();
        for (int e = t; e < 1024; e += 256) {
            int jj = e >> 3, ch = e & 7;
            *(float4*)(KS + jj * 72 + ch * 8) = *(const float4*)(
                qkvh + ((size_t)(b * N_TOK + jt + jj)) * NQKV + IC + h * HD + ch * 8);
        }
        for (int e = t; e < 8192; e += 256) {
            int d = e & 63, jj = e >> 6;
            VT[d * 136 + jj] =
                qkvh[((size_t)(b * N_TOK + jt + jj)) * NQKV + 2 * IC + h * HD + d];
        }
        __syncthreads();

        float acc1[2][4][4];
#pragma unroll
        for (int mf = 0; mf < 2; mf++)
#pragma unroll
            for (int nf = 0; nf < 4; nf++)
#pragma unroll
                for (int k = 0; k < 4; k++) acc1[mf][nf][k] = 0.0f;
#pragma unroll
        for (int kk = 0; kk < 4; kk++) {
            uint32_t bf[8];
            LDSM4(bf[0], bf[1], bf[2], bf[3], ks_u + b1_off[kk][0]);
            LDSM4(bf[4], bf[5], bf[6], bf[7], ks_u + b1_off[kk][1]);
#pragma unroll
            for (int mf = 0; mf < 2; mf++) {
                uint32_t af[4];
                LDSM4(af[0], af[1], af[2], af[3], at_u + a1_off[kk][mf]);
#pragma unroll
                for (int nf = 0; nf < 4; nf++)
                    MMA_F16(acc1[mf][nf], af, bf[nf * 2], bf[nf * 2 + 1]);
            }
        }
#pragma unroll
        for (int mf = 0; mf < 2; mf++) {
            int a0 = wm1 + mf * 16 + er, a1 = a0 + 8;
            const float* bb0 = (a0 < AG) ? bias_an + (size_t)(h * AG + a0) * N_TOK + jt : nullptr;
            const float* bb1 = (a1 < AG) ? bias_an + (size_t)(h * AG + a1) * N_TOK + jt : nullptr;
#pragma unroll
            for (int nf = 0; nf < 4; nf++) {
                int jc = wn1 + nf * 8 + ec;
                if (bb0) {
                    SS[a0 * 133 + jc]     = acc1[mf][nf][0] * 0.125f + bb0[jc];
                    SS[a0 * 133 + jc + 1] = acc1[mf][nf][1] * 0.125f + bb0[jc + 1];
                } else {
                    SS[a0 * 133 + jc] = -1e30f; SS[a0 * 133 + jc + 1] = -1e30f;
                }
                if (bb1) {
                    SS[a1 * 133 + jc]     = acc1[mf][nf][2] * 0.125f + bb1[jc];
                    SS[a1 * 133 + jc + 1] = acc1[mf][nf][3] * 0.125f + bb1[jc + 1];
                } else {
                    SS[a1 * 133 + jc] = -1e30f; SS[a1 * 133 + jc + 1] = -1e30f;
                }
            }
        }
        __syncthreads();

        {
            float pm = -1e30f;
            const float* row = SS + rid * 133 + seg * 32;
            for (int i = 0; i < 32; i++) pm = fmaxf(pm, row[i]);
            PM[rid * 4 + seg] = pm;
        }
        __syncthreads();
        if (t < 64) {
            float mnew = fmaxf(fmaxf(PM[t * 4], PM[t * 4 + 1]),
                               fmaxf(PM[t * 4 + 2], PM[t * 4 + 3]));
            mnew = fmaxf(MR[t], mnew);
            FR[t] = __expf(MR[t] - mnew);
            MR[t] = mnew;
        }
        __syncthreads();
        {
            float m = MR[rid], ps = 0.0f;
            const float* row = SS + rid * 133 + seg * 32;
            __half* prow = PS + rid * 136 + seg * 32;
            for (int i = 0; i < 32; i++) {
                float e = __expf(row[i] - m);
                prow[i] = __float2half(e);
                ps += e;
            }
            PX[rid * 4 + seg] = ps;
        }
        __syncthreads();
        if (t < 64)
            LR[t] = LR[t] * FR[t]
                  + PX[t * 4] + PX[t * 4 + 1] + PX[t * 4 + 2] + PX[t * 4 + 3];

        {
            float f0 = FR[wm2 + er], f1 = FR[wm2 + er + 8];
#pragma unroll
            for (int nf = 0; nf < 4; nf++) {
                acc2[nf][0] *= f0; acc2[nf][1] *= f0;
                acc2[nf][2] *= f1; acc2[nf][3] *= f1;
            }
        }
#pragma unroll
        for (int kk = 0; kk < 8; kk++) {
            uint32_t bf[8];
            LDSM4(bf[0], bf[1], bf[2], bf[3], vt_u + b2_off[kk][0]);
            LDSM4(bf[4], bf[5], bf[6], bf[7], vt_u + b2_off[kk][1]);
            uint32_t af[4];
            LDSM4(af[0], af[1], af[2], af[3], ps_u + a2_off[kk]);
#pragma unroll
            for (int nf = 0; nf < 4; nf++)
                MMA_F16(acc2[nf], af, bf[nf * 2], bf[nf * 2 + 1]);
        }
    }

    __syncthreads();
    {
        int a0 = wm2 + er, a1 = a0 + 8;
        float i0 = (a0 < AG) ? 1.0f / LR[a0] : 0.0f;
        float i1 = (a1 < AG) ? 1.0f / LR[a1] : 0.0f;
#pragma unroll
        for (int nf = 0; nf < 4; nf++) {
            int d = wn2 + nf * 8 + ec;
            if (a0 < AG)
                *(float2*)&agv[(((size_t)(b * NH + h) * AG) + a0) * HD + d]
                    = make_float2(acc2[nf][0] * i0, acc2[nf][1] * i0);
            if (a1 < AG)
                *(float2*)&agv[(((size_t)(b * NH + h) * AG) + a1) * HD + d]
                    = make_float2(acc2[nf][2] * i1, acc2[nf][3] * i1);
        }
    }
}

// ---------------------------------------------------------------------------
// Query attention (tensor-core) -> outh (fp16).  Block (b,h,nt), 128 threads.
// ---------------------------------------------------------------------------
#define QA_SS 0
#define QA_QS 16640
#define QA_AT 25856
#define QA_PS 35072
#define QA_SMEM 44288

__global__ __launch_bounds__(128) void qattn_mma(
    const __half* __restrict__ qkvh, const float* __restrict__ agent_cs,
    const float* __restrict__ agv, const float* __restrict__ bias_na,
    __half* __restrict__ outh)
{
    extern __shared__ char qsm[];
    float*  SS  = (float*)(qsm + QA_SS);
    __half* QS  = (__half*)(qsm + QA_QS);
    __half* ATS = (__half*)(qsm + QA_AT);
    __half* PS  = (__half*)(qsm + QA_PS);

    int b = blockIdx.x, h = blockIdx.y, nt = blockIdx.z;
    int t = threadIdx.x;
    int lane = t & 31, wid = t >> 5;
    int rr = lane & 7, j = lane >> 3;
    int er = lane >> 2, ec = (lane & 3) * 2;
    int wm = (wid & 1) * 32, wn = (wid >> 1) * 32;

    uint32_t qs_u = smem_u32(QS), at_u = smem_u32(ATS), ps_u = smem_u32(PS);

    for (int e = t; e < 512; e += 128) {
        int nn = e >> 3, ch = e & 7;
        *(float4*)(QS + nn * 72 + ch * 8) = *(const float4*)(
            qkvh + ((size_t)(b * N_TOK) + nt * 64 + nn) * NQKV + h * HD + ch * 8);
    }
    for (int e = t; e < 64 * 64; e += 128) {
        int a = e >> 6, d = e & 63;
        ATS[a * 72 + d] = (a < AG)
            ? __float2half(agent_cs[(size_t)b * AGFLAT + a * IC + h * HD + d])
            : __half(0.0f);
    }
    __syncthreads();

    uint32_t a_off[4][2], b_off[4][2];
#pragma unroll
    for (int kk = 0; kk < 4; kk++) {
#pragma unroll
        for (int mf = 0; mf < 2; mf++)
            a_off[kk][mf] = (uint32_t)(((wm + mf * 16 + rr + (j & 1) * 8) * 72
                                        + kk * 16 + (j >> 1) * 8) * 2);
#pragma unroll
        for (int p = 0; p < 2; p++)
            b_off[kk][p] = (uint32_t)(((wn + p * 16 + rr + (j >> 1) * 8) * 72
                                       + kk * 16 + (j & 1) * 8) * 2);
    }

    float acc[2][4][4];
#pragma unroll
    for (int mf = 0; mf < 2; mf++)
#pragma unroll
        for (int nf = 0; nf < 4; nf++)
#pragma unroll
            for (int k = 0; k < 4; k++) acc[mf][nf][k] = 0.0f;

#pragma unroll
    for (int kk = 0; kk < 4; kk++) {
        uint32_t bf[8];
        LDSM4(bf[0], bf[1], bf[2], bf[3], at_u + b_off[kk][0]);
        LDSM4(bf[4], bf[5], bf[6], bf[7], at_u + b_off[kk][1]);
#pragma unroll
        for (int mf = 0; mf < 2; mf++) {
            uint32_t af[4];
            LDSM4(af[0], af[1], af[2], af[3], qs_u + a_off[kk][mf]);
#pragma unroll
            for (int nf = 0; nf < 4; nf++)
                MMA_F16(acc[mf][nf], af, bf[nf * 2], bf[nf * 2 + 1]);
        }
    }
#pragma unroll
    for (int mf = 0; mf < 2; mf++) {
        int tok0 = wm + mf * 16 + er, tok1 = tok0 + 8;
        const float* bn0 = bias_na + ((size_t)(h * N_TOK) + nt * 64 + tok0) * AG;
        const float* bn1 = bias_na + ((size_t)(h * N_TOK) + nt * 64 + tok1) * AG;
#pragma unroll
        for (int nf = 0; nf < 4; nf++) {
            int a = wn + nf * 8 + ec;
            SS[tok0 * 65 + a]     = (a < AG)     ? acc[mf][nf][0] * 0.125f + bn0[a]     : -1e30f;
            SS[tok0 * 65 + a + 1] = (a + 1 < AG) ? acc[mf][nf][1] * 0.125f + bn0[a + 1] : -1e30f;
            SS[tok1 * 65 + a]     = (a < AG)     ? acc[mf][nf][2] * 0.125f + bn1[a]     : -1e30f;
            SS[tok1 * 65 + a + 1] = (a + 1 < AG) ? acc[mf][nf][3] * 0.125f + bn1[a + 1] : -1e30f;
        }
    }
    __syncthreads();

    if (t < 64) {
        const float* row = SS + t * 65;
        float m = -1e30f;
        for (int a = 0; a < 64; a++) m = fmaxf(m, row[a]);
        float s = 0.0f;
        float e[64];
        for (int a = 0; a < 64; a++) { e[a] = __expf(row[a] - m); s += e[a]; }
        float inv = 1.0f / s;
        __half* prow = PS + t * 72;
        for (int a = 0; a < 64; a++) prow[a] = __float2half(e[a] * inv);
    } else {
        int d = t - 64;
        __half* vrow = ATS + d * 72;
        const float* ga = agv + ((size_t)(b * NH + h) * AG) * HD + d;
        for (int a = 0; a < AG; a++) vrow[a] = __float2half(ga[(size_t)a * HD]);
        for (int a = AG; a < 64; a++) vrow[a] = __half(0.0f);
    }
    __syncthreads();

#pragma unroll
    for (int mf = 0; mf < 2; mf++)
#pragma unroll
        for (int nf = 0; nf < 4; nf++)
#pragma unroll
            for (int k = 0; k < 4; k++) acc[mf][nf][k] = 0.0f;
#pragma unroll
    for (int kk = 0; kk < 4; kk++) {
        uint32_t bf[8];
        LDSM4(bf[0], bf[1], bf[2], bf[3], at_u + b_off[kk][0]);
        LDSM4(bf[4], bf[5], bf[6], bf[7], at_u + b_off[kk][1]);
#pragma unroll
        for (int mf = 0; mf < 2; mf++) {
            uint32_t af[4];
            LDSM4(af[0], af[1], af[2], af[3], ps_u + a_off[kk][mf]);
#pragma unroll
            for (int nf = 0; nf < 4; nf++)
                MMA_F16(acc[mf][nf], af, bf[nf * 2], bf[nf * 2 + 1]);
        }
    }
#pragma unroll
    for (int mf = 0; mf < 2; mf++) {
        int tok0 = nt * 64 + wm + mf * 16 + er;
#pragma unroll
        for (int nf = 0; nf < 4; nf++) {
            int d = wn + nf * 8 + ec;
            *(__half2*)&outh[((size_t)(b * N_TOK) + tok0) * IC + h * HD + d]
                = __halves2half2(__float2half(acc[mf][nf][0]),
                                 __float2half(acc[mf][nf][1]));
            *(__half2*)&outh[((size_t)(b * N_TOK) + tok0 + 8) * IC + h * HD + d]
                = __halves2half2(__float2half(acc[mf][nf][2]),
                                 __float2half(acc[mf][nf][3]));
        }
    }
}

// ---------------------------------------------------------------------------
// Depthwise 3x3 conv, sliding-window; fused in-place add into outh.
// Block = (row hh, b), 512 threads (one per channel).  Summation order
// (ky outer, kx inner, +0 for OOB) is bitwise-identical to the naive version.
// ---------------------------------------------------------------------------
__global__ __launch_bounds__(512) void dwc_kernel(
    const __half* __restrict__ qkvh,
    const float* __restrict__ dwc_w, const float* __restrict__ dwc_b,
    __half* __restrict__ outh)
{
    int hh = blockIdx.x, b = blockIdx.y;
    int c = threadIdx.x;
    float w9[9];
#pragma unroll
    for (int i = 0; i < 9; i++) w9[i] = dwc_w[c * 9 + i];
    float wb = dwc_b[c];
    const __half* vb = qkvh + (size_t)(b * N_TOK) * NQKV + 2 * IC + c;

    float c0[3], c1[3], c2[3];
#define LOADCOL(x, dst)                                                   \
    {   if ((x) < 0 || (x) >= WW) { dst[0] = dst[1] = dst[2] = 0.0f; }    \
        else {                                                            \
            _Pragma("unroll")                                             \
            for (int r = 0; r < 3; r++) {                                 \
                int y = hh - 1 + r;                                       \
                dst[r] = (y >= 0 && y < HH)                               \
                    ? __half2float(vb[(size_t)(y * WW + (x)) * NQKV])     \
                    : 0.0f;                                               \
            } } }

    LOADCOL(-1, c0);
    LOADCOL(0, c1);
    for (int x = 0; x < WW; x++) {
        LOADCOL(x + 1, c2);
        float s = wb;
#pragma unroll
        for (int r = 0; r < 3; r++) {
            s += w9[r * 3 + 0] * c0[r];
            s += w9[r * 3 + 1] * c1[r];
            s += w9[r * 3 + 2] * c2[r];
        }
        size_t i = ((size_t)(b * N_TOK) + hh * WW + x) * IC + c;
        outh[i] = __float2half(__half2float(outh[i]) + s);
#pragma unroll
        for (int r = 0; r < 3; r++) { c0[r] = c1[r]; c1[r] = c2[r]; }
    }
}

// ---------------------------------------------------------------------------
// Host launcher
// ---------------------------------------------------------------------------
extern "C" void kernel_launch(void* const* d_in, const int* in_sizes, int n_in,
                              void* d_out, int out_size)
{
    const float* x       = (const float*)d_in[0];
    const float* context = (const float*)d_in[1];
    const float* Wq      = (const float*)d_in[2];
    const float* Wkv     = (const float*)d_in[3];
    const float* conv_w  = (const float*)d_in[4];
    const float* conv_b  = (const float*)d_in[5];
    const float* dwc_w   = (const float*)d_in[6];
    const float* dwc_b   = (const float*)d_in[7];
    const float* proj_w  = (const float*)d_in[8];
    const float* proj_b  = (const float*)d_in[9];
    const float* an_bias = (const float*)d_in[10];
    const float* na_bias = (const float*)d_in[11];
    const float* ah_bias = (const float*)d_in[12];
    const float* aw_bias = (const float*)d_in[13];
    const float* ha_bias = (const float*)d_in[14];
    const float* wa_bias = (const float*)d_in[15];
    float* out = (float*)d_out;

    float  *pooled, *convp, *agent_cs, *ban, *bna, *agv;
    __half *qkvh, *xh, *whT, *pwhT, *cwh, *colh, *outh;
    cudaGetSymbolAddress((void**)&qkvh,     g_qkvh);
    cudaGetSymbolAddress((void**)&xh,       g_xh);
    cudaGetSymbolAddress((void**)&whT,      g_whT);
    cudaGetSymbolAddress((void**)&pwhT,     g_pwhT);
    cudaGetSymbolAddress((void**)&cwh,      g_cwh);
    cudaGetSymbolAddress((void**)&pooled,   g_pooled);
    cudaGetSymbolAddress((void**)&colh,     g_colh);
    cudaGetSymbolAddress((void**)&convp,    g_convp);
    cudaGetSymbolAddress((void**)&agent_cs, g_agent_cs);
    cudaGetSymbolAddress((void**)&ban,      g_bias_an);
    cudaGetSymbolAddress((void**)&bna,      g_bias_na);
    cudaGetSymbolAddress((void**)&agv,      g_agv);
    cudaGetSymbolAddress((void**)&outh,     g_outh);

    cudaFuncSetAttribute(gemm_f16a,
                         cudaFuncAttributeMaxDynamicSharedMemorySize, GSMEM);
    cudaFuncSetAttribute(agent_flash_mma,
                         cudaFuncAttributeMaxDynamicSharedMemorySize, FL_SMEM);
    cudaFuncSetAttribute(qattn_mma,
                         cudaFuncAttributeMaxDynamicSharedMemorySize, QA_SMEM);

    // 1. operand prep (merged)
    {
        size_t nx = (size_t)B * N_TOK * DIM;
        size_t nc = (size_t)IC * KCONV;
        cvt2_kernel<<<(int)((nx + nc + 255) / 256), 256>>>(
            x, conv_w, xh, cwh, nx, nc);
    }
    transpose3_h<<<dim3(32, DIM / 32, 3), 256>>>(Wq, Wkv, proj_w, whT, pwhT);

    // 2. fused QKV GEMM -> fp16
    gemm_f16a<<<dim3(NQKV / 128, (B * N_TOK) / 128, 1), 256, GSMEM>>>(
        xh, DIM, whT, DIM, nullptr, nullptr, qkvh,
        B * N_TOK, NQKV, DIM, 0, 0, 0);

    // 3. adaptive pool
    pool_kernel<<<dim3(AG, B), 256>>>(qkvh, context, pooled);

    // 4. conv: im2col(fp16) + split-K GEMM + reduce
    im2col_kernel<<<(int)(((size_t)MCONV * KCONV + 255) / 256), 256>>>(pooled, colh);
    gemm_f16a<<<dim3(IC / 128, (MCONV + 127) / 128, KSPLIT), 256, GSMEM>>>(
        colh, KCONV, cwh, KCONV, nullptr, convp, nullptr,
        MCONV, IC, KSLAB,
        (size_t)KSLAB, (size_t)KSLAB, (size_t)MCONV * IC);
    conv_reduce_tr<<<dim3(B, IC / 64), 256>>>(convp, conv_b, agent_cs);

    // 5. bias tables (merged)
    bias_both_kernel<<<dim3((NH * AG * N_TOK + 255) / 256, 2), 256>>>(
        an_bias, ah_bias, aw_bias, na_bias, ha_bias, wa_bias, ban, bna);

    // 6. agent attention (tensor-core flash)
    agent_flash_mma<<<dim3(B, NH), 256, FL_SMEM>>>(qkvh, agent_cs, ban, agv);

    // 7. query attention (tensor-core) -> outh (fp16)
    qattn_mma<<<dim3(B, NH, N_TOK / 64), 128, QA_SMEM>>>(
        qkvh, agent_cs, agv, bna, outh);

    // 8. depthwise conv residual, sliding-window, in-place into outh
    dwc_kernel<<<dim3(HH, B), 512>>>(qkvh, dwc_w, dwc_b, outh);

    // 9. output projection
    gemm_f16a<<<dim3(IC / 128, (B * N_TOK) / 128, 1), 256, GSMEM>>>(
        outh, IC, pwhT, DIM, proj_b, out, nullptr,
        B * N_TOK, IC, DIM, 0, 0, 0);

    (void)in_sizes; (void)n_in; (void)out_size;
}

// round 15
// speedup vs baseline: 2.0304x; 1.0444x over previous
#include <cuda_runtime.h>
#include <cuda_fp16.h>
#include <cstdint>

// ---------------------------------------------------------------------------
// Problem constants
// ---------------------------------------------------------------------------
#define B 32
#define N_TOK 1024
#define DIM 512
#define IC 512
#define CC 256
#define NH 8
#define AG 49
#define HD 64
#define HH 32
#define WW 32
#define CIN 768            // IC + CC
#define KCONV 6912         // 768*9
#define MCONV 1568         // B*49
#define NQKV 1536          // IC + 2*IC
#define AGFLAT 25088       // IC*AG
#define KSPLIT 4
#define KSLAB 1728         // KCONV / KSPLIT
#define PFLAT 37632        // AG*CIN per batch

// ---------------------------------------------------------------------------
// Scratch (static device globals; no allocation allowed)
// ---------------------------------------------------------------------------
__device__ __half g_qkvh[(size_t)B * N_TOK * NQKV];          // [q|k|v] fp16
__device__ __half g_xh[(size_t)B * N_TOK * DIM];             // x in fp16
__device__ __half g_whT[(size_t)NQKV * DIM];                 // [j][k]
__device__ __half g_pwhT[(size_t)IC * DIM];
__device__ __half g_cwh9[(size_t)IC * KCONV];                // [co][k9*768+ci]
__device__ float  g_pooled[(size_t)B * AG * CIN];            // natural [b][a*768+c]
__device__ __half g_poolT[(size_t)B * PFLAT];                // [b][s*768+ci] (reshaped view T)
__device__ float  g_convp[(size_t)KSPLIT * MCONV * IC];
__device__ float  g_agent_cs[(size_t)B * AGFLAT];
__device__ float  g_bias_an[NH * AG * N_TOK];
__device__ float  g_bias_na[NH * N_TOK * AG];
__device__ float  g_agv[(size_t)B * NH * AG * HD];
__device__ __half g_outh[(size_t)B * N_TOK * IC];

// ---------------------------------------------------------------------------
// PTX helpers
// ---------------------------------------------------------------------------
#define LDSM4(r0, r1, r2, r3, addr)                                      \
    asm volatile("ldmatrix.sync.aligned.m8n8.x4.shared.b16 "             \
                 "{%0,%1,%2,%3}, [%4];"                                  \
                 : "=r"(r0), "=r"(r1), "=r"(r2), "=r"(r3) : "r"(addr))

#define MMA_F16(d, a, b0, b1)                                            \
    asm volatile(                                                        \
        "mma.sync.aligned.m16n8k16.row.col.f32.f16.f16.f32 "             \
        "{%0,%1,%2,%3}, {%4,%5,%6,%7}, {%8,%9}, {%0,%1,%2,%3};"          \
        : "+f"((d)[0]), "+f"((d)[1]), "+f"((d)[2]), "+f"((d)[3])         \
        : "r"((a)[0]), "r"((a)[1]), "r"((a)[2]), "r"((a)[3]),            \
          "r"(b0), "r"(b1))

#define CP16(dst, src, bytes)                                            \
    asm volatile("cp.async.ca.shared.global [%0], [%1], 16, %2;"         \
                 :: "r"(dst), "l"(src), "r"(bytes))
#define CP_COMMIT() asm volatile("cp.async.commit_group;")
#define CP_WAIT(n)  asm volatile("cp.async.wait_group %0;" :: "n"(n))

__device__ __forceinline__ uint32_t smem_u32(const void* p) {
    uint32_t a;
    asm("{ .reg .u64 t; cvta.to.shared.u64 t, %1; cvt.u32.u64 %0, t; }"
        : "=r"(a) : "l"(p));
    return a;
}

// ---------------------------------------------------------------------------
// fp16 tensor-core GEMM, cp.async 3-stage pipeline (single product).
// ---------------------------------------------------------------------------
#define TROW   40
#define TILEB  10240
#define STAGEB (2 * TILEB)
#define NSTAGE 3
#define GSMEM  (NSTAGE * STAGEB)

__global__ __launch_bounds__(256, 2) void gemm_f16a(
    const __half* __restrict__ A, int lda,
    const __half* __restrict__ Bh, int ldb,
    const float* __restrict__ bias, float* __restrict__ C,
    __half* __restrict__ Ch,
    int M, int N, int K)
{
    extern __shared__ __half sm[];

    int t = threadIdx.x;
    int lane = t & 31, wid = t >> 5;
    int wm = (wid & 1) * 64, wn = (wid >> 1) * 32;
    int rr = lane & 7, j = lane >> 3;
    int m0 = blockIdx.y * 128, n0 = blockIdx.x * 128;

    float acc[4][4][4];
#pragma unroll
    for (int i = 0; i < 4; i++)
#pragma unroll
        for (int jj = 0; jj < 4; jj++)
#pragma unroll
            for (int k = 0; k < 4; k++) acc[i][jj][k] = 0.0f;

    int srow = t >> 1, shalf = t & 1;
    bool aok = (m0 + srow) < M;
    const __half* Ap  = A + (size_t)(aok ? (m0 + srow) : 0) * lda + shalf * 16;
    const __half* Bhp = Bh + (size_t)(n0 + srow) * ldb + shalf * 16;
    uint32_t abytes = aok ? 16u : 0u;
    uint32_t sm_u = smem_u32(sm);
    uint32_t sdst = (uint32_t)(srow * 80 + shalf * 32);

    uint32_t a_off[2][4];
#pragma unroll
    for (int kk = 0; kk < 2; kk++)
#pragma unroll
        for (int mf = 0; mf < 4; mf++)
            a_off[kk][mf] = (uint32_t)(((wm + mf * 16 + rr + (j & 1) * 8) * TROW
                                        + kk * 16 + (j >> 1) * 8) * 2);
    uint32_t b_off[2][2];
#pragma unroll
    for (int kk = 0; kk < 2; kk++)
#pragma unroll
        for (int p = 0; p < 2; p++)
            b_off[kk][p] = (uint32_t)(((wn + p * 16 + rr + (j >> 1) * 8) * TROW
                                       + kk * 16 + (j & 1) * 8) * 2);

#define ISSUE(stg, kt)                                                    \
    {   uint32_t base = sm_u + (stg) * STAGEB + sdst;                     \
        const __half* as = Ap + (kt);                                     \
        CP16(base, as, abytes); CP16(base + 16, as + 8, abytes);          \
        const __half* hs = Bhp + (kt);                                    \
        CP16(base + TILEB, hs, 16u); CP16(base + TILEB + 16, hs + 8, 16u);\
        CP_COMMIT(); }

    int NC = K / 32;
    ISSUE(0, 0);
    if (NC > 1) ISSUE(1, 32);

    for (int c = 0; c < NC; c++) {
        if (c + 1 < NC) { CP_WAIT(1); } else { CP_WAIT(0); }
        __syncthreads();
        if (c + 2 < NC) ISSUE((c + 2) % NSTAGE, (c + 2) * 32);

        uint32_t bb = sm_u + (c % NSTAGE) * STAGEB;
#pragma unroll
        for (int kk = 0; kk < 2; kk++) {
            uint32_t bhf[8];
            LDSM4(bhf[0], bhf[1], bhf[2], bhf[3], bb + TILEB + b_off[kk][0]);
            LDSM4(bhf[4], bhf[5], bhf[6], bhf[7], bb + TILEB + b_off[kk][1]);
#pragma unroll
            for (int mf = 0; mf < 4; mf++) {
                uint32_t ahf[4];
                LDSM4(ahf[0], ahf[1], ahf[2], ahf[3], bb + a_off[kk][mf]);
#pragma unroll
                for (int nf = 0; nf < 4; nf++)
                    MMA_F16(acc[mf][nf], ahf, bhf[nf * 2], bhf[nf * 2 + 1]);
            }
        }
        __syncthreads();
    }

    int er = lane >> 2, ec = (lane & 3) * 2;
#pragma unroll
    for (int nf = 0; nf < 4; nf++) {
        int col = n0 + wn + nf * 8 + ec;
        float bb0 = bias ? bias[col] : 0.0f;
        float bb1 = bias ? bias[col + 1] : 0.0f;
#pragma unroll
        for (int mf = 0; mf < 4; mf++) {
            int row = m0 + wm + mf * 16 + er;
            if (row < M) {
                float v0 = acc[mf][nf][0] + bb0, v1 = acc[mf][nf][1] + bb1;
                if (Ch)
                    *(__half2*)&Ch[(size_t)row * N + col]
                        = __halves2half2(__float2half(v0), __float2half(v1));
                else
                    *(float2*)&C[(size_t)row * N + col] = make_float2(v0, v1);
            }
            if (row + 8 < M) {
                float v0 = acc[mf][nf][2] + bb0, v1 = acc[mf][nf][3] + bb1;
                if (Ch)
                    *(__half2*)&Ch[(size_t)(row + 8) * N + col]
                        = __halves2half2(__float2half(v0), __float2half(v1));
                else
                    *(float2*)&C[(size_t)(row + 8) * N + col] = make_float2(v0, v1);
            }
        }
    }
}

// ---------------------------------------------------------------------------
// Implicit-GEMM conv (fused im2col): A streamed straight from poolT with
// zero-fill for out-of-bounds taps.  k' = k9*768 + ci ordering; weights cwh9
// are pre-reordered to match.  blockIdx.z = K split.
// ---------------------------------------------------------------------------
__global__ __launch_bounds__(256, 2) void gemm_conv(
    const __half* __restrict__ PT,      // [b][s*768+ci] fp16
    const __half* __restrict__ Bh,      // cwh9 [co][k'] (ldb=KCONV)
    float* __restrict__ C)              // convp partials
{
    extern __shared__ __half sm[];

    int kbase = blockIdx.z * KSLAB;
    C += (size_t)blockIdx.z * MCONV * IC;

    int t = threadIdx.x;
    int lane = t & 31, wid = t >> 5;
    int wm = (wid & 1) * 64, wn = (wid >> 1) * 32;
    int rr = lane & 7, j = lane >> 3;
    int m0 = blockIdx.y * 128, n0 = blockIdx.x * 128;

    float acc[4][4][4];
#pragma unroll
    for (int i = 0; i < 4; i++)
#pragma unroll
        for (int jj = 0; jj < 4; jj++)
#pragma unroll
            for (int k = 0; k < 4; k++) acc[i][jj][k] = 0.0f;

    int srow = t >> 1, shalf = t & 1;
    int gr = m0 + srow;
    bool aok = gr < MCONV;
    int bb_ = aok ? gr / AG : 0, pp = aok ? gr % AG : 0;
    int py = pp / 7, px = pp % 7;
    const __half* Pb = PT + (size_t)bb_ * PFLAT;
    const __half* Bhp = Bh + (size_t)(n0 + srow) * KCONV + kbase + shalf * 16;
    uint32_t sm_u = smem_u32(sm);
    uint32_t sdst = (uint32_t)(srow * 80 + shalf * 32);

    uint32_t a_off[2][4];
#pragma unroll
    for (int kk = 0; kk < 2; kk++)
#pragma unroll
        for (int mf = 0; mf < 4; mf++)
            a_off[kk][mf] = (uint32_t)(((wm + mf * 16 + rr + (j & 1) * 8) * TROW
                                        + kk * 16 + (j >> 1) * 8) * 2);
    uint32_t b_off[2][2];
#pragma unroll
    for (int kk = 0; kk < 2; kk++)
#pragma unroll
        for (int p = 0; p < 2; p++)
            b_off[kk][p] = (uint32_t)(((wn + p * 16 + rr + (j >> 1) * 8) * TROW
                                       + kk * 16 + (j & 1) * 8) * 2);

#define ISSUEC(stg, kt)                                                   \
    {   uint32_t base = sm_u + (stg) * STAGEB + sdst;                     \
        int kabs = kbase + (kt) + shalf * 16;                             \
        int k9 = kabs / 768, kof = kabs - k9 * 768;                       \
        int sy = py + k9 / 3 - 1, sx = px + (k9 - (k9 / 3) * 3) - 1;      \
        bool v = aok && sy >= 0 && sy < 7 && sx >= 0 && sx < 7;           \
        int sp = v ? (sy * 7 + sx) : 0;                                   \
        const __half* as = Pb + (size_t)sp * CIN + kof;                   \
        uint32_t ab = v ? 16u : 0u;                                       \
        CP16(base, as, ab); CP16(base + 16, as + 8, ab);                  \
        const __half* hs = Bhp + (kt);                                    \
        CP16(base + TILEB, hs, 16u); CP16(base + TILEB + 16, hs + 8, 16u);\
        CP_COMMIT(); }

    int NC = KSLAB / 32;
    ISSUEC(0, 0);
    ISSUEC(1, 32);

    for (int c = 0; c < NC; c++) {
        if (c + 1 < NC) { CP_WAIT(1); } else { CP_WAIT(0); }
        __syncthreads();
        if (c + 2 < NC) ISSUEC((c + 2) % NSTAGE, (c + 2) * 32);

        uint32_t bb = sm_u + (c % NSTAGE) * STAGEB;
#pragma unroll
        for (int kk = 0; kk < 2; kk++) {
            uint32_t bhf[8];
            LDSM4(bhf[0], bhf[1], bhf[2], bhf[3], bb + TILEB + b_off[kk][0]);
            LDSM4(bhf[4], bhf[5], bhf[6], bhf[7], bb + TILEB + b_off[kk][1]);
#pragma unroll
            for (int mf = 0; mf < 4; mf++) {
                uint32_t ahf[4];
                LDSM4(ahf[0], ahf[1], ahf[2], ahf[3], bb + a_off[kk][mf]);
#pragma unroll
                for (int nf = 0; nf < 4; nf++)
                    MMA_F16(acc[mf][nf], ahf, bhf[nf * 2], bhf[nf * 2 + 1]);
            }
        }
        __syncthreads();
    }

    int er = lane >> 2, ec = (lane & 3) * 2;
#pragma unroll
    for (int nf = 0; nf < 4; nf++) {
        int col = n0 + wn + nf * 8 + ec;
#pragma unroll
        for (int mf = 0; mf < 4; mf++) {
            int row = m0 + wm + mf * 16 + er;
            if (row < MCONV)
                *(float2*)&C[(size_t)row * IC + col]
                    = make_float2(acc[mf][nf][0], acc[mf][nf][1]);
            if (row + 8 < MCONV)
                *(float2*)&C[(size_t)(row + 8) * IC + col]
                    = make_float2(acc[mf][nf][2], acc[mf][nf][3]);
        }
    }
}

// ---------------------------------------------------------------------------
// Merged pre-convert kernels
// ---------------------------------------------------------------------------
// z=0: Wq->whT; z=1: Wkv->whT+IC*DIM; z=2: proj->pwhT
__global__ __launch_bounds__(256) void transpose3_h(
    const float* __restrict__ Wq, const float* __restrict__ Wkv,
    const float* __restrict__ proj_w,
    __half* __restrict__ whT, __half* __restrict__ pwhT)
{
    __shared__ float tile[32][33];
    int z = blockIdx.z;
    const float* src; __half* dst; int C;
    if (z == 0)      { src = Wq;     dst = whT;                       C = IC; }
    else if (z == 1) { src = Wkv;    dst = whT + (size_t)IC * DIM;    C = 2 * IC; }
    else             { src = proj_w; dst = pwhT;                      C = IC; }
    int cb = blockIdx.x * 32, rb = blockIdx.y * 32;
    if (cb >= C) return;
    int tx = threadIdx.x & 31, ty = threadIdx.x >> 5;
    for (int i = ty; i < 32; i += 8) {
        int r = rb + i, c = cb + tx;
        if (c < C) tile[i][tx] = src[(size_t)r * C + c];
    }
    __syncthreads();
    for (int i = ty; i < 32; i += 8) {
        int c = cb + i, r = rb + tx;
        if (c < C) dst[(size_t)c * DIM + r] = __float2half(tile[tx][i]);
    }
}

// flat cvt: x -> xh; conv_w -> cwh9 (k9-major reorder)
__global__ void cvt2_kernel(const float* __restrict__ x,
                            const float* __restrict__ conv_w,
                            __half* __restrict__ xh, __half* __restrict__ cwh9,
                            size_t nx, size_t nc)
{
    size_t i = (size_t)blockIdx.x * blockDim.x + threadIdx.x;
    if (i < nx) xh[i] = __float2half(x[i]);
    else if (i < nx + nc) {
        size_t w = i - nx;
        int co = (int)(w / KCONV), r = (int)(w % KCONV);
        int k9 = r / CIN, ci = r % CIN;
        cwh9[w] = __float2half(conv_w[(size_t)co * KCONV + ci * 9 + k9]);
    }
}

// ---------------------------------------------------------------------------
// Adaptive pooling -> pooled[b][a*768 + c].  One block per (a, b).
// ---------------------------------------------------------------------------
__global__ __launch_bounds__(256) void pool_kernel(
    const __half* __restrict__ qkvh, const float* __restrict__ context,
    float* __restrict__ pooled)
{
    int a = blockIdx.x, b = blockIdx.y;
    int p = a / 7, q = a % 7;
    int sh = p * 32 / 7, eh = ((p + 1) * 32 + 6) / 7;
    int sw = q * 32 / 7, ew = ((q + 1) * 32 + 6) / 7;
    float inv = 1.0f / (float)((eh - sh) * (ew - sw));
    for (int c = threadIdx.x; c < CIN; c += 256) {
        float s = 0.0f;
        if (c < IC) {
            for (int hh = sh; hh < eh; hh++) {
                const __half* row = qkvh + ((size_t)(b * N_TOK) + hh * WW) * NQKV + c;
                for (int ww = sw; ww < ew; ww++)
                    s += __half2float(row[(size_t)ww * NQKV]);
            }
        } else {
            for (int hh = sh; hh < eh; hh++) {
                const float* row = context + ((size_t)(b * N_TOK) + hh * WW) * CC + (c - IC);
                for (int ww = sw; ww < ew; ww++) s += row[(size_t)ww * CC];
            }
        }
        pooled[((size_t)b * AG + a) * CIN + c] = s * inv;
    }
}

// Transpose the raw-reshaped (768,49) view -> poolT[b][s*768+ci] (fp16).
// IN (per b, flat 37632) viewed as IN2[ci][s] row-major (49 wide).
__global__ __launch_bounds__(256) void poolT_kernel(
    const float* __restrict__ pooled, __half* __restrict__ PT)
{
    __shared__ float tile[64][52];
    int b = blockIdx.y, cr0 = blockIdx.x * 64;
    const float* IN = pooled + (size_t)b * PFLAT;
    __half* OUT = PT + (size_t)b * PFLAT;
    for (int e = threadIdx.x; e < 64 * AG; e += 256) {
        int i = e / AG, s = e % AG;
        tile[i][s] = IN[(size_t)(cr0 + i) * AG + s];
    }
    __syncthreads();
    for (int e = threadIdx.x; e < 64 * AG; e += 256) {
        int s = e >> 6, i = e & 63;
        OUT[(size_t)s * CIN + cr0 + i] = __float2half(tile[i][s]);
    }
}

// Reduce split-K partials + conv bias, transpose to agent_cs[b][c*49+s]
__global__ __launch_bounds__(256) void conv_reduce_tr(
    const float* __restrict__ parts, const float* __restrict__ conv_b,
    float* __restrict__ out)
{
    int b = blockIdx.x, cb = blockIdx.y * 64;
    __shared__ float tile[64][50];
    int t = threadIdx.x;
    for (int e = t; e < 64 * AG; e += 256) {
        int c = e & 63, s = e >> 6;
        float v = conv_b[cb + c];
#pragma unroll
        for (int p = 0; p < KSPLIT; p++)
            v += parts[(size_t)p * MCONV * IC + ((size_t)b * AG + s) * IC + cb + c];
        tile[c][s] = v;
    }
    __syncthreads();
    for (int e = t; e < 64 * AG; e += 256) {
        int s = e % AG, c = e / AG;
        out[(size_t)b * AGFLAT + (cb + c) * AG + s] = tile[c][s];
    }
}

// ---------------------------------------------------------------------------
// Bias tables (merged)
// ---------------------------------------------------------------------------
__device__ __forceinline__ float bilin7(const float* __restrict__ src, int yi, int xi)
{
    float fy = (yi + 0.5f) * (7.0f / 32.0f) - 0.5f;
    float fx = (xi + 0.5f) * (7.0f / 32.0f) - 0.5f;
    int y0 = (int)floorf(fy); float wy = fy - (float)y0;
    int x0 = (int)floorf(fx); float wx = fx - (float)x0;
    int y0c = max(y0, 0), y1c = min(y0 + 1, 6);
    int x0c = max(x0, 0), x1c = min(x0 + 1, 6);
    float v00 = src[y0c * 7 + x0c], v01 = src[y0c * 7 + x1c];
    float v10 = src[y1c * 7 + x0c], v11 = src[y1c * 7 + x1c];
    return (1.f - wy) * ((1.f - wx) * v00 + wx * v01)
         + wy * ((1.f - wx) * v10 + wx * v11);
}

__global__ void bias_both_kernel(
    const float* __restrict__ an_bias, const float* __restrict__ ah_bias,
    const float* __restrict__ aw_bias,
    const float* __restrict__ na_bias, const float* __restrict__ ha_bias,
    const float* __restrict__ wa_bias,
    float* __restrict__ out_an, float* __restrict__ out_na)
{
    int idx = blockIdx.x * blockDim.x + threadIdx.x;
    if (blockIdx.y == 0) {
        if (idx >= NH * AG * N_TOK) return;
        int n = idx % N_TOK;
        int r = idx / N_TOK;
        int a = r % AG, h = r / AG;
        int hi = n >> 5, wi = n & 31;
        const float* src = an_bias + (size_t)(h * AG + a) * 49;
        out_an[idx] = bilin7(src, hi, wi)
                    + ah_bias[(h * AG + a) * 32 + hi]
                    + aw_bias[(h * AG + a) * 32 + wi];
    } else {
        if (idx >= NH * N_TOK * AG) return;
        int a = idx % AG;
        int r = idx / AG;
        int n = r % N_TOK, h = r / N_TOK;
        int hi = n >> 5, wi = n & 31;
        const float* src = na_bias + (size_t)(h * AG + a) * 49;
        out_na[idx] = bilin7(src, hi, wi)
                    + ha_bias[(h * 32 + hi) * AG + a]
                    + wa_bias[(h * 32 + wi) * AG + a];
    }
}

// ---------------------------------------------------------------------------
// Agent attention (flash, tensor-core).  One block per (b,h), 256 threads.
// ---------------------------------------------------------------------------
#define FL_SS 0
#define FL_AT 34048
#define FL_KS 43264
#define FL_VT 61696
#define FL_PS 79104
#define FL_MR 96512
#define FL_LR 96768
#define FL_FR 97024
#define FL_PM 97280
#define FL_PX 98304
#define FL_SMEM 99328

__global__ __launch_bounds__(256) void agent_flash_mma(
    const __half* __restrict__ qkvh, const float* __restrict__ agent_cs,
    const float* __restrict__ bias_an, float* __restrict__ agv)
{
    extern __shared__ char fsm[];
    float*  SS = (float*)(fsm + FL_SS);
    __half* AT = (__half*)(fsm + FL_AT);
    __half* KS = (__half*)(fsm + FL_KS);
    __half* VT = (__half*)(fsm + FL_VT);
    __half* PS = (__half*)(fsm + FL_PS);
    float*  MR = (float*)(fsm + FL_MR);
    float*  LR = (float*)(fsm + FL_LR);
    float*  FR = (float*)(fsm + FL_FR);
    float*  PM = (float*)(fsm + FL_PM);
    float*  PX = (float*)(fsm + FL_PX);

    int b = blockIdx.x, h = blockIdx.y, t = threadIdx.x;
    int lane = t & 31, wid = t >> 5;
    int rr = lane & 7, j = lane >> 3;
    int er = lane >> 2, ec = (lane & 3) * 2;
    int rid = t >> 2, seg = t & 3;

    uint32_t at_u = smem_u32(AT), ks_u = smem_u32(KS);
    uint32_t vt_u = smem_u32(VT), ps_u = smem_u32(PS);

    int wm1 = (wid & 1) * 32, wn1 = (wid >> 1) * 32;
    int wm2 = (wid & 3) * 16, wn2 = (wid >> 2) * 32;

    for (int e = t; e < 64 * 64; e += 256) {
        int a = e >> 6, d = e & 63;
        AT[a * 72 + d] = (a < AG)
            ? __float2half(agent_cs[(size_t)b * AGFLAT + a * IC + h * HD + d])
            : __half(0.0f);
    }
    if (t < 64) { MR[t] = -1e30f; LR[t] = 0.0f; }

    float acc2[4][4];
#pragma unroll
    for (int nf = 0; nf < 4; nf++)
#pragma unroll
        for (int k = 0; k < 4; k++) acc2[nf][k] = 0.0f;

    uint32_t a1_off[4][2], b1_off[4][2];
#pragma unroll
    for (int kk = 0; kk < 4; kk++) {
#pragma unroll
        for (int mf = 0; mf < 2; mf++)
            a1_off[kk][mf] = (uint32_t)(((wm1 + mf * 16 + rr + (j & 1) * 8) * 72
                                         + kk * 16 + (j >> 1) * 8) * 2);
#pragma unroll
        for (int p = 0; p < 2; p++)
            b1_off[kk][p] = (uint32_t)(((wn1 + p * 16 + rr + (j >> 1) * 8) * 72
                                        + kk * 16 + (j & 1) * 8) * 2);
    }
    uint32_t a2_off[8], b2_off[8][2];
#pragma unroll
    for (int kk = 0; kk < 8; kk++) {
        a2_off[kk] = (uint32_t)(((wm2 + rr + (j & 1) * 8) * 136
                                 + kk * 16 + (j >> 1) * 8) * 2);
#pragma unroll
        for (int p = 0; p < 2; p++)
            b2_off[kk][p] = (uint32_t)(((wn2 + p * 16 + rr + (j >> 1) * 8) * 136
                                        + kk * 16 + (j & 1) * 8) * 2);
    }

    for (int jt = 0; jt < N_TOK; jt += 128) {
        __syncthreads();
        for (int e = t; e < 1024; e += 256) {
            int jj = e >> 3, ch = e & 7;
            *(float4*)(KS + jj * 72 + ch * 8) = *(const float4*)(
                qkvh + ((size_t)(b * N_TOK + jt + jj)) * NQKV + IC + h * HD + ch * 8);
        }
        for (int e = t; e < 8192; e += 256) {
            int d = e & 63, jj = e >> 6;
            VT[d * 136 + jj] =
                qkvh[((size_t)(b * N_TOK + jt + jj)) * NQKV + 2 * IC + h * HD + d];
        }
        __syncthreads();

        float acc1[2][4][4];
#pragma unroll
        for (int mf = 0; mf < 2; mf++)
#pragma unroll
            for (int nf = 0; nf < 4; nf++)
#pragma unroll
                for (int k = 0; k < 4; k++) acc1[mf][nf][k] = 0.0f;
#pragma unroll
        for (int kk = 0; kk < 4; kk++) {
            uint32_t bf[8];
            LDSM4(bf[0], bf[1], bf[2], bf[3], ks_u + b1_off[kk][0]);
            LDSM4(bf[4], bf[5], bf[6], bf[7], ks_u + b1_off[kk][1]);
#pragma unroll
            for (int mf = 0; mf < 2; mf++) {
                uint32_t af[4];
                LDSM4(af[0], af[1], af[2], af[3], at_u + a1_off[kk][mf]);
#pragma unroll
                for (int nf = 0; nf < 4; nf++)
                    MMA_F16(acc1[mf][nf], af, bf[nf * 2], bf[nf * 2 + 1]);
            }
        }
#pragma unroll
        for (int mf = 0; mf < 2; mf++) {
            int a0 = wm1 + mf * 16 + er, a1 = a0 + 8;
            const float* bb0 = (a0 < AG) ? bias_an + (size_t)(h * AG + a0) * N_TOK + jt : nullptr;
            const float* bb1 = (a1 < AG) ? bias_an + (size_t)(h * AG + a1) * N_TOK + jt : nullptr;
#pragma unroll
            for (int nf = 0; nf < 4; nf++) {
                int jc = wn1 + nf * 8 + ec;
                if (bb0) {
                    SS[a0 * 133 + jc]     = acc1[mf][nf][0] * 0.125f + bb0[jc];
                    SS[a0 * 133 + jc + 1] = acc1[mf][nf][1] * 0.125f + bb0[jc + 1];
                } else {
                    SS[a0 * 133 + jc] = -1e30f; SS[a0 * 133 + jc + 1] = -1e30f;
                }
                if (bb1) {
                    SS[a1 * 133 + jc]     = acc1[mf][nf][2] * 0.125f + bb1[jc];
                    SS[a1 * 133 + jc + 1] = acc1[mf][nf][3] * 0.125f + bb1[jc + 1];
                } else {
                    SS[a1 * 133 + jc] = -1e30f; SS[a1 * 133 + jc + 1] = -1e30f;
                }
            }
        }
        __syncthreads();

        {
            float pm = -1e30f;
            const float* row = SS + rid * 133 + seg * 32;
            for (int i = 0; i < 32; i++) pm = fmaxf(pm, row[i]);
            PM[rid * 4 + seg] = pm;
        }
        __syncthreads();
        if (t < 64) {
            float mnew = fmaxf(fmaxf(PM[t * 4], PM[t * 4 + 1]),
                               fmaxf(PM[t * 4 + 2], PM[t * 4 + 3]));
            mnew = fmaxf(MR[t], mnew);
            FR[t] = __expf(MR[t] - mnew);
            MR[t] = mnew;
        }
        __syncthreads();
        {
            float m = MR[rid], ps = 0.0f;
            const float* row = SS + rid * 133 + seg * 32;
            __half* prow = PS + rid * 136 + seg * 32;
            for (int i = 0; i < 32; i++) {
                float e = __expf(row[i] - m);
                prow[i] = __float2half(e);
                ps += e;
            }
            PX[rid * 4 + seg] = ps;
        }
        __syncthreads();
        if (t < 64)
            LR[t] = LR[t] * FR[t]
                  + PX[t * 4] + PX[t * 4 + 1] + PX[t * 4 + 2] + PX[t * 4 + 3];

        {
            float f0 = FR[wm2 + er], f1 = FR[wm2 + er + 8];
#pragma unroll
            for (int nf = 0; nf < 4; nf++) {
                acc2[nf][0] *= f0; acc2[nf][1] *= f0;
                acc2[nf][2] *= f1; acc2[nf][3] *= f1;
            }
        }
#pragma unroll
        for (int kk = 0; kk < 8; kk++) {
            uint32_t bf[8];
            LDSM4(bf[0], bf[1], bf[2], bf[3], vt_u + b2_off[kk][0]);
            LDSM4(bf[4], bf[5], bf[6], bf[7], vt_u + b2_off[kk][1]);
            uint32_t af[4];
            LDSM4(af[0], af[1], af[2], af[3], ps_u + a2_off[kk]);
#pragma unroll
            for (int nf = 0; nf < 4; nf++)
                MMA_F16(acc2[nf], af, bf[nf * 2], bf[nf * 2 + 1]);
        }
    }

    __syncthreads();
    {
        int a0 = wm2 + er, a1 = a0 + 8;
        float i0 = (a0 < AG) ? 1.0f / LR[a0] : 0.0f;
        float i1 = (a1 < AG) ? 1.0f / LR[a1] : 0.0f;
#pragma unroll
        for (int nf = 0; nf < 4; nf++) {
            int d = wn2 + nf * 8 + ec;
            if (a0 < AG)
                *(float2*)&agv[(((size_t)(b * NH + h) * AG) + a0) * HD + d]
                    = make_float2(acc2[nf][0] * i0, acc2[nf][1] * i0);
            if (a1 < AG)
                *(float2*)&agv[(((size_t)(b * NH + h) * AG) + a1) * HD + d]
                    = make_float2(acc2[nf][2] * i1, acc2[nf][3] * i1);
        }
    }
}

// ---------------------------------------------------------------------------
// Query attention (tensor-core) -> outh (fp16).  Block (b,h,nt), 128 threads.
// ---------------------------------------------------------------------------
#define QA_SS 0
#define QA_QS 16640
#define QA_AT 25856
#define QA_PS 35072
#define QA_SMEM 44288

__global__ __launch_bounds__(128) void qattn_mma(
    const __half* __restrict__ qkvh, const float* __restrict__ agent_cs,
    const float* __restrict__ agv, const float* __restrict__ bias_na,
    __half* __restrict__ outh)
{
    extern __shared__ char qsm[];
    float*  SS  = (float*)(qsm + QA_SS);
    __half* QS  = (__half*)(qsm + QA_QS);
    __half* ATS = (__half*)(qsm + QA_AT);
    __half* PS  = (__half*)(qsm + QA_PS);

    int b = blockIdx.x, h = blockIdx.y, nt = blockIdx.z;
    int t = threadIdx.x;
    int lane = t & 31, wid = t >> 5;
    int rr = lane & 7, j = lane >> 3;
    int er = lane >> 2, ec = (lane & 3) * 2;
    int wm = (wid & 1) * 32, wn = (wid >> 1) * 32;

    uint32_t qs_u = smem_u32(QS), at_u = smem_u32(ATS), ps_u = smem_u32(PS);

    for (int e = t; e < 512; e += 128) {
        int nn = e >> 3, ch = e & 7;
        *(float4*)(QS + nn * 72 + ch * 8) = *(const float4*)(
            qkvh + ((size_t)(b * N_TOK) + nt * 64 + nn) * NQKV + h * HD + ch * 8);
    }
    for (int e = t; e < 64 * 64; e += 128) {
        int a = e >> 6, d = e & 63;
        ATS[a * 72 + d] = (a < AG)
            ? __float2half(agent_cs[(size_t)b * AGFLAT + a * IC + h * HD + d])
            : __half(0.0f);
    }
    __syncthreads();

    uint32_t a_off[4][2], b_off[4][2];
#pragma unroll
    for (int kk = 0; kk < 4; kk++) {
#pragma unroll
        for (int mf = 0; mf < 2; mf++)
            a_off[kk][mf] = (uint32_t)(((wm + mf * 16 + rr + (j & 1) * 8) * 72
                                        + kk * 16 + (j >> 1) * 8) * 2);
#pragma unroll
        for (int p = 0; p < 2; p++)
            b_off[kk][p] = (uint32_t)(((wn + p * 16 + rr + (j >> 1) * 8) * 72
                                       + kk * 16 + (j & 1) * 8) * 2);
    }

    float acc[2][4][4];
#pragma unroll
    for (int mf = 0; mf < 2; mf++)
#pragma unroll
        for (int nf = 0; nf < 4; nf++)
#pragma unroll
            for (int k = 0; k < 4; k++) acc[mf][nf][k] = 0.0f;

#pragma unroll
    for (int kk = 0; kk < 4; kk++) {
        uint32_t bf[8];
        LDSM4(bf[0], bf[1], bf[2], bf[3], at_u + b_off[kk][0]);
        LDSM4(bf[4], bf[5], bf[6], bf[7], at_u + b_off[kk][1]);
#pragma unroll
        for (int mf = 0; mf < 2; mf++) {
            uint32_t af[4];
            LDSM4(af[0], af[1], af[2], af[3], qs_u + a_off[kk][mf]);
#pragma unroll
            for (int nf = 0; nf < 4; nf++)
                MMA_F16(acc[mf][nf], af, bf[nf * 2], bf[nf * 2 + 1]);
        }
    }
#pragma unroll
    for (int mf = 0; mf < 2; mf++) {
        int tok0 = wm + mf * 16 + er, tok1 = tok0 + 8;
        const float* bn0 = bias_na + ((size_t)(h * N_TOK) + nt * 64 + tok0) * AG;
        const float* bn1 = bias_na + ((size_t)(h * N_TOK) + nt * 64 + tok1) * AG;
#pragma unroll
        for (int nf = 0; nf < 4; nf++) {
            int a = wn + nf * 8 + ec;
            SS[tok0 * 65 + a]     = (a < AG)     ? acc[mf][nf][0] * 0.125f + bn0[a]     : -1e30f;
            SS[tok0 * 65 + a + 1] = (a + 1 < AG) ? acc[mf][nf][1] * 0.125f + bn0[a + 1] : -1e30f;
            SS[tok1 * 65 + a]     = (a < AG)     ? acc[mf][nf][2] * 0.125f + bn1[a]     : -1e30f;
            SS[tok1 * 65 + a + 1] = (a + 1 < AG) ? acc[mf][nf][3] * 0.125f + bn1[a + 1] : -1e30f;
        }
    }
    __syncthreads();

    if (t < 64) {
        const float* row = SS + t * 65;
        float m = -1e30f;
        for (int a = 0; a < 64; a++) m = fmaxf(m, row[a]);
        float s = 0.0f;
        float e[64];
        for (int a = 0; a < 64; a++) { e[a] = __expf(row[a] - m); s += e[a]; }
        float inv = 1.0f / s;
        __half* prow = PS + t * 72;
        for (int a = 0; a < 64; a++) prow[a] = __float2half(e[a] * inv);
    } else {
        int d = t - 64;
        __half* vrow = ATS + d * 72;
        const float* ga = agv + ((size_t)(b * NH + h) * AG) * HD + d;
        for (int a = 0; a < AG; a++) vrow[a] = __float2half(ga[(size_t)a * HD]);
        for (int a = AG; a < 64; a++) vrow[a] = __half(0.0f);
    }
    __syncthreads();

#pragma unroll
    for (int mf = 0; mf < 2; mf++)
#pragma unroll
        for (int nf = 0; nf < 4; nf++)
#pragma unroll
            for (int k = 0; k < 4; k++) acc[mf][nf][k] = 0.0f;
#pragma unroll
    for (int kk = 0; kk < 4; kk++) {
        uint32_t bf[8];
        LDSM4(bf[0], bf[1], bf[2], bf[3], at_u + b_off[kk][0]);
        LDSM4(bf[4], bf[5], bf[6], bf[7], at_u + b_off[kk][1]);
#pragma unroll
        for (int mf = 0; mf < 2; mf++) {
            uint32_t af[4];
            LDSM4(af[0], af[1], af[2], af[3], ps_u + a_off[kk][mf]);
#pragma unroll
            for (int nf = 0; nf < 4; nf++)
                MMA_F16(acc[mf][nf], af, bf[nf * 2], bf[nf * 2 + 1]);
        }
    }
#pragma unroll
    for (int mf = 0; mf < 2; mf++) {
        int tok0 = nt * 64 + wm + mf * 16 + er;
#pragma unroll
        for (int nf = 0; nf < 4; nf++) {
            int d = wn + nf * 8 + ec;
            *(__half2*)&outh[((size_t)(b * N_TOK) + tok0) * IC + h * HD + d]
                = __halves2half2(__float2half(acc[mf][nf][0]),
                                 __float2half(acc[mf][nf][1]));
            *(__half2*)&outh[((size_t)(b * N_TOK) + tok0 + 8) * IC + h * HD + d]
                = __halves2half2(__float2half(acc[mf][nf][2]),
                                 __float2half(acc[mf][nf][3]));
        }
    }
}

// ---------------------------------------------------------------------------
// Depthwise 3x3 conv, sliding-window; fused in-place add into outh.
// ---------------------------------------------------------------------------
__global__ __launch_bounds__(512) void dwc_kernel(
    const __half* __restrict__ qkvh,
    const float* __restrict__ dwc_w, const float* __restrict__ dwc_b,
    __half* __restrict__ outh)
{
    int hh = blockIdx.x, b = blockIdx.y;
    int c = threadIdx.x;
    float w9[9];
#pragma unroll
    for (int i = 0; i < 9; i++) w9[i] = dwc_w[c * 9 + i];
    float wb = dwc_b[c];
    const __half* vb = qkvh + (size_t)(b * N_TOK) * NQKV + 2 * IC + c;

    float c0[3], c1[3], c2[3];
#define LOADCOL(x, dst)                                                   \
    {   if ((x) < 0 || (x) >= WW) { dst[0] = dst[1] = dst[2] = 0.0f; }    \
        else {                                                            \
            _Pragma("unroll")                                             \
            for (int r = 0; r < 3; r++) {                                 \
                int y = hh - 1 + r;                                       \
                dst[r] = (y >= 0 && y < HH)                               \
                    ? __half2float(vb[(size_t)(y * WW + (x)) * NQKV])     \
                    : 0.0f;                                               \
            } } }

    LOADCOL(-1, c0);
    LOADCOL(0, c1);
    for (int x = 0; x < WW; x++) {
        LOADCOL(x + 1, c2);
        float s = wb;
#pragma unroll
        for (int r = 0; r < 3; r++) {
            s += w9[r * 3 + 0] * c0[r];
            s += w9[r * 3 + 1] * c1[r];
            s += w9[r * 3 + 2] * c2[r];
        }
        size_t i = ((size_t)(b * N_TOK) + hh * WW + x) * IC + c;
        outh[i] = __float2half(__half2float(outh[i]) + s);
#pragma unroll
        for (int r = 0; r < 3; r++) { c0[r] = c1[r]; c1[r] = c2[r]; }
    }
}

// ---------------------------------------------------------------------------
// Host launcher
// ---------------------------------------------------------------------------
extern "C" void kernel_launch(void* const* d_in, const int* in_sizes, int n_in,
                              void* d_out, int out_size)
{
    const float* x       = (const float*)d_in[0];
    const float* context = (const float*)d_in[1];
    const float* Wq      = (const float*)d_in[2];
    const float* Wkv     = (const float*)d_in[3];
    const float* conv_w  = (const float*)d_in[4];
    const float* conv_b  = (const float*)d_in[5];
    const float* dwc_w   = (const float*)d_in[6];
    const float* dwc_b   = (const float*)d_in[7];
    const float* proj_w  = (const float*)d_in[8];
    const float* proj_b  = (const float*)d_in[9];
    const float* an_bias = (const float*)d_in[10];
    const float* na_bias = (const float*)d_in[11];
    const float* ah_bias = (const float*)d_in[12];
    const float* aw_bias = (const float*)d_in[13];
    const float* ha_bias = (const float*)d_in[14];
    const float* wa_bias = (const float*)d_in[15];
    float* out = (float*)d_out;

    float  *pooled, *convp, *agent_cs, *ban, *bna, *agv;
    __half *qkvh, *xh, *whT, *pwhT, *cwh9, *poolT, *outh;
    cudaGetSymbolAddress((void**)&qkvh,     g_qkvh);
    cudaGetSymbolAddress((void**)&xh,       g_xh);
    cudaGetSymbolAddress((void**)&whT,      g_whT);
    cudaGetSymbolAddress((void**)&pwhT,     g_pwhT);
    cudaGetSymbolAddress((void**)&cwh9,     g_cwh9);
    cudaGetSymbolAddress((void**)&pooled,   g_pooled);
    cudaGetSymbolAddress((void**)&poolT,    g_poolT);
    cudaGetSymbolAddress((void**)&convp,    g_convp);
    cudaGetSymbolAddress((void**)&agent_cs, g_agent_cs);
    cudaGetSymbolAddress((void**)&ban,      g_bias_an);
    cudaGetSymbolAddress((void**)&bna,      g_bias_na);
    cudaGetSymbolAddress((void**)&agv,      g_agv);
    cudaGetSymbolAddress((void**)&outh,     g_outh);

    cudaFuncSetAttribute(gemm_f16a,
                         cudaFuncAttributeMaxDynamicSharedMemorySize, GSMEM);
    cudaFuncSetAttribute(gemm_conv,
                         cudaFuncAttributeMaxDynamicSharedMemorySize, GSMEM);
    cudaFuncSetAttribute(agent_flash_mma,
                         cudaFuncAttributeMaxDynamicSharedMemorySize, FL_SMEM);
    cudaFuncSetAttribute(qattn_mma,
                         cudaFuncAttributeMaxDynamicSharedMemorySize, QA_SMEM);

    // 1. operand prep (merged; conv weights reordered k9-major)
    {
        size_t nx = (size_t)B * N_TOK * DIM;
        size_t nc = (size_t)IC * KCONV;
        cvt2_kernel<<<(int)((nx + nc + 255) / 256), 256>>>(
            x, conv_w, xh, cwh9, nx, nc);
    }
    transpose3_h<<<dim3(32, DIM / 32, 3), 256>>>(Wq, Wkv, proj_w, whT, pwhT);

    // 2. fused QKV GEMM -> fp16
    gemm_f16a<<<dim3(NQKV / 128, (B * N_TOK) / 128), 256, GSMEM>>>(
        xh, DIM, whT, DIM, nullptr, nullptr, qkvh, B * N_TOK, NQKV, DIM);

    // 3. adaptive pool + transpose to implicit-GEMM layout
    pool_kernel<<<dim3(AG, B), 256>>>(qkvh, context, pooled);
    poolT_kernel<<<dim3(CIN / 64, B), 256>>>(pooled, poolT);

    // 4. implicit-GEMM conv (fused im2col) + reduce
    gemm_conv<<<dim3(IC / 128, (MCONV + 127) / 128, KSPLIT), 256, GSMEM>>>(
        poolT, cwh9, convp);
    conv_reduce_tr<<<dim3(B, IC / 64), 256>>>(convp, conv_b, agent_cs);

    // 5. bias tables (merged)
    bias_both_kernel<<<dim3((NH * AG * N_TOK + 255) / 256, 2), 256>>>(
        an_bias, ah_bias, aw_bias, na_bias, ha_bias, wa_bias, ban, bna);

    // 6. agent attention (tensor-core flash)
    agent_flash_mma<<<dim3(B, NH), 256, FL_SMEM>>>(qkvh, agent_cs, ban, agv);

    // 7. query attention (tensor-core) -> outh (fp16)
    qattn_mma<<<dim3(B, NH, N_TOK / 64), 128, QA_SMEM>>>(
        qkvh, agent_cs, agv, bna, outh);

    // 8. depthwise conv residual, sliding-window, in-place into outh
    dwc_kernel<<<dim3(HH, B), 512>>>(qkvh, dwc_w, dwc_b, outh);

    // 9. output projection
    gemm_f16a<<<dim3(IC / 128, (B * N_TOK) / 128), 256, GSMEM>>>(
        outh, IC, pwhT, DIM, proj_b, out, nullptr, B * N_TOK, IC, DIM);

    (void)in_sizes; (void)n_in; (void)out_size;
}

// round 16
// speedup vs baseline: 2.0965x; 1.0326x over previous
#include <cuda_runtime.h>
#include <cuda_fp16.h>
#include <cstdint>

// ---------------------------------------------------------------------------
// Problem constants
// ---------------------------------------------------------------------------
#define B 32
#define N_TOK 1024
#define DIM 512
#define IC 512
#define CC 256
#define NH 8
#define AG 49
#define HD 64
#define HH 32
#define WW 32
#define CIN 768            // IC + CC
#define KCONV 6912         // 768*9
#define MCONV 1568         // B*49
#define NQKV 1536          // IC + 2*IC
#define AGFLAT 25088       // IC*AG
#define KSPLIT 8
#define KSLAB 864          // KCONV / KSPLIT
#define PFLAT 37632        // AG*CIN per batch

// ---------------------------------------------------------------------------
// Scratch (static device globals; no allocation allowed)
// ---------------------------------------------------------------------------
__device__ __half g_qkvh[(size_t)B * N_TOK * NQKV];          // [q|k|v] fp16
__device__ __half g_xh[(size_t)B * N_TOK * DIM];             // x in fp16
__device__ __half g_whT[(size_t)NQKV * DIM];                 // [j][k]
__device__ __half g_pwhT[(size_t)IC * DIM];
__device__ __half g_cwh9[(size_t)IC * KCONV];                // [co][k9*768+ci]
__device__ float  g_pooled[(size_t)B * AG * CIN];            // natural [b][a*768+c]
__device__ __half g_poolT[(size_t)B * PFLAT];                // [b][s*768+ci]
__device__ float  g_convp[(size_t)KSPLIT * MCONV * IC];
__device__ float  g_agent_cs[(size_t)B * AGFLAT];
__device__ float  g_bias_an[NH * AG * N_TOK];
__device__ float  g_bias_na[NH * N_TOK * AG];
__device__ float  g_agv[(size_t)B * NH * AG * HD];
__device__ __half g_outh[(size_t)B * N_TOK * IC];

// ---------------------------------------------------------------------------
// PTX helpers
// ---------------------------------------------------------------------------
#define LDSM4(r0, r1, r2, r3, addr)                                      \
    asm volatile("ldmatrix.sync.aligned.m8n8.x4.shared.b16 "             \
                 "{%0,%1,%2,%3}, [%4];"                                  \
                 : "=r"(r0), "=r"(r1), "=r"(r2), "=r"(r3) : "r"(addr))

#define MMA_F16(d, a, b0, b1)                                            \
    asm volatile(                                                        \
        "mma.sync.aligned.m16n8k16.row.col.f32.f16.f16.f32 "             \
        "{%0,%1,%2,%3}, {%4,%5,%6,%7}, {%8,%9}, {%0,%1,%2,%3};"          \
        : "+f"((d)[0]), "+f"((d)[1]), "+f"((d)[2]), "+f"((d)[3])         \
        : "r"((a)[0]), "r"((a)[1]), "r"((a)[2]), "r"((a)[3]),            \
          "r"(b0), "r"(b1))

#define CP16(dst, src, bytes)                                            \
    asm volatile("cp.async.ca.shared.global [%0], [%1], 16, %2;"         \
                 :: "r"(dst), "l"(src), "r"(bytes))
#define CP_COMMIT() asm volatile("cp.async.commit_group;")
#define CP_WAIT(n)  asm volatile("cp.async.wait_group %0;" :: "n"(n))

__device__ __forceinline__ uint32_t smem_u32(const void* p) {
    uint32_t a;
    asm("{ .reg .u64 t; cvta.to.shared.u64 t, %1; cvt.u32.u64 %0, t; }"
        : "=r"(a) : "l"(p));
    return a;
}

// ---------------------------------------------------------------------------
// fp16 tensor-core GEMM, cp.async 3-stage pipeline (single product).
// ---------------------------------------------------------------------------
#define TROW   40
#define TILEB  10240
#define STAGEB (2 * TILEB)
#define NSTAGE 3
#define GSMEM  (NSTAGE * STAGEB)

__global__ __launch_bounds__(256, 2) void gemm_f16a(
    const __half* __restrict__ A, int lda,
    const __half* __restrict__ Bh, int ldb,
    const float* __restrict__ bias, float* __restrict__ C,
    __half* __restrict__ Ch,
    int M, int N, int K)
{
    extern __shared__ __half sm[];

    int t = threadIdx.x;
    int lane = t & 31, wid = t >> 5;
    int wm = (wid & 1) * 64, wn = (wid >> 1) * 32;
    int rr = lane & 7, j = lane >> 3;
    int m0 = blockIdx.y * 128, n0 = blockIdx.x * 128;

    float acc[4][4][4];
#pragma unroll
    for (int i = 0; i < 4; i++)
#pragma unroll
        for (int jj = 0; jj < 4; jj++)
#pragma unroll
            for (int k = 0; k < 4; k++) acc[i][jj][k] = 0.0f;

    int srow = t >> 1, shalf = t & 1;
    bool aok = (m0 + srow) < M;
    const __half* Ap  = A + (size_t)(aok ? (m0 + srow) : 0) * lda + shalf * 16;
    const __half* Bhp = Bh + (size_t)(n0 + srow) * ldb + shalf * 16;
    uint32_t abytes = aok ? 16u : 0u;
    uint32_t sm_u = smem_u32(sm);
    uint32_t sdst = (uint32_t)(srow * 80 + shalf * 32);

    uint32_t a_off[2][4];
#pragma unroll
    for (int kk = 0; kk < 2; kk++)
#pragma unroll
        for (int mf = 0; mf < 4; mf++)
            a_off[kk][mf] = (uint32_t)(((wm + mf * 16 + rr + (j & 1) * 8) * TROW
                                        + kk * 16 + (j >> 1) * 8) * 2);
    uint32_t b_off[2][2];
#pragma unroll
    for (int kk = 0; kk < 2; kk++)
#pragma unroll
        for (int p = 0; p < 2; p++)
            b_off[kk][p] = (uint32_t)(((wn + p * 16 + rr + (j >> 1) * 8) * TROW
                                       + kk * 16 + (j & 1) * 8) * 2);

#define ISSUE(stg, kt)                                                    \
    {   uint32_t base = sm_u + (stg) * STAGEB + sdst;                     \
        const __half* as = Ap + (kt);                                     \
        CP16(base, as, abytes); CP16(base + 16, as + 8, abytes);          \
        const __half* hs = Bhp + (kt);                                    \
        CP16(base + TILEB, hs, 16u); CP16(base + TILEB + 16, hs + 8, 16u);\
        CP_COMMIT(); }

    int NC = K / 32;
    ISSUE(0, 0);
    if (NC > 1) ISSUE(1, 32);

    for (int c = 0; c < NC; c++) {
        if (c + 1 < NC) { CP_WAIT(1); } else { CP_WAIT(0); }
        __syncthreads();
        if (c + 2 < NC) ISSUE((c + 2) % NSTAGE, (c + 2) * 32);

        uint32_t bb = sm_u + (c % NSTAGE) * STAGEB;
#pragma unroll
        for (int kk = 0; kk < 2; kk++) {
            uint32_t bhf[8];
            LDSM4(bhf[0], bhf[1], bhf[2], bhf[3], bb + TILEB + b_off[kk][0]);
            LDSM4(bhf[4], bhf[5], bhf[6], bhf[7], bb + TILEB + b_off[kk][1]);
#pragma unroll
            for (int mf = 0; mf < 4; mf++) {
                uint32_t ahf[4];
                LDSM4(ahf[0], ahf[1], ahf[2], ahf[3], bb + a_off[kk][mf]);
#pragma unroll
                for (int nf = 0; nf < 4; nf++)
                    MMA_F16(acc[mf][nf], ahf, bhf[nf * 2], bhf[nf * 2 + 1]);
            }
        }
        __syncthreads();
    }

    int er = lane >> 2, ec = (lane & 3) * 2;
#pragma unroll
    for (int nf = 0; nf < 4; nf++) {
        int col = n0 + wn + nf * 8 + ec;
        float bb0 = bias ? bias[col] : 0.0f;
        float bb1 = bias ? bias[col + 1] : 0.0f;
#pragma unroll
        for (int mf = 0; mf < 4; mf++) {
            int row = m0 + wm + mf * 16 + er;
            if (row < M) {
                float v0 = acc[mf][nf][0] + bb0, v1 = acc[mf][nf][1] + bb1;
                if (Ch)
                    *(__half2*)&Ch[(size_t)row * N + col]
                        = __halves2half2(__float2half(v0), __float2half(v1));
                else
                    *(float2*)&C[(size_t)row * N + col] = make_float2(v0, v1);
            }
            if (row + 8 < M) {
                float v0 = acc[mf][nf][2] + bb0, v1 = acc[mf][nf][3] + bb1;
                if (Ch)
                    *(__half2*)&Ch[(size_t)(row + 8) * N + col]
                        = __halves2half2(__float2half(v0), __float2half(v1));
                else
                    *(float2*)&C[(size_t)(row + 8) * N + col] = make_float2(v0, v1);
            }
        }
    }
}

// ---------------------------------------------------------------------------
// Implicit-GEMM conv (fused im2col).  blockIdx.z = K split (KSPLIT ways).
// ---------------------------------------------------------------------------
__global__ __launch_bounds__(256, 2) void gemm_conv(
    const __half* __restrict__ PT,
    const __half* __restrict__ Bh,
    float* __restrict__ C)
{
    extern __shared__ __half sm[];

    int kbase = blockIdx.z * KSLAB;
    C += (size_t)blockIdx.z * MCONV * IC;

    int t = threadIdx.x;
    int lane = t & 31, wid = t >> 5;
    int wm = (wid & 1) * 64, wn = (wid >> 1) * 32;
    int rr = lane & 7, j = lane >> 3;
    int m0 = blockIdx.y * 128, n0 = blockIdx.x * 128;

    float acc[4][4][4];
#pragma unroll
    for (int i = 0; i < 4; i++)
#pragma unroll
        for (int jj = 0; jj < 4; jj++)
#pragma unroll
            for (int k = 0; k < 4; k++) acc[i][jj][k] = 0.0f;

    int srow = t >> 1, shalf = t & 1;
    int gr = m0 + srow;
    bool aok = gr < MCONV;
    int bb_ = aok ? gr / AG : 0, pp = aok ? gr % AG : 0;
    int py = pp / 7, px = pp % 7;
    const __half* Pb = PT + (size_t)bb_ * PFLAT;
    const __half* Bhp = Bh + (size_t)(n0 + srow) * KCONV + kbase + shalf * 16;
    uint32_t sm_u = smem_u32(sm);
    uint32_t sdst = (uint32_t)(srow * 80 + shalf * 32);

    uint32_t a_off[2][4];
#pragma unroll
    for (int kk = 0; kk < 2; kk++)
#pragma unroll
        for (int mf = 0; mf < 4; mf++)
            a_off[kk][mf] = (uint32_t)(((wm + mf * 16 + rr + (j & 1) * 8) * TROW
                                        + kk * 16 + (j >> 1) * 8) * 2);
    uint32_t b_off[2][2];
#pragma unroll
    for (int kk = 0; kk < 2; kk++)
#pragma unroll
        for (int p = 0; p < 2; p++)
            b_off[kk][p] = (uint32_t)(((wn + p * 16 + rr + (j >> 1) * 8) * TROW
                                       + kk * 16 + (j & 1) * 8) * 2);

#define ISSUEC(stg, kt)                                                   \
    {   uint32_t base = sm_u + (stg) * STAGEB + sdst;                     \
        int kabs = kbase + (kt) + shalf * 16;                             \
        int k9 = kabs / 768, kof = kabs - k9 * 768;                       \
        int sy = py + k9 / 3 - 1, sx = px + (k9 - (k9 / 3) * 3) - 1;      \
        bool v = aok && sy >= 0 && sy < 7 && sx >= 0 && sx < 7;           \
        int sp = v ? (sy * 7 + sx) : 0;                                   \
        const __half* as = Pb + (size_t)sp * CIN + kof;                   \
        uint32_t ab = v ? 16u : 0u;                                       \
        CP16(base, as, ab); CP16(base + 16, as + 8, ab);                  \
        const __half* hs = Bhp + (kt);                                    \
        CP16(base + TILEB, hs, 16u); CP16(base + TILEB + 16, hs + 8, 16u);\
        CP_COMMIT(); }

    int NC = KSLAB / 32;
    ISSUEC(0, 0);
    ISSUEC(1, 32);

    for (int c = 0; c < NC; c++) {
        if (c + 1 < NC) { CP_WAIT(1); } else { CP_WAIT(0); }
        __syncthreads();
        if (c + 2 < NC) ISSUEC((c + 2) % NSTAGE, (c + 2) * 32);

        uint32_t bb = sm_u + (c % NSTAGE) * STAGEB;
#pragma unroll
        for (int kk = 0; kk < 2; kk++) {
            uint32_t bhf[8];
            LDSM4(bhf[0], bhf[1], bhf[2], bhf[3], bb + TILEB + b_off[kk][0]);
            LDSM4(bhf[4], bhf[5], bhf[6], bhf[7], bb + TILEB + b_off[kk][1]);
#pragma unroll
            for (int mf = 0; mf < 4; mf++) {
                uint32_t ahf[4];
                LDSM4(ahf[0], ahf[1], ahf[2], ahf[3], bb + a_off[kk][mf]);
#pragma unroll
                for (int nf = 0; nf < 4; nf++)
                    MMA_F16(acc[mf][nf], ahf, bhf[nf * 2], bhf[nf * 2 + 1]);
            }
        }
        __syncthreads();
    }

    int er = lane >> 2, ec = (lane & 3) * 2;
#pragma unroll
    for (int nf = 0; nf < 4; nf++) {
        int col = n0 + wn + nf * 8 + ec;
#pragma unroll
        for (int mf = 0; mf < 4; mf++) {
            int row = m0 + wm + mf * 16 + er;
            if (row < MCONV)
                *(float2*)&C[(size_t)row * IC + col]
                    = make_float2(acc[mf][nf][0], acc[mf][nf][1]);
            if (row + 8 < MCONV)
                *(float2*)&C[(size_t)(row + 8) * IC + col]
                    = make_float2(acc[mf][nf][2], acc[mf][nf][3]);
        }
    }
}

// ---------------------------------------------------------------------------
// Merged pre-convert kernels
// ---------------------------------------------------------------------------
__global__ __launch_bounds__(256) void transpose3_h(
    const float* __restrict__ Wq, const float* __restrict__ Wkv,
    const float* __restrict__ proj_w,
    __half* __restrict__ whT, __half* __restrict__ pwhT)
{
    __shared__ float tile[32][33];
    int z = blockIdx.z;
    const float* src; __half* dst; int C;
    if (z == 0)      { src = Wq;     dst = whT;                       C = IC; }
    else if (z == 1) { src = Wkv;    dst = whT + (size_t)IC * DIM;    C = 2 * IC; }
    else             { src = proj_w; dst = pwhT;                      C = IC; }
    int cb = blockIdx.x * 32, rb = blockIdx.y * 32;
    if (cb >= C) return;
    int tx = threadIdx.x & 31, ty = threadIdx.x >> 5;
    for (int i = ty; i < 32; i += 8) {
        int r = rb + i, c = cb + tx;
        if (c < C) tile[i][tx] = src[(size_t)r * C + c];
    }
    __syncthreads();
    for (int i = ty; i < 32; i += 8) {
        int c = cb + i, r = rb + tx;
        if (c < C) dst[(size_t)c * DIM + r] = __float2half(tile[tx][i]);
    }
}

__global__ void cvt2_kernel(const float* __restrict__ x,
                            const float* __restrict__ conv_w,
                            __half* __restrict__ xh, __half* __restrict__ cwh9,
                            size_t nx, size_t nc)
{
    size_t i = (size_t)blockIdx.x * blockDim.x + threadIdx.x;
    if (i < nx) xh[i] = __float2half(x[i]);
    else if (i < nx + nc) {
        size_t w = i - nx;
        int co = (int)(w / KCONV), r = (int)(w % KCONV);
        int k9 = r / CIN, ci = r % CIN;
        cwh9[w] = __float2half(conv_w[(size_t)co * KCONV + ci * 9 + k9]);
    }
}

// ---------------------------------------------------------------------------
// Adaptive pooling -> pooled[b][a*768 + c].  One block per (a, b).
// Thread t: q channels (2t, 2t+1) via half2 + ctx channel 512+t.
// Per-channel (hh,ww) summation order identical to prior version.
// ---------------------------------------------------------------------------
__global__ __launch_bounds__(256) void pool_kernel(
    const __half* __restrict__ qkvh, const float* __restrict__ context,
    float* __restrict__ pooled)
{
    int a = blockIdx.x, b = blockIdx.y;
    int p = a / 7, q = a % 7;
    int sh = p * 32 / 7, eh = ((p + 1) * 32 + 6) / 7;
    int sw = q * 32 / 7, ew = ((q + 1) * 32 + 6) / 7;
    float inv = 1.0f / (float)((eh - sh) * (ew - sw));
    int t = threadIdx.x;

    float s0 = 0.0f, s1 = 0.0f, sc = 0.0f;
    for (int hh = sh; hh < eh; hh++) {
        const __half* qrow = qkvh + ((size_t)(b * N_TOK) + hh * WW) * NQKV + 2 * t;
        const float*  crow = context + ((size_t)(b * N_TOK) + hh * WW) * CC + t;
        for (int ww = sw; ww < ew; ww++) {
            float2 f = __half22float2(*(const __half2*)(qrow + (size_t)ww * NQKV));
            s0 += f.x; s1 += f.y;
            sc += crow[(size_t)ww * CC];
        }
    }
    float* dst = pooled + ((size_t)b * AG + a) * CIN;
    dst[2 * t]     = s0 * inv;
    dst[2 * t + 1] = s1 * inv;
    dst[IC + t]    = sc * inv;
}

// Transpose raw-reshaped (768,49) view -> poolT[b][s*768+ci] (fp16).
__global__ __launch_bounds__(256) void poolT_kernel(
    const float* __restrict__ pooled, __half* __restrict__ PT)
{
    __shared__ float tile[64][52];
    int b = blockIdx.y, cr0 = blockIdx.x * 64;
    const float* IN = pooled + (size_t)b * PFLAT;
    __half* OUT = PT + (size_t)b * PFLAT;
    for (int e = threadIdx.x; e < 64 * AG; e += 256) {
        int i = e / AG, s = e % AG;
        tile[i][s] = IN[(size_t)(cr0 + i) * AG + s];
    }
    __syncthreads();
    for (int e = threadIdx.x; e < 64 * AG; e += 256) {
        int s = e >> 6, i = e & 63;
        OUT[(size_t)s * CIN + cr0 + i] = __float2half(tile[i][s]);
    }
}

// Reduce split-K partials + conv bias, transpose to agent_cs[b][c*49+s]
__global__ __launch_bounds__(256) void conv_reduce_tr(
    const float* __restrict__ parts, const float* __restrict__ conv_b,
    float* __restrict__ out)
{
    int b = blockIdx.x, cb = blockIdx.y * 64;
    __shared__ float tile[64][50];
    int t = threadIdx.x;
    for (int e = t; e < 64 * AG; e += 256) {
        int c = e & 63, s = e >> 6;
        float v = conv_b[cb + c];
#pragma unroll
        for (int p = 0; p < KSPLIT; p++)
            v += parts[(size_t)p * MCONV * IC + ((size_t)b * AG + s) * IC + cb + c];
        tile[c][s] = v;
    }
    __syncthreads();
    for (int e = t; e < 64 * AG; e += 256) {
        int s = e % AG, c = e / AG;
        out[(size_t)b * AGFLAT + (cb + c) * AG + s] = tile[c][s];
    }
}

// ---------------------------------------------------------------------------
// Bias tables (merged)
// ---------------------------------------------------------------------------
__device__ __forceinline__ float bilin7(const float* __restrict__ src, int yi, int xi)
{
    float fy = (yi + 0.5f) * (7.0f / 32.0f) - 0.5f;
    float fx = (xi + 0.5f) * (7.0f / 32.0f) - 0.5f;
    int y0 = (int)floorf(fy); float wy = fy - (float)y0;
    int x0 = (int)floorf(fx); float wx = fx - (float)x0;
    int y0c = max(y0, 0), y1c = min(y0 + 1, 6);
    int x0c = max(x0, 0), x1c = min(x0 + 1, 6);
    float v00 = src[y0c * 7 + x0c], v01 = src[y0c * 7 + x1c];
    float v10 = src[y1c * 7 + x0c], v11 = src[y1c * 7 + x1c];
    return (1.f - wy) * ((1.f - wx) * v00 + wx * v01)
         + wy * ((1.f - wx) * v10 + wx * v11);
}

__global__ void bias_both_kernel(
    const float* __restrict__ an_bias, const float* __restrict__ ah_bias,
    const float* __restrict__ aw_bias,
    const float* __restrict__ na_bias, const float* __restrict__ ha_bias,
    const float* __restrict__ wa_bias,
    float* __restrict__ out_an, float* __restrict__ out_na)
{
    int idx = blockIdx.x * blockDim.x + threadIdx.x;
    if (blockIdx.y == 0) {
        if (idx >= NH * AG * N_TOK) return;
        int n = idx % N_TOK;
        int r = idx / N_TOK;
        int a = r % AG, h = r / AG;
        int hi = n >> 5, wi = n & 31;
        const float* src = an_bias + (size_t)(h * AG + a) * 49;
        out_an[idx] = bilin7(src, hi, wi)
                    + ah_bias[(h * AG + a) * 32 + hi]
                    + aw_bias[(h * AG + a) * 32 + wi];
    } else {
        if (idx >= NH * N_TOK * AG) return;
        int a = idx % AG;
        int r = idx / AG;
        int n = r % N_TOK, h = r / N_TOK;
        int hi = n >> 5, wi = n & 31;
        const float* src = na_bias + (size_t)(h * AG + a) * 49;
        out_na[idx] = bilin7(src, hi, wi)
                    + ha_bias[(h * 32 + hi) * AG + a]
                    + wa_bias[(h * 32 + wi) * AG + a];
    }
}

// ---------------------------------------------------------------------------
// Agent attention (flash, tensor-core).  One block per (b,h), 256 threads.
// ---------------------------------------------------------------------------
#define FL_SS 0
#define FL_AT 34048
#define FL_KS 43264
#define FL_VT 61696
#define FL_PS 79104
#define FL_MR 96512
#define FL_LR 96768
#define FL_FR 97024
#define FL_PM 97280
#define FL_PX 98304
#define FL_SMEM 99328

__global__ __launch_bounds__(256) void agent_flash_mma(
    const __half* __restrict__ qkvh, const float* __restrict__ agent_cs,
    const float* __restrict__ bias_an, float* __restrict__ agv)
{
    extern __shared__ char fsm[];
    float*  SS = (float*)(fsm + FL_SS);
    __half* AT = (__half*)(fsm + FL_AT);
    __half* KS = (__half*)(fsm + FL_KS);
    __half* VT = (__half*)(fsm + FL_VT);
    __half* PS = (__half*)(fsm + FL_PS);
    float*  MR = (float*)(fsm + FL_MR);
    float*  LR = (float*)(fsm + FL_LR);
    float*  FR = (float*)(fsm + FL_FR);
    float*  PM = (float*)(fsm + FL_PM);
    float*  PX = (float*)(fsm + FL_PX);

    int b = blockIdx.x, h = blockIdx.y, t = threadIdx.x;
    int lane = t & 31, wid = t >> 5;
    int rr = lane & 7, j = lane >> 3;
    int er = lane >> 2, ec = (lane & 3) * 2;
    int rid = t >> 2, seg = t & 3;

    uint32_t at_u = smem_u32(AT), ks_u = smem_u32(KS);
    uint32_t vt_u = smem_u32(VT), ps_u = smem_u32(PS);

    int wm1 = (wid & 1) * 32, wn1 = (wid >> 1) * 32;
    int wm2 = (wid & 3) * 16, wn2 = (wid >> 2) * 32;

    for (int e = t; e < 64 * 64; e += 256) {
        int a = e >> 6, d = e & 63;
        AT[a * 72 + d] = (a < AG)
            ? __float2half(agent_cs[(size_t)b * AGFLAT + a * IC + h * HD + d])
            : __half(0.0f);
    }
    if (t < 64) { MR[t] = -1e30f; LR[t] = 0.0f; }

    float acc2[4][4];
#pragma unroll
    for (int nf = 0; nf < 4; nf++)
#pragma unroll
        for (int k = 0; k < 4; k++) acc2[nf][k] = 0.0f;

    uint32_t a1_off[4][2], b1_off[4][2];
#pragma unroll
    for (int kk = 0; kk < 4; kk++) {
#pragma unroll
        for (int mf = 0; mf < 2; mf++)
            a1_off[kk][mf] = (uint32_t)(((wm1 + mf * 16 + rr + (j & 1) * 8) * 72
                                         + kk * 16 + (j >> 1) * 8) * 2);
#pragma unroll
        for (int p = 0; p < 2; p++)
            b1_off[kk][p] = (uint32_t)(((wn1 + p * 16 + rr + (j >> 1) * 8) * 72
                                        + kk * 16 + (j & 1) * 8) * 2);
    }
    uint32_t a2_off[8], b2_off[8][2];
#pragma unroll
    for (int kk = 0; kk < 8; kk++) {
        a2_off[kk] = (uint32_t)(((wm2 + rr + (j & 1) * 8) * 136
                                 + kk * 16 + (j >> 1) * 8) * 2);
#pragma unroll
        for (int p = 0; p < 2; p++)
            b2_off[kk][p] = (uint32_t)(((wn2 + p * 16 + rr + (j >> 1) * 8) * 136
                                        + kk * 16 + (j & 1) * 8) * 2);
    }

    for (int jt = 0; jt < N_TOK; jt += 128) {
        __syncthreads();
        for (int e = t; e < 1024; e += 256) {
            int jj = e >> 3, ch = e & 7;
            *(float4*)(KS + jj * 72 + ch * 8) = *(const float4*)(
                qkvh + ((size_t)(b * N_TOK + jt + jj)) * NQKV + IC + h * HD + ch * 8);
        }
        for (int e = t; e < 8192; e += 256) {
            int d = e & 63, jj = e >> 6;
            VT[d * 136 + jj] =
                qkvh[((size_t)(b * N_TOK + jt + jj)) * NQKV + 2 * IC + h * HD + d];
        }
        __syncthreads();

        float acc1[2][4][4];
#pragma unroll
        for (int mf = 0; mf < 2; mf++)
#pragma unroll
            for (int nf = 0; nf < 4; nf++)
#pragma unroll
                for (int k = 0; k < 4; k++) acc1[mf][nf][k] = 0.0f;
#pragma unroll
        for (int kk = 0; kk < 4; kk++) {
            uint32_t bf[8];
            LDSM4(bf[0], bf[1], bf[2], bf[3], ks_u + b1_off[kk][0]);
            LDSM4(bf[4], bf[5], bf[6], bf[7], ks_u + b1_off[kk][1]);
#pragma unroll
            for (int mf = 0; mf < 2; mf++) {
                uint32_t af[4];
                LDSM4(af[0], af[1], af[2], af[3], at_u + a1_off[kk][mf]);
#pragma unroll
                for (int nf = 0; nf < 4; nf++)
                    MMA_F16(acc1[mf][nf], af, bf[nf * 2], bf[nf * 2 + 1]);
            }
        }
#pragma unroll
        for (int mf = 0; mf < 2; mf++) {
            int a0 = wm1 + mf * 16 + er, a1 = a0 + 8;
            const float* bb0 = (a0 < AG) ? bias_an + (size_t)(h * AG + a0) * N_TOK + jt : nullptr;
            const float* bb1 = (a1 < AG) ? bias_an + (size_t)(h * AG + a1) * N_TOK + jt : nullptr;
#pragma unroll
            for (int nf = 0; nf < 4; nf++) {
                int jc = wn1 + nf * 8 + ec;
                if (bb0) {
                    SS[a0 * 133 + jc]     = acc1[mf][nf][0] * 0.125f + bb0[jc];
                    SS[a0 * 133 + jc + 1] = acc1[mf][nf][1] * 0.125f + bb0[jc + 1];
                } else {
                    SS[a0 * 133 + jc] = -1e30f; SS[a0 * 133 + jc + 1] = -1e30f;
                }
                if (bb1) {
                    SS[a1 * 133 + jc]     = acc1[mf][nf][2] * 0.125f + bb1[jc];
                    SS[a1 * 133 + jc + 1] = acc1[mf][nf][3] * 0.125f + bb1[jc + 1];
                } else {
                    SS[a1 * 133 + jc] = -1e30f; SS[a1 * 133 + jc + 1] = -1e30f;
                }
            }
        }
        __syncthreads();

        {
            float pm = -1e30f;
            const float* row = SS + rid * 133 + seg * 32;
            for (int i = 0; i < 32; i++) pm = fmaxf(pm, row[i]);
            PM[rid * 4 + seg] = pm;
        }
        __syncthreads();
        if (t < 64) {
            float mnew = fmaxf(fmaxf(PM[t * 4], PM[t * 4 + 1]),
                               fmaxf(PM[t * 4 + 2], PM[t * 4 + 3]));
            mnew = fmaxf(MR[t], mnew);
            FR[t] = __expf(MR[t] - mnew);
            MR[t] = mnew;
        }
        __syncthreads();
        {
            float m = MR[rid], ps = 0.0f;
            const float* row = SS + rid * 133 + seg * 32;
            __half* prow = PS + rid * 136 + seg * 32;
            for (int i = 0; i < 32; i++) {
                float e = __expf(row[i] - m);
                prow[i] = __float2half(e);
                ps += e;
            }
            PX[rid * 4 + seg] = ps;
        }
        __syncthreads();
        if (t < 64)
            LR[t] = LR[t] * FR[t]
                  + PX[t * 4] + PX[t * 4 + 1] + PX[t * 4 + 2] + PX[t * 4 + 3];

        {
            float f0 = FR[wm2 + er], f1 = FR[wm2 + er + 8];
#pragma unroll
            for (int nf = 0; nf < 4; nf++) {
                acc2[nf][0] *= f0; acc2[nf][1] *= f0;
                acc2[nf][2] *= f1; acc2[nf][3] *= f1;
            }
        }
#pragma unroll
        for (int kk = 0; kk < 8; kk++) {
            uint32_t bf[8];
            LDSM4(bf[0], bf[1], bf[2], bf[3], vt_u + b2_off[kk][0]);
            LDSM4(bf[4], bf[5], bf[6], bf[7], vt_u + b2_off[kk][1]);
            uint32_t af[4];
            LDSM4(af[0], af[1], af[2], af[3], ps_u + a2_off[kk]);
#pragma unroll
            for (int nf = 0; nf < 4; nf++)
                MMA_F16(acc2[nf], af, bf[nf * 2], bf[nf * 2 + 1]);
        }
    }

    __syncthreads();
    {
        int a0 = wm2 + er, a1 = a0 + 8;
        float i0 = (a0 < AG) ? 1.0f / LR[a0] : 0.0f;
        float i1 = (a1 < AG) ? 1.0f / LR[a1] : 0.0f;
#pragma unroll
        for (int nf = 0; nf < 4; nf++) {
            int d = wn2 + nf * 8 + ec;
            if (a0 < AG)
                *(float2*)&agv[(((size_t)(b * NH + h) * AG) + a0) * HD + d]
                    = make_float2(acc2[nf][0] * i0, acc2[nf][1] * i0);
            if (a1 < AG)
                *(float2*)&agv[(((size_t)(b * NH + h) * AG) + a1) * HD + d]
                    = make_float2(acc2[nf][2] * i1, acc2[nf][3] * i1);
        }
    }
}

// ---------------------------------------------------------------------------
// Query attention (tensor-core) -> outh (fp16).  Block (b,h,nt), 128 threads.
// ---------------------------------------------------------------------------
#define QA_SS 0
#define QA_QS 16640
#define QA_AT 25856
#define QA_PS 35072
#define QA_SMEM 44288

__global__ __launch_bounds__(128) void qattn_mma(
    const __half* __restrict__ qkvh, const float* __restrict__ agent_cs,
    const float* __restrict__ agv, const float* __restrict__ bias_na,
    __half* __restrict__ outh)
{
    extern __shared__ char qsm[];
    float*  SS  = (float*)(qsm + QA_SS);
    __half* QS  = (__half*)(qsm + QA_QS);
    __half* ATS = (__half*)(qsm + QA_AT);
    __half* PS  = (__half*)(qsm + QA_PS);

    int b = blockIdx.x, h = blockIdx.y, nt = blockIdx.z;
    int t = threadIdx.x;
    int lane = t & 31, wid = t >> 5;
    int rr = lane & 7, j = lane >> 3;
    int er = lane >> 2, ec = (lane & 3) * 2;
    int wm = (wid & 1) * 32, wn = (wid >> 1) * 32;

    uint32_t qs_u = smem_u32(QS), at_u = smem_u32(ATS), ps_u = smem_u32(PS);

    for (int e = t; e < 512; e += 128) {
        int nn = e >> 3, ch = e & 7;
        *(float4*)(QS + nn * 72 + ch * 8) = *(const float4*)(
            qkvh + ((size_t)(b * N_TOK) + nt * 64 + nn) * NQKV + h * HD + ch * 8);
    }
    for (int e = t; e < 64 * 64; e += 128) {
        int a = e >> 6, d = e & 63;
        ATS[a * 72 + d] = (a < AG)
            ? __float2half(agent_cs[(size_t)b * AGFLAT + a * IC + h * HD + d])
            : __half(0.0f);
    }
    __syncthreads();

    uint32_t a_off[4][2], b_off[4][2];
#pragma unroll
    for (int kk = 0; kk < 4; kk++) {
#pragma unroll
        for (int mf = 0; mf < 2; mf++)
            a_off[kk][mf] = (uint32_t)(((wm + mf * 16 + rr + (j & 1) * 8) * 72
                                        + kk * 16 + (j >> 1) * 8) * 2);
#pragma unroll
        for (int p = 0; p < 2; p++)
            b_off[kk][p] = (uint32_t)(((wn + p * 16 + rr + (j >> 1) * 8) * 72
                                       + kk * 16 + (j & 1) * 8) * 2);
    }

    float acc[2][4][4];
#pragma unroll
    for (int mf = 0; mf < 2; mf++)
#pragma unroll
        for (int nf = 0; nf < 4; nf++)
#pragma unroll
            for (int k = 0; k < 4; k++) acc[mf][nf][k] = 0.0f;

#pragma unroll
    for (int kk = 0; kk < 4; kk++) {
        uint32_t bf[8];
        LDSM4(bf[0], bf[1], bf[2], bf[3], at_u + b_off[kk][0]);
        LDSM4(bf[4], bf[5], bf[6], bf[7], at_u + b_off[kk][1]);
#pragma unroll
        for (int mf = 0; mf < 2; mf++) {
            uint32_t af[4];
            LDSM4(af[0], af[1], af[2], af[3], qs_u + a_off[kk][mf]);
#pragma unroll
            for (int nf = 0; nf < 4; nf++)
                MMA_F16(acc[mf][nf], af, bf[nf * 2], bf[nf * 2 + 1]);
        }
    }
#pragma unroll
    for (int mf = 0; mf < 2; mf++) {
        int tok0 = wm + mf * 16 + er, tok1 = tok0 + 8;
        const float* bn0 = bias_na + ((size_t)(h * N_TOK) + nt * 64 + tok0) * AG;
        const float* bn1 = bias_na + ((size_t)(h * N_TOK) + nt * 64 + tok1) * AG;
#pragma unroll
        for (int nf = 0; nf < 4; nf++) {
            int a = wn + nf * 8 + ec;
            SS[tok0 * 65 + a]     = (a < AG)     ? acc[mf][nf][0] * 0.125f + bn0[a]     : -1e30f;
            SS[tok0 * 65 + a + 1] = (a + 1 < AG) ? acc[mf][nf][1] * 0.125f + bn0[a + 1] : -1e30f;
            SS[tok1 * 65 + a]     = (a < AG)     ? acc[mf][nf][2] * 0.125f + bn1[a]     : -1e30f;
            SS[tok1 * 65 + a + 1] = (a + 1 < AG) ? acc[mf][nf][3] * 0.125f + bn1[a + 1] : -1e30f;
        }
    }
    __syncthreads();

    if (t < 64) {
        const float* row = SS + t * 65;
        float m = -1e30f;
        for (int a = 0; a < 64; a++) m = fmaxf(m, row[a]);
        float s = 0.0f;
        float e[64];
        for (int a = 0; a < 64; a++) { e[a] = __expf(row[a] - m); s += e[a]; }
        float inv = 1.0f / s;
        __half* prow = PS + t * 72;
        for (int a = 0; a < 64; a++) prow[a] = __float2half(e[a] * inv);
    } else {
        int d = t - 64;
        __half* vrow = ATS + d * 72;
        const float* ga = agv + ((size_t)(b * NH + h) * AG) * HD + d;
        for (int a = 0; a < AG; a++) vrow[a] = __float2half(ga[(size_t)a * HD]);
        for (int a = AG; a < 64; a++) vrow[a] = __half(0.0f);
    }
    __syncthreads();

#pragma unroll
    for (int mf = 0; mf < 2; mf++)
#pragma unroll
        for (int nf = 0; nf < 4; nf++)
#pragma unroll
            for (int k = 0; k < 4; k++) acc[mf][nf][k] = 0.0f;
#pragma unroll
    for (int kk = 0; kk < 4; kk++) {
        uint32_t bf[8];
        LDSM4(bf[0], bf[1], bf[2], bf[3], at_u + b_off[kk][0]);
        LDSM4(bf[4], bf[5], bf[6], bf[7], at_u + b_off[kk][1]);
#pragma unroll
        for (int mf = 0; mf < 2; mf++) {
            uint32_t af[4];
            LDSM4(af[0], af[1], af[2], af[3], ps_u + a_off[kk][mf]);
#pragma unroll
            for (int nf = 0; nf < 4; nf++)
                MMA_F16(acc[mf][nf], af, bf[nf * 2], bf[nf * 2 + 1]);
        }
    }
#pragma unroll
    for (int mf = 0; mf < 2; mf++) {
        int tok0 = nt * 64 + wm + mf * 16 + er;
#pragma unroll
        for (int nf = 0; nf < 4; nf++) {
            int d = wn + nf * 8 + ec;
            *(__half2*)&outh[((size_t)(b * N_TOK) + tok0) * IC + h * HD + d]
                = __halves2half2(__float2half(acc[mf][nf][0]),
                                 __float2half(acc[mf][nf][1]));
            *(__half2*)&outh[((size_t)(b * N_TOK) + tok0 + 8) * IC + h * HD + d]
                = __halves2half2(__float2half(acc[mf][nf][2]),
                                 __float2half(acc[mf][nf][3]));
        }
    }
}

// ---------------------------------------------------------------------------
// Depthwise 3x3 conv, sliding-window; fused in-place add into outh.
// ---------------------------------------------------------------------------
__global__ __launch_bounds__(512) void dwc_kernel(
    const __half* __restrict__ qkvh,
    const float* __restrict__ dwc_w, const float* __restrict__ dwc_b,
    __half* __restrict__ outh)
{
    int hh = blockIdx.x, b = blockIdx.y;
    int c = threadIdx.x;
    float w9[9];
#pragma unroll
    for (int i = 0; i < 9; i++) w9[i] = dwc_w[c * 9 + i];
    float wb = dwc_b[c];
    const __half* vb = qkvh + (size_t)(b * N_TOK) * NQKV + 2 * IC + c;

    float c0[3], c1[3], c2[3];
#define LOADCOL(x, dst)                                                   \
    {   if ((x) < 0 || (x) >= WW) { dst[0] = dst[1] = dst[2] = 0.0f; }    \
        else {                                                            \
            _Pragma("unroll")                                             \
            for (int r = 0; r < 3; r++) {                                 \
                int y = hh - 1 + r;                                       \
                dst[r] = (y >= 0 && y < HH)                               \
                    ? __half2float(vb[(size_t)(y * WW + (x)) * NQKV])     \
                    : 0.0f;                                               \
            } } }

    LOADCOL(-1, c0);
    LOADCOL(0, c1);
    for (int x = 0; x < WW; x++) {
        LOADCOL(x + 1, c2);
        float s = wb;
#pragma unroll
        for (int r = 0; r < 3; r++) {
            s += w9[r * 3 + 0] * c0[r];
            s += w9[r * 3 + 1] * c1[r];
            s += w9[r * 3 + 2] * c2[r];
        }
        size_t i = ((size_t)(b * N_TOK) + hh * WW + x) * IC + c;
        outh[i] = __float2half(__half2float(outh[i]) + s);
#pragma unroll
        for (int r = 0; r < 3; r++) { c0[r] = c1[r]; c1[r] = c2[r]; }
    }
}

// ---------------------------------------------------------------------------
// Host launcher
// ---------------------------------------------------------------------------
extern "C" void kernel_launch(void* const* d_in, const int* in_sizes, int n_in,
                              void* d_out, int out_size)
{
    const float* x       = (const float*)d_in[0];
    const float* context = (const float*)d_in[1];
    const float* Wq      = (const float*)d_in[2];
    const float* Wkv     = (const float*)d_in[3];
    const float* conv_w  = (const float*)d_in[4];
    const float* conv_b  = (const float*)d_in[5];
    const float* dwc_w   = (const float*)d_in[6];
    const float* dwc_b   = (const float*)d_in[7];
    const float* proj_w  = (const float*)d_in[8];
    const float* proj_b  = (const float*)d_in[9];
    const float* an_bias = (const float*)d_in[10];
    const float* na_bias = (const float*)d_in[11];
    const float* ah_bias = (const float*)d_in[12];
    const float* aw_bias = (const float*)d_in[13];
    const float* ha_bias = (const float*)d_in[14];
    const float* wa_bias = (const float*)d_in[15];
    float* out = (float*)d_out;

    float  *pooled, *convp, *agent_cs, *ban, *bna, *agv;
    __half *qkvh, *xh, *whT, *pwhT, *cwh9, *poolT, *outh;
    cudaGetSymbolAddress((void**)&qkvh,     g_qkvh);
    cudaGetSymbolAddress((void**)&xh,       g_xh);
    cudaGetSymbolAddress((void**)&whT,      g_whT);
    cudaGetSymbolAddress((void**)&pwhT,     g_pwhT);
    cudaGetSymbolAddress((void**)&cwh9,     g_cwh9);
    cudaGetSymbolAddress((void**)&pooled,   g_pooled);
    cudaGetSymbolAddress((void**)&poolT,    g_poolT);
    cudaGetSymbolAddress((void**)&convp,    g_convp);
    cudaGetSymbolAddress((void**)&agent_cs, g_agent_cs);
    cudaGetSymbolAddress((void**)&ban,      g_bias_an);
    cudaGetSymbolAddress((void**)&bna,      g_bias_na);
    cudaGetSymbolAddress((void**)&agv,      g_agv);
    cudaGetSymbolAddress((void**)&outh,     g_outh);

    cudaFuncSetAttribute(gemm_f16a,
                         cudaFuncAttributeMaxDynamicSharedMemorySize, GSMEM);
    cudaFuncSetAttribute(gemm_conv,
                         cudaFuncAttributeMaxDynamicSharedMemorySize, GSMEM);
    cudaFuncSetAttribute(agent_flash_mma,
                         cudaFuncAttributeMaxDynamicSharedMemorySize, FL_SMEM);
    cudaFuncSetAttribute(qattn_mma,
                         cudaFuncAttributeMaxDynamicSharedMemorySize, QA_SMEM);

    // 1. operand prep (merged; conv weights reordered k9-major)
    {
        size_t nx = (size_t)B * N_TOK * DIM;
        size_t nc = (size_t)IC * KCONV;
        cvt2_kernel<<<(int)((nx + nc + 255) / 256), 256>>>(
            x, conv_w, xh, cwh9, nx, nc);
    }
    transpose3_h<<<dim3(32, DIM / 32, 3), 256>>>(Wq, Wkv, proj_w, whT, pwhT);

    // 2. fused QKV GEMM -> fp16
    gemm_f16a<<<dim3(NQKV / 128, (B * N_TOK) / 128), 256, GSMEM>>>(
        xh, DIM, whT, DIM, nullptr, nullptr, qkvh, B * N_TOK, NQKV, DIM);

    // 3. adaptive pool (vectorized) + transpose to implicit-GEMM layout
    pool_kernel<<<dim3(AG, B), 256>>>(qkvh, context, pooled);
    poolT_kernel<<<dim3(CIN / 64, B), 256>>>(pooled, poolT);

    // 4. implicit-GEMM conv (8-way split-K) + reduce
    gemm_conv<<<dim3(IC / 128, (MCONV + 127) / 128, KSPLIT), 256, GSMEM>>>(
        poolT, cwh9, convp);
    conv_reduce_tr<<<dim3(B, IC / 64), 256>>>(convp, conv_b, agent_cs);

    // 5. bias tables (merged)
    bias_both_kernel<<<dim3((NH * AG * N_TOK + 255) / 256, 2), 256>>>(
        an_bias, ah_bias, aw_bias, na_bias, ha_bias, wa_bias, ban, bna);

    // 6. agent attention (tensor-core flash)
    agent_flash_mma<<<dim3(B, NH), 256, FL_SMEM>>>(qkvh, agent_cs, ban, agv);

    // 7. query attention (tensor-core) -> outh (fp16)
    qattn_mma<<<dim3(B, NH, N_TOK / 64), 128, QA_SMEM>>>(
        qkvh, agent_cs, agv, bna, outh);

    // 8. depthwise conv residual, sliding-window, in-place into outh
    dwc_kernel<<<dim3(HH, B), 512>>>(qkvh, dwc_w, dwc_b, outh);

    // 9. output projection
    gemm_f16a<<<dim3(IC / 128, (B * N_TOK) / 128), 256, GSMEM>>>(
        outh, IC, pwhT, DIM, proj_b, out, nullptr, B * N_TOK, IC, DIM);

    (void)in_sizes; (void)n_in; (void)out_size;
}

// round 17
// speedup vs baseline: 2.1292x; 1.0156x over previous
#include <cuda_runtime.h>
#include <cuda_fp16.h>
#include <cstdint>

// ---------------------------------------------------------------------------
// Problem constants
// ---------------------------------------------------------------------------
#define B 32
#define N_TOK 1024
#define DIM 512
#define IC 512
#define CC 256
#define NH 8
#define AG 49
#define HD 64
#define HH 32
#define WW 32
#define CIN 768            // IC + CC
#define KCONV 6912         // 768*9
#define MCONV 1568         // B*49
#define NQKV 1536          // IC + 2*IC
#define AGFLAT 25088       // IC*AG
#define KSPLIT 8
#define KSLAB 864          // KCONV / KSPLIT
#define PFLAT 37632        // AG*CIN per batch

// ---------------------------------------------------------------------------
// Scratch (static device globals; no allocation allowed)
// ---------------------------------------------------------------------------
__device__ __half g_qkvh[(size_t)B * N_TOK * NQKV];          // [q|k|v] fp16
__device__ __half g_xh[(size_t)B * N_TOK * DIM];             // x in fp16
__device__ __half g_whT[(size_t)NQKV * DIM];                 // [j][k]
__device__ __half g_pwhT[(size_t)IC * DIM];
__device__ __half g_cwh9[(size_t)IC * KCONV];                // [co][k9*768+ci]
__device__ float  g_pooled[(size_t)B * AG * CIN];            // natural [b][a*768+c]
__device__ __half g_poolT[(size_t)B * PFLAT];                // [b][s*768+ci]
__device__ float  g_convp[(size_t)KSPLIT * MCONV * IC];
__device__ float  g_agent_cs[(size_t)B * AGFLAT];
__device__ float  g_bias_an[NH * AG * N_TOK];
__device__ float  g_bias_na[NH * N_TOK * AG];
__device__ float  g_agv[(size_t)B * NH * AG * HD];
__device__ __half g_outh[(size_t)B * N_TOK * IC];

// ---------------------------------------------------------------------------
// PTX helpers
// ---------------------------------------------------------------------------
#define LDSM4(r0, r1, r2, r3, addr)                                      \
    asm volatile("ldmatrix.sync.aligned.m8n8.x4.shared.b16 "             \
                 "{%0,%1,%2,%3}, [%4];"                                  \
                 : "=r"(r0), "=r"(r1), "=r"(r2), "=r"(r3) : "r"(addr))

#define MMA_F16(d, a, b0, b1)                                            \
    asm volatile(                                                        \
        "mma.sync.aligned.m16n8k16.row.col.f32.f16.f16.f32 "             \
        "{%0,%1,%2,%3}, {%4,%5,%6,%7}, {%8,%9}, {%0,%1,%2,%3};"          \
        : "+f"((d)[0]), "+f"((d)[1]), "+f"((d)[2]), "+f"((d)[3])         \
        : "r"((a)[0]), "r"((a)[1]), "r"((a)[2]), "r"((a)[3]),            \
          "r"(b0), "r"(b1))

#define CP16(dst, src, bytes)                                            \
    asm volatile("cp.async.ca.shared.global [%0], [%1], 16, %2;"         \
                 :: "r"(dst), "l"(src), "r"(bytes))
#define CP_COMMIT() asm volatile("cp.async.commit_group;")
#define CP_WAIT(n)  asm volatile("cp.async.wait_group %0;" :: "n"(n))

__device__ __forceinline__ uint32_t smem_u32(const void* p) {
    uint32_t a;
    asm("{ .reg .u64 t; cvta.to.shared.u64 t, %1; cvt.u32.u64 %0, t; }"
        : "=r"(a) : "l"(p));
    return a;
}

// ---------------------------------------------------------------------------
// fp16 tensor-core GEMM, cp.async 3-stage pipeline (single product).
// ---------------------------------------------------------------------------
#define TROW   40
#define TILEB  10240
#define STAGEB (2 * TILEB)
#define NSTAGE 3
#define GSMEM  (NSTAGE * STAGEB)

__global__ __launch_bounds__(256, 2) void gemm_f16a(
    const __half* __restrict__ A, int lda,
    const __half* __restrict__ Bh, int ldb,
    const float* __restrict__ bias, float* __restrict__ C,
    __half* __restrict__ Ch,
    int M, int N, int K)
{
    extern __shared__ __half sm[];

    int t = threadIdx.x;
    int lane = t & 31, wid = t >> 5;
    int wm = (wid & 1) * 64, wn = (wid >> 1) * 32;
    int rr = lane & 7, j = lane >> 3;
    int m0 = blockIdx.y * 128, n0 = blockIdx.x * 128;

    float acc[4][4][4];
#pragma unroll
    for (int i = 0; i < 4; i++)
#pragma unroll
        for (int jj = 0; jj < 4; jj++)
#pragma unroll
            for (int k = 0; k < 4; k++) acc[i][jj][k] = 0.0f;

    int srow = t >> 1, shalf = t & 1;
    bool aok = (m0 + srow) < M;
    const __half* Ap  = A + (size_t)(aok ? (m0 + srow) : 0) * lda + shalf * 16;
    const __half* Bhp = Bh + (size_t)(n0 + srow) * ldb + shalf * 16;
    uint32_t abytes = aok ? 16u : 0u;
    uint32_t sm_u = smem_u32(sm);
    uint32_t sdst = (uint32_t)(srow * 80 + shalf * 32);

    uint32_t a_off[2][4];
#pragma unroll
    for (int kk = 0; kk < 2; kk++)
#pragma unroll
        for (int mf = 0; mf < 4; mf++)
            a_off[kk][mf] = (uint32_t)(((wm + mf * 16 + rr + (j & 1) * 8) * TROW
                                        + kk * 16 + (j >> 1) * 8) * 2);
    uint32_t b_off[2][2];
#pragma unroll
    for (int kk = 0; kk < 2; kk++)
#pragma unroll
        for (int p = 0; p < 2; p++)
            b_off[kk][p] = (uint32_t)(((wn + p * 16 + rr + (j >> 1) * 8) * TROW
                                       + kk * 16 + (j & 1) * 8) * 2);

#define ISSUE(stg, kt)                                                    \
    {   uint32_t base = sm_u + (stg) * STAGEB + sdst;                     \
        const __half* as = Ap + (kt);                                     \
        CP16(base, as, abytes); CP16(base + 16, as + 8, abytes);          \
        const __half* hs = Bhp + (kt);                                    \
        CP16(base + TILEB, hs, 16u); CP16(base + TILEB + 16, hs + 8, 16u);\
        CP_COMMIT(); }

    int NC = K / 32;
    ISSUE(0, 0);
    if (NC > 1) ISSUE(1, 32);

    for (int c = 0; c < NC; c++) {
        if (c + 1 < NC) { CP_WAIT(1); } else { CP_WAIT(0); }
        __syncthreads();
        if (c + 2 < NC) ISSUE((c + 2) % NSTAGE, (c + 2) * 32);

        uint32_t bb = sm_u + (c % NSTAGE) * STAGEB;
#pragma unroll
        for (int kk = 0; kk < 2; kk++) {
            uint32_t bhf[8];
            LDSM4(bhf[0], bhf[1], bhf[2], bhf[3], bb + TILEB + b_off[kk][0]);
            LDSM4(bhf[4], bhf[5], bhf[6], bhf[7], bb + TILEB + b_off[kk][1]);
#pragma unroll
            for (int mf = 0; mf < 4; mf++) {
                uint32_t ahf[4];
                LDSM4(ahf[0], ahf[1], ahf[2], ahf[3], bb + a_off[kk][mf]);
#pragma unroll
                for (int nf = 0; nf < 4; nf++)
                    MMA_F16(acc[mf][nf], ahf, bhf[nf * 2], bhf[nf * 2 + 1]);
            }
        }
        __syncthreads();
    }

    int er = lane >> 2, ec = (lane & 3) * 2;
#pragma unroll
    for (int nf = 0; nf < 4; nf++) {
        int col = n0 + wn + nf * 8 + ec;
        float bb0 = bias ? bias[col] : 0.0f;
        float bb1 = bias ? bias[col + 1] : 0.0f;
#pragma unroll
        for (int mf = 0; mf < 4; mf++) {
            int row = m0 + wm + mf * 16 + er;
            if (row < M) {
                float v0 = acc[mf][nf][0] + bb0, v1 = acc[mf][nf][1] + bb1;
                if (Ch)
                    *(__half2*)&Ch[(size_t)row * N + col]
                        = __halves2half2(__float2half(v0), __float2half(v1));
                else
                    *(float2*)&C[(size_t)row * N + col] = make_float2(v0, v1);
            }
            if (row + 8 < M) {
                float v0 = acc[mf][nf][2] + bb0, v1 = acc[mf][nf][3] + bb1;
                if (Ch)
                    *(__half2*)&Ch[(size_t)(row + 8) * N + col]
                        = __halves2half2(__float2half(v0), __float2half(v1));
                else
                    *(float2*)&C[(size_t)(row + 8) * N + col] = make_float2(v0, v1);
            }
        }
    }
}

// ---------------------------------------------------------------------------
// Implicit-GEMM conv (fused im2col).  blockIdx.z = K split (KSPLIT ways).
// ---------------------------------------------------------------------------
__global__ __launch_bounds__(256, 2) void gemm_conv(
    const __half* __restrict__ PT,
    const __half* __restrict__ Bh,
    float* __restrict__ C)
{
    extern __shared__ __half sm[];

    int kbase = blockIdx.z * KSLAB;
    C += (size_t)blockIdx.z * MCONV * IC;

    int t = threadIdx.x;
    int lane = t & 31, wid = t >> 5;
    int wm = (wid & 1) * 64, wn = (wid >> 1) * 32;
    int rr = lane & 7, j = lane >> 3;
    int m0 = blockIdx.y * 128, n0 = blockIdx.x * 128;

    float acc[4][4][4];
#pragma unroll
    for (int i = 0; i < 4; i++)
#pragma unroll
        for (int jj = 0; jj < 4; jj++)
#pragma unroll
            for (int k = 0; k < 4; k++) acc[i][jj][k] = 0.0f;

    int srow = t >> 1, shalf = t & 1;
    int gr = m0 + srow;
    bool aok = gr < MCONV;
    int bb_ = aok ? gr / AG : 0, pp = aok ? gr % AG : 0;
    int py = pp / 7, px = pp % 7;
    const __half* Pb = PT + (size_t)bb_ * PFLAT;
    const __half* Bhp = Bh + (size_t)(n0 + srow) * KCONV + kbase + shalf * 16;
    uint32_t sm_u = smem_u32(sm);
    uint32_t sdst = (uint32_t)(srow * 80 + shalf * 32);

    uint32_t a_off[2][4];
#pragma unroll
    for (int kk = 0; kk < 2; kk++)
#pragma unroll
        for (int mf = 0; mf < 4; mf++)
            a_off[kk][mf] = (uint32_t)(((wm + mf * 16 + rr + (j & 1) * 8) * TROW
                                        + kk * 16 + (j >> 1) * 8) * 2);
    uint32_t b_off[2][2];
#pragma unroll
    for (int kk = 0; kk < 2; kk++)
#pragma unroll
        for (int p = 0; p < 2; p++)
            b_off[kk][p] = (uint32_t)(((wn + p * 16 + rr + (j >> 1) * 8) * TROW
                                       + kk * 16 + (j & 1) * 8) * 2);

#define ISSUEC(stg, kt)                                                   \
    {   uint32_t base = sm_u + (stg) * STAGEB + sdst;                     \
        int kabs = kbase + (kt) + shalf * 16;                             \
        int k9 = kabs / 768, kof = kabs - k9 * 768;                       \
        int sy = py + k9 / 3 - 1, sx = px + (k9 - (k9 / 3) * 3) - 1;      \
        bool v = aok && sy >= 0 && sy < 7 && sx >= 0 && sx < 7;           \
        int sp = v ? (sy * 7 + sx) : 0;                                   \
        const __half* as = Pb + (size_t)sp * CIN + kof;                   \
        uint32_t ab = v ? 16u : 0u;                                       \
        CP16(base, as, ab); CP16(base + 16, as + 8, ab);                  \
        const __half* hs = Bhp + (kt);                                    \
        CP16(base + TILEB, hs, 16u); CP16(base + TILEB + 16, hs + 8, 16u);\
        CP_COMMIT(); }

    int NC = KSLAB / 32;
    ISSUEC(0, 0);
    ISSUEC(1, 32);

    for (int c = 0; c < NC; c++) {
        if (c + 1 < NC) { CP_WAIT(1); } else { CP_WAIT(0); }
        __syncthreads();
        if (c + 2 < NC) ISSUEC((c + 2) % NSTAGE, (c + 2) * 32);

        uint32_t bb = sm_u + (c % NSTAGE) * STAGEB;
#pragma unroll
        for (int kk = 0; kk < 2; kk++) {
            uint32_t bhf[8];
            LDSM4(bhf[0], bhf[1], bhf[2], bhf[3], bb + TILEB + b_off[kk][0]);
            LDSM4(bhf[4], bhf[5], bhf[6], bhf[7], bb + TILEB + b_off[kk][1]);
#pragma unroll
            for (int mf = 0; mf < 4; mf++) {
                uint32_t ahf[4];
                LDSM4(ahf[0], ahf[1], ahf[2], ahf[3], bb + a_off[kk][mf]);
#pragma unroll
                for (int nf = 0; nf < 4; nf++)
                    MMA_F16(acc[mf][nf], ahf, bhf[nf * 2], bhf[nf * 2 + 1]);
            }
        }
        __syncthreads();
    }

    int er = lane >> 2, ec = (lane & 3) * 2;
#pragma unroll
    for (int nf = 0; nf < 4; nf++) {
        int col = n0 + wn + nf * 8 + ec;
#pragma unroll
        for (int mf = 0; mf < 4; mf++) {
            int row = m0 + wm + mf * 16 + er;
            if (row < MCONV)
                *(float2*)&C[(size_t)row * IC + col]
                    = make_float2(acc[mf][nf][0], acc[mf][nf][1]);
            if (row + 8 < MCONV)
                *(float2*)&C[(size_t)(row + 8) * IC + col]
                    = make_float2(acc[mf][nf][2], acc[mf][nf][3]);
        }
    }
}

// ---------------------------------------------------------------------------
// Merged pre-convert kernels
// ---------------------------------------------------------------------------
__global__ __launch_bounds__(256) void transpose3_h(
    const float* __restrict__ Wq, const float* __restrict__ Wkv,
    const float* __restrict__ proj_w,
    __half* __restrict__ whT, __half* __restrict__ pwhT)
{
    __shared__ float tile[32][33];
    int z = blockIdx.z;
    const float* src; __half* dst; int C;
    if (z == 0)      { src = Wq;     dst = whT;                       C = IC; }
    else if (z == 1) { src = Wkv;    dst = whT + (size_t)IC * DIM;    C = 2 * IC; }
    else             { src = proj_w; dst = pwhT;                      C = IC; }
    int cb = blockIdx.x * 32, rb = blockIdx.y * 32;
    if (cb >= C) return;
    int tx = threadIdx.x & 31, ty = threadIdx.x >> 5;
    for (int i = ty; i < 32; i += 8) {
        int r = rb + i, c = cb + tx;
        if (c < C) tile[i][tx] = src[(size_t)r * C + c];
    }
    __syncthreads();
    for (int i = ty; i < 32; i += 8) {
        int c = cb + i, r = rb + tx;
        if (c < C) dst[(size_t)c * DIM + r] = __float2half(tile[tx][i]);
    }
}

__global__ void cvt2_kernel(const float* __restrict__ x,
                            const float* __restrict__ conv_w,
                            __half* __restrict__ xh, __half* __restrict__ cwh9,
                            size_t nx, size_t nc)
{
    size_t i = (size_t)blockIdx.x * blockDim.x + threadIdx.x;
    if (i < nx) xh[i] = __float2half(x[i]);
    else if (i < nx + nc) {
        size_t w = i - nx;
        int co = (int)(w / KCONV), r = (int)(w % KCONV);
        int k9 = r / CIN, ci = r % CIN;
        cwh9[w] = __float2half(conv_w[(size_t)co * KCONV + ci * 9 + k9]);
    }
}

// ---------------------------------------------------------------------------
// Adaptive pooling -> pooled[b][a*768 + c].  One block per (a, b).
// ---------------------------------------------------------------------------
__global__ __launch_bounds__(256) void pool_kernel(
    const __half* __restrict__ qkvh, const float* __restrict__ context,
    float* __restrict__ pooled)
{
    int a = blockIdx.x, b = blockIdx.y;
    int p = a / 7, q = a % 7;
    int sh = p * 32 / 7, eh = ((p + 1) * 32 + 6) / 7;
    int sw = q * 32 / 7, ew = ((q + 1) * 32 + 6) / 7;
    float inv = 1.0f / (float)((eh - sh) * (ew - sw));
    int t = threadIdx.x;

    float s0 = 0.0f, s1 = 0.0f, sc = 0.0f;
    for (int hh = sh; hh < eh; hh++) {
        const __half* qrow = qkvh + ((size_t)(b * N_TOK) + hh * WW) * NQKV + 2 * t;
        const float*  crow = context + ((size_t)(b * N_TOK) + hh * WW) * CC + t;
        for (int ww = sw; ww < ew; ww++) {
            float2 f = __half22float2(*(const __half2*)(qrow + (size_t)ww * NQKV));
            s0 += f.x; s1 += f.y;
            sc += crow[(size_t)ww * CC];
        }
    }
    float* dst = pooled + ((size_t)b * AG + a) * CIN;
    dst[2 * t]     = s0 * inv;
    dst[2 * t + 1] = s1 * inv;
    dst[IC + t]    = sc * inv;
}

// Transpose raw-reshaped (768,49) view -> poolT[b][s*768+ci] (fp16).
__global__ __launch_bounds__(256) void poolT_kernel(
    const float* __restrict__ pooled, __half* __restrict__ PT)
{
    __shared__ float tile[64][52];
    int b = blockIdx.y, cr0 = blockIdx.x * 64;
    const float* IN = pooled + (size_t)b * PFLAT;
    __half* OUT = PT + (size_t)b * PFLAT;
    for (int e = threadIdx.x; e < 64 * AG; e += 256) {
        int i = e / AG, s = e % AG;
        tile[i][s] = IN[(size_t)(cr0 + i) * AG + s];
    }
    __syncthreads();
    for (int e = threadIdx.x; e < 64 * AG; e += 256) {
        int s = e >> 6, i = e & 63;
        OUT[(size_t)s * CIN + cr0 + i] = __float2half(tile[i][s]);
    }
}

// Reduce split-K partials + conv bias, transpose to agent_cs[b][c*49+s]
__global__ __launch_bounds__(256) void conv_reduce_tr(
    const float* __restrict__ parts, const float* __restrict__ conv_b,
    float* __restrict__ out)
{
    int b = blockIdx.x, cb = blockIdx.y * 64;
    __shared__ float tile[64][50];
    int t = threadIdx.x;
    for (int e = t; e < 64 * AG; e += 256) {
        int c = e & 63, s = e >> 6;
        float v = conv_b[cb + c];
#pragma unroll
        for (int p = 0; p < KSPLIT; p++)
            v += parts[(size_t)p * MCONV * IC + ((size_t)b * AG + s) * IC + cb + c];
        tile[c][s] = v;
    }
    __syncthreads();
    for (int e = t; e < 64 * AG; e += 256) {
        int s = e % AG, c = e / AG;
        out[(size_t)b * AGFLAT + (cb + c) * AG + s] = tile[c][s];
    }
}

// ---------------------------------------------------------------------------
// Bias tables (merged)
// ---------------------------------------------------------------------------
__device__ __forceinline__ float bilin7(const float* __restrict__ src, int yi, int xi)
{
    float fy = (yi + 0.5f) * (7.0f / 32.0f) - 0.5f;
    float fx = (xi + 0.5f) * (7.0f / 32.0f) - 0.5f;
    int y0 = (int)floorf(fy); float wy = fy - (float)y0;
    int x0 = (int)floorf(fx); float wx = fx - (float)x0;
    int y0c = max(y0, 0), y1c = min(y0 + 1, 6);
    int x0c = max(x0, 0), x1c = min(x0 + 1, 6);
    float v00 = src[y0c * 7 + x0c], v01 = src[y0c * 7 + x1c];
    float v10 = src[y1c * 7 + x0c], v11 = src[y1c * 7 + x1c];
    return (1.f - wy) * ((1.f - wx) * v00 + wx * v01)
         + wy * ((1.f - wx) * v10 + wx * v11);
}

__global__ void bias_both_kernel(
    const float* __restrict__ an_bias, const float* __restrict__ ah_bias,
    const float* __restrict__ aw_bias,
    const float* __restrict__ na_bias, const float* __restrict__ ha_bias,
    const float* __restrict__ wa_bias,
    float* __restrict__ out_an, float* __restrict__ out_na)
{
    int idx = blockIdx.x * blockDim.x + threadIdx.x;
    if (blockIdx.y == 0) {
        if (idx >= NH * AG * N_TOK) return;
        int n = idx % N_TOK;
        int r = idx / N_TOK;
        int a = r % AG, h = r / AG;
        int hi = n >> 5, wi = n & 31;
        const float* src = an_bias + (size_t)(h * AG + a) * 49;
        out_an[idx] = bilin7(src, hi, wi)
                    + ah_bias[(h * AG + a) * 32 + hi]
                    + aw_bias[(h * AG + a) * 32 + wi];
    } else {
        if (idx >= NH * N_TOK * AG) return;
        int a = idx % AG;
        int r = idx / AG;
        int n = r % N_TOK, h = r / N_TOK;
        int hi = n >> 5, wi = n & 31;
        const float* src = na_bias + (size_t)(h * AG + a) * 49;
        out_na[idx] = bilin7(src, hi, wi)
                    + ha_bias[(h * 32 + hi) * AG + a]
                    + wa_bias[(h * 32 + wi) * AG + a];
    }
}

// ---------------------------------------------------------------------------
// Agent attention (flash, tensor-core).  One block per (b,h), 256 threads.
// ---------------------------------------------------------------------------
#define FL_SS 0
#define FL_AT 34048
#define FL_KS 43264
#define FL_VT 61696
#define FL_PS 79104
#define FL_MR 96512
#define FL_LR 96768
#define FL_FR 97024
#define FL_PM 97280
#define FL_PX 98304
#define FL_SMEM 99328

__global__ __launch_bounds__(256) void agent_flash_mma(
    const __half* __restrict__ qkvh, const float* __restrict__ agent_cs,
    const float* __restrict__ bias_an, float* __restrict__ agv)
{
    extern __shared__ char fsm[];
    float*  SS = (float*)(fsm + FL_SS);
    __half* AT = (__half*)(fsm + FL_AT);
    __half* KS = (__half*)(fsm + FL_KS);
    __half* VT = (__half*)(fsm + FL_VT);
    __half* PS = (__half*)(fsm + FL_PS);
    float*  MR = (float*)(fsm + FL_MR);
    float*  LR = (float*)(fsm + FL_LR);
    float*  FR = (float*)(fsm + FL_FR);
    float*  PM = (float*)(fsm + FL_PM);
    float*  PX = (float*)(fsm + FL_PX);

    int b = blockIdx.x, h = blockIdx.y, t = threadIdx.x;
    int lane = t & 31, wid = t >> 5;
    int rr = lane & 7, j = lane >> 3;
    int er = lane >> 2, ec = (lane & 3) * 2;
    int rid = t >> 2, seg = t & 3;

    uint32_t at_u = smem_u32(AT), ks_u = smem_u32(KS);
    uint32_t vt_u = smem_u32(VT), ps_u = smem_u32(PS);

    int wm1 = (wid & 1) * 32, wn1 = (wid >> 1) * 32;
    int wm2 = (wid & 3) * 16, wn2 = (wid >> 2) * 32;

    for (int e = t; e < 64 * 64; e += 256) {
        int a = e >> 6, d = e & 63;
        AT[a * 72 + d] = (a < AG)
            ? __float2half(agent_cs[(size_t)b * AGFLAT + a * IC + h * HD + d])
            : __half(0.0f);
    }
    if (t < 64) { MR[t] = -1e30f; LR[t] = 0.0f; }

    float acc2[4][4];
#pragma unroll
    for (int nf = 0; nf < 4; nf++)
#pragma unroll
        for (int k = 0; k < 4; k++) acc2[nf][k] = 0.0f;

    uint32_t a1_off[4][2], b1_off[4][2];
#pragma unroll
    for (int kk = 0; kk < 4; kk++) {
#pragma unroll
        for (int mf = 0; mf < 2; mf++)
            a1_off[kk][mf] = (uint32_t)(((wm1 + mf * 16 + rr + (j & 1) * 8) * 72
                                         + kk * 16 + (j >> 1) * 8) * 2);
#pragma unroll
        for (int p = 0; p < 2; p++)
            b1_off[kk][p] = (uint32_t)(((wn1 + p * 16 + rr + (j >> 1) * 8) * 72
                                        + kk * 16 + (j & 1) * 8) * 2);
    }
    uint32_t a2_off[8], b2_off[8][2];
#pragma unroll
    for (int kk = 0; kk < 8; kk++) {
        a2_off[kk] = (uint32_t)(((wm2 + rr + (j & 1) * 8) * 136
                                 + kk * 16 + (j >> 1) * 8) * 2);
#pragma unroll
        for (int p = 0; p < 2; p++)
            b2_off[kk][p] = (uint32_t)(((wn2 + p * 16 + rr + (j >> 1) * 8) * 136
                                        + kk * 16 + (j & 1) * 8) * 2);
    }

    for (int jt = 0; jt < N_TOK; jt += 128) {
        __syncthreads();
        // K tile: vectorized (float4 = 8 halves)
        for (int e = t; e < 1024; e += 256) {
            int jj = e >> 3, ch = e & 7;
            *(float4*)(KS + jj * 72 + ch * 8) = *(const float4*)(
                qkvh + ((size_t)(b * N_TOK + jt + jj)) * NQKV + IC + h * HD + ch * 8);
        }
        // V tile transposed: vectorized gmem load (float4 = 8 d-values),
        // scatter 8 scalar STS (same values/slots as scalar version)
        for (int e = t; e < 1024; e += 256) {
            int jj = e >> 3, dc = e & 7;
            float4 v4 = *(const float4*)(
                qkvh + ((size_t)(b * N_TOK + jt + jj)) * NQKV + 2 * IC + h * HD + dc * 8);
            const __half* hv = (const __half*)&v4;
#pragma unroll
            for (int i = 0; i < 8; i++)
                VT[(dc * 8 + i) * 136 + jj] = hv[i];
        }
        __syncthreads();

        float acc1[2][4][4];
#pragma unroll
        for (int mf = 0; mf < 2; mf++)
#pragma unroll
            for (int nf = 0; nf < 4; nf++)
#pragma unroll
                for (int k = 0; k < 4; k++) acc1[mf][nf][k] = 0.0f;
#pragma unroll
        for (int kk = 0; kk < 4; kk++) {
            uint32_t bf[8];
            LDSM4(bf[0], bf[1], bf[2], bf[3], ks_u + b1_off[kk][0]);
            LDSM4(bf[4], bf[5], bf[6], bf[7], ks_u + b1_off[kk][1]);
#pragma unroll
            for (int mf = 0; mf < 2; mf++) {
                uint32_t af[4];
                LDSM4(af[0], af[1], af[2], af[3], at_u + a1_off[kk][mf]);
#pragma unroll
                for (int nf = 0; nf < 4; nf++)
                    MMA_F16(acc1[mf][nf], af, bf[nf * 2], bf[nf * 2 + 1]);
            }
        }
#pragma unroll
        for (int mf = 0; mf < 2; mf++) {
            int a0 = wm1 + mf * 16 + er, a1 = a0 + 8;
            const float* bb0 = (a0 < AG) ? bias_an + (size_t)(h * AG + a0) * N_TOK + jt : nullptr;
            const float* bb1 = (a1 < AG) ? bias_an + (size_t)(h * AG + a1) * N_TOK + jt : nullptr;
#pragma unroll
            for (int nf = 0; nf < 4; nf++) {
                int jc = wn1 + nf * 8 + ec;
                if (bb0) {
                    SS[a0 * 133 + jc]     = acc1[mf][nf][0] * 0.125f + bb0[jc];
                    SS[a0 * 133 + jc + 1] = acc1[mf][nf][1] * 0.125f + bb0[jc + 1];
                } else {
                    SS[a0 * 133 + jc] = -1e30f; SS[a0 * 133 + jc + 1] = -1e30f;
                }
                if (bb1) {
                    SS[a1 * 133 + jc]     = acc1[mf][nf][2] * 0.125f + bb1[jc];
                    SS[a1 * 133 + jc + 1] = acc1[mf][nf][3] * 0.125f + bb1[jc + 1];
                } else {
                    SS[a1 * 133 + jc] = -1e30f; SS[a1 * 133 + jc + 1] = -1e30f;
                }
            }
        }
        __syncthreads();

        {
            float pm = -1e30f;
            const float* row = SS + rid * 133 + seg * 32;
            for (int i = 0; i < 32; i++) pm = fmaxf(pm, row[i]);
            PM[rid * 4 + seg] = pm;
        }
        __syncthreads();
        if (t < 64) {
            float mnew = fmaxf(fmaxf(PM[t * 4], PM[t * 4 + 1]),
                               fmaxf(PM[t * 4 + 2], PM[t * 4 + 3]));
            mnew = fmaxf(MR[t], mnew);
            FR[t] = __expf(MR[t] - mnew);
            MR[t] = mnew;
        }
        __syncthreads();
        {
            float m = MR[rid], ps = 0.0f;
            const float* row = SS + rid * 133 + seg * 32;
            __half* prow = PS + rid * 136 + seg * 32;
            for (int i = 0; i < 32; i++) {
                float e = __expf(row[i] - m);
                prow[i] = __float2half(e);
                ps += e;
            }
            PX[rid * 4 + seg] = ps;
        }
        __syncthreads();
        if (t < 64)
            LR[t] = LR[t] * FR[t]
                  + PX[t * 4] + PX[t * 4 + 1] + PX[t * 4 + 2] + PX[t * 4 + 3];

        {
            float f0 = FR[wm2 + er], f1 = FR[wm2 + er + 8];
#pragma unroll
            for (int nf = 0; nf < 4; nf++) {
                acc2[nf][0] *= f0; acc2[nf][1] *= f0;
                acc2[nf][2] *= f1; acc2[nf][3] *= f1;
            }
        }
#pragma unroll
        for (int kk = 0; kk < 8; kk++) {
            uint32_t bf[8];
            LDSM4(bf[0], bf[1], bf[2], bf[3], vt_u + b2_off[kk][0]);
            LDSM4(bf[4], bf[5], bf[6], bf[7], vt_u + b2_off[kk][1]);
            uint32_t af[4];
            LDSM4(af[0], af[1], af[2], af[3], ps_u + a2_off[kk]);
#pragma unroll
            for (int nf = 0; nf < 4; nf++)
                MMA_F16(acc2[nf], af, bf[nf * 2], bf[nf * 2 + 1]);
        }
    }

    __syncthreads();
    {
        int a0 = wm2 + er, a1 = a0 + 8;
        float i0 = (a0 < AG) ? 1.0f / LR[a0] : 0.0f;
        float i1 = (a1 < AG) ? 1.0f / LR[a1] : 0.0f;
#pragma unroll
        for (int nf = 0; nf < 4; nf++) {
            int d = wn2 + nf * 8 + ec;
            if (a0 < AG)
                *(float2*)&agv[(((size_t)(b * NH + h) * AG) + a0) * HD + d]
                    = make_float2(acc2[nf][0] * i0, acc2[nf][1] * i0);
            if (a1 < AG)
                *(float2*)&agv[(((size_t)(b * NH + h) * AG) + a1) * HD + d]
                    = make_float2(acc2[nf][2] * i1, acc2[nf][3] * i1);
        }
    }
}

// ---------------------------------------------------------------------------
// Query attention (tensor-core) -> outh (fp16).  Block (b,h,nt), 128 threads.
// ---------------------------------------------------------------------------
#define QA_SS 0
#define QA_QS 16640
#define QA_AT 25856
#define QA_PS 35072
#define QA_SMEM 44288

__global__ __launch_bounds__(128) void qattn_mma(
    const __half* __restrict__ qkvh, const float* __restrict__ agent_cs,
    const float* __restrict__ agv, const float* __restrict__ bias_na,
    __half* __restrict__ outh)
{
    extern __shared__ char qsm[];
    float*  SS  = (float*)(qsm + QA_SS);
    __half* QS  = (__half*)(qsm + QA_QS);
    __half* ATS = (__half*)(qsm + QA_AT);
    __half* PS  = (__half*)(qsm + QA_PS);

    int b = blockIdx.x, h = blockIdx.y, nt = blockIdx.z;
    int t = threadIdx.x;
    int lane = t & 31, wid = t >> 5;
    int rr = lane & 7, j = lane >> 3;
    int er = lane >> 2, ec = (lane & 3) * 2;
    int wm = (wid & 1) * 32, wn = (wid >> 1) * 32;

    uint32_t qs_u = smem_u32(QS), at_u = smem_u32(ATS), ps_u = smem_u32(PS);

    for (int e = t; e < 512; e += 128) {
        int nn = e >> 3, ch = e & 7;
        *(float4*)(QS + nn * 72 + ch * 8) = *(const float4*)(
            qkvh + ((size_t)(b * N_TOK) + nt * 64 + nn) * NQKV + h * HD + ch * 8);
    }
    for (int e = t; e < 64 * 64; e += 128) {
        int a = e >> 6, d = e & 63;
        ATS[a * 72 + d] = (a < AG)
            ? __float2half(agent_cs[(size_t)b * AGFLAT + a * IC + h * HD + d])
            : __half(0.0f);
    }
    __syncthreads();

    uint32_t a_off[4][2], b_off[4][2];
#pragma unroll
    for (int kk = 0; kk < 4; kk++) {
#pragma unroll
        for (int mf = 0; mf < 2; mf++)
            a_off[kk][mf] = (uint32_t)(((wm + mf * 16 + rr + (j & 1) * 8) * 72
                                        + kk * 16 + (j >> 1) * 8) * 2);
#pragma unroll
        for (int p = 0; p < 2; p++)
            b_off[kk][p] = (uint32_t)(((wn + p * 16 + rr + (j >> 1) * 8) * 72
                                       + kk * 16 + (j & 1) * 8) * 2);
    }

    float acc[2][4][4];
#pragma unroll
    for (int mf = 0; mf < 2; mf++)
#pragma unroll
        for (int nf = 0; nf < 4; nf++)
#pragma unroll
            for (int k = 0; k < 4; k++) acc[mf][nf][k] = 0.0f;

#pragma unroll
    for (int kk = 0; kk < 4; kk++) {
        uint32_t bf[8];
        LDSM4(bf[0], bf[1], bf[2], bf[3], at_u + b_off[kk][0]);
        LDSM4(bf[4], bf[5], bf[6], bf[7], at_u + b_off[kk][1]);
#pragma unroll
        for (int mf = 0; mf < 2; mf++) {
            uint32_t af[4];
            LDSM4(af[0], af[1], af[2], af[3], qs_u + a_off[kk][mf]);
#pragma unroll
            for (int nf = 0; nf < 4; nf++)
                MMA_F16(acc[mf][nf], af, bf[nf * 2], bf[nf * 2 + 1]);
        }
    }
#pragma unroll
    for (int mf = 0; mf < 2; mf++) {
        int tok0 = wm + mf * 16 + er, tok1 = tok0 + 8;
        const float* bn0 = bias_na + ((size_t)(h * N_TOK) + nt * 64 + tok0) * AG;
        const float* bn1 = bias_na + ((size_t)(h * N_TOK) + nt * 64 + tok1) * AG;
#pragma unroll
        for (int nf = 0; nf < 4; nf++) {
            int a = wn + nf * 8 + ec;
            SS[tok0 * 65 + a]     = (a < AG)     ? acc[mf][nf][0] * 0.125f + bn0[a]     : -1e30f;
            SS[tok0 * 65 + a + 1] = (a + 1 < AG) ? acc[mf][nf][1] * 0.125f + bn0[a + 1] : -1e30f;
            SS[tok1 * 65 + a]     = (a < AG)     ? acc[mf][nf][2] * 0.125f + bn1[a]     : -1e30f;
            SS[tok1 * 65 + a + 1] = (a + 1 < AG) ? acc[mf][nf][3] * 0.125f + bn1[a + 1] : -1e30f;
        }
    }
    __syncthreads();

    if (t < 64) {
        const float* row = SS + t * 65;
        float m = -1e30f;
        for (int a = 0; a < 64; a++) m = fmaxf(m, row[a]);
        float s = 0.0f;
        float e[64];
        for (int a = 0; a < 64; a++) { e[a] = __expf(row[a] - m); s += e[a]; }
        float inv = 1.0f / s;
        __half* prow = PS + t * 72;
        for (int a = 0; a < 64; a++) prow[a] = __float2half(e[a] * inv);
    } else {
        int d = t - 64;
        __half* vrow = ATS + d * 72;
        const float* ga = agv + ((size_t)(b * NH + h) * AG) * HD + d;
        for (int a = 0; a < AG; a++) vrow[a] = __float2half(ga[(size_t)a * HD]);
        for (int a = AG; a < 64; a++) vrow[a] = __half(0.0f);
    }
    __syncthreads();

#pragma unroll
    for (int mf = 0; mf < 2; mf++)
#pragma unroll
        for (int nf = 0; nf < 4; nf++)
#pragma unroll
            for (int k = 0; k < 4; k++) acc[mf][nf][k] = 0.0f;
#pragma unroll
    for (int kk = 0; kk < 4; kk++) {
        uint32_t bf[8];
        LDSM4(bf[0], bf[1], bf[2], bf[3], at_u + b_off[kk][0]);
        LDSM4(bf[4], bf[5], bf[6], bf[7], at_u + b_off[kk][1]);
#pragma unroll
        for (int mf = 0; mf < 2; mf++) {
            uint32_t af[4];
            LDSM4(af[0], af[1], af[2], af[3], ps_u + a_off[kk][mf]);
#pragma unroll
            for (int nf = 0; nf < 4; nf++)
                MMA_F16(acc[mf][nf], af, bf[nf * 2], bf[nf * 2 + 1]);
        }
    }
#pragma unroll
    for (int mf = 0; mf < 2; mf++) {
        int tok0 = nt * 64 + wm + mf * 16 + er;
#pragma unroll
        for (int nf = 0; nf < 4; nf++) {
            int d = wn + nf * 8 + ec;
            *(__half2*)&outh[((size_t)(b * N_TOK) + tok0) * IC + h * HD + d]
                = __halves2half2(__float2half(acc[mf][nf][0]),
                                 __float2half(acc[mf][nf][1]));
            *(__half2*)&outh[((size_t)(b * N_TOK) + tok0 + 8) * IC + h * HD + d]
                = __halves2half2(__float2half(acc[mf][nf][2]),
                                 __float2half(acc[mf][nf][3]));
        }
    }
}

// ---------------------------------------------------------------------------
// Depthwise 3x3 conv, sliding-window, half2 (channel pair per thread);
// fused in-place add into outh.  Per-channel math order unchanged.
// ---------------------------------------------------------------------------
__global__ __launch_bounds__(256) void dwc_kernel(
    const __half* __restrict__ qkvh,
    const float* __restrict__ dwc_w, const float* __restrict__ dwc_b,
    __half* __restrict__ outh)
{
    int hh = blockIdx.x, b = blockIdx.y;
    int c2 = threadIdx.x;               // channel pair: (2*c2, 2*c2+1)
    int c0i = 2 * c2;
    float w9a[9], w9b[9];
#pragma unroll
    for (int i = 0; i < 9; i++) {
        w9a[i] = dwc_w[c0i * 9 + i];
        w9b[i] = dwc_w[(c0i + 1) * 9 + i];
    }
    float wba = dwc_b[c0i], wbb = dwc_b[c0i + 1];
    const __half2* vb = (const __half2*)(
        qkvh + (size_t)(b * N_TOK) * NQKV + 2 * IC + c0i);

    float2 c0[3], c1[3], c2v[3];
#define LOADCOL2(x, dst)                                                  \
    {   if ((x) < 0 || (x) >= WW) {                                       \
            dst[0] = dst[1] = dst[2] = make_float2(0.f, 0.f);             \
        } else {                                                          \
            _Pragma("unroll")                                             \
            for (int r = 0; r < 3; r++) {                                 \
                int y = hh - 1 + r;                                       \
                dst[r] = (y >= 0 && y < HH)                               \
                    ? __half22float2(vb[(size_t)(y * WW + (x)) * (NQKV / 2)]) \
                    : make_float2(0.f, 0.f);                              \
            } } }

    LOADCOL2(-1, c0);
    LOADCOL2(0, c1);
    for (int x = 0; x < WW; x++) {
        LOADCOL2(x + 1, c2v);
        float sa = wba, sb = wbb;
#pragma unroll
        for (int r = 0; r < 3; r++) {
            sa += w9a[r * 3 + 0] * c0[r].x;
            sb += w9b[r * 3 + 0] * c0[r].y;
            sa += w9a[r * 3 + 1] * c1[r].x;
            sb += w9b[r * 3 + 1] * c1[r].y;
            sa += w9a[r * 3 + 2] * c2v[r].x;
            sb += w9b[r * 3 + 2] * c2v[r].y;
        }
        size_t i = ((size_t)(b * N_TOK) + hh * WW + x) * IC + c0i;
        __half2 o = *(__half2*)&outh[i];
        float2 of = __half22float2(o);
        *(__half2*)&outh[i] = __halves2half2(__float2half(of.x + sa),
                                             __float2half(of.y + sb));
#pragma unroll
        for (int r = 0; r < 3; r++) { c0[r] = c1[r]; c1[r] = c2v[r]; }
    }
}

// ---------------------------------------------------------------------------
// Host launcher
// ---------------------------------------------------------------------------
extern "C" void kernel_launch(void* const* d_in, const int* in_sizes, int n_in,
                              void* d_out, int out_size)
{
    const float* x       = (const float*)d_in[0];
    const float* context = (const float*)d_in[1];
    const float* Wq      = (const float*)d_in[2];
    const float* Wkv     = (const float*)d_in[3];
    const float* conv_w  = (const float*)d_in[4];
    const float* conv_b  = (const float*)d_in[5];
    const float* dwc_w   = (const float*)d_in[6];
    const float* dwc_b   = (const float*)d_in[7];
    const float* proj_w  = (const float*)d_in[8];
    const float* proj_b  = (const float*)d_in[9];
    const float* an_bias = (const float*)d_in[10];
    const float* na_bias = (const float*)d_in[11];
    const float* ah_bias = (const float*)d_in[12];
    const float* aw_bias = (const float*)d_in[13];
    const float* ha_bias = (const float*)d_in[14];
    const float* wa_bias = (const float*)d_in[15];
    float* out = (float*)d_out;

    float  *pooled, *convp, *agent_cs, *ban, *bna, *agv;
    __half *qkvh, *xh, *whT, *pwhT, *cwh9, *poolT, *outh;
    cudaGetSymbolAddress((void**)&qkvh,     g_qkvh);
    cudaGetSymbolAddress((void**)&xh,       g_xh);
    cudaGetSymbolAddress((void**)&whT,      g_whT);
    cudaGetSymbolAddress((void**)&pwhT,     g_pwhT);
    cudaGetSymbolAddress((void**)&cwh9,     g_cwh9);
    cudaGetSymbolAddress((void**)&pooled,   g_pooled);
    cudaGetSymbolAddress((void**)&poolT,    g_poolT);
    cudaGetSymbolAddress((void**)&convp,    g_convp);
    cudaGetSymbolAddress((void**)&agent_cs, g_agent_cs);
    cudaGetSymbolAddress((void**)&ban,      g_bias_an);
    cudaGetSymbolAddress((void**)&bna,      g_bias_na);
    cudaGetSymbolAddress((void**)&agv,      g_agv);
    cudaGetSymbolAddress((void**)&outh,     g_outh);

    cudaFuncSetAttribute(gemm_f16a,
                         cudaFuncAttributeMaxDynamicSharedMemorySize, GSMEM);
    cudaFuncSetAttribute(gemm_conv,
                         cudaFuncAttributeMaxDynamicSharedMemorySize, GSMEM);
    cudaFuncSetAttribute(agent_flash_mma,
                         cudaFuncAttributeMaxDynamicSharedMemorySize, FL_SMEM);
    cudaFuncSetAttribute(qattn_mma,
                         cudaFuncAttributeMaxDynamicSharedMemorySize, QA_SMEM);

    // 1. operand prep (merged; conv weights reordered k9-major)
    {
        size_t nx = (size_t)B * N_TOK * DIM;
        size_t nc = (size_t)IC * KCONV;
        cvt2_kernel<<<(int)((nx + nc + 255) / 256), 256>>>(
            x, conv_w, xh, cwh9, nx, nc);
    }
    transpose3_h<<<dim3(32, DIM / 32, 3), 256>>>(Wq, Wkv, proj_w, whT, pwhT);

    // 2. fused QKV GEMM -> fp16
    gemm_f16a<<<dim3(NQKV / 128, (B * N_TOK) / 128), 256, GSMEM>>>(
        xh, DIM, whT, DIM, nullptr, nullptr, qkvh, B * N_TOK, NQKV, DIM);

    // 3. adaptive pool (vectorized) + transpose to implicit-GEMM layout
    pool_kernel<<<dim3(AG, B), 256>>>(qkvh, context, pooled);
    poolT_kernel<<<dim3(CIN / 64, B), 256>>>(pooled, poolT);

    // 4. implicit-GEMM conv (8-way split-K) + reduce
    gemm_conv<<<dim3(IC / 128, (MCONV + 127) / 128, KSPLIT), 256, GSMEM>>>(
        poolT, cwh9, convp);
    conv_reduce_tr<<<dim3(B, IC / 64), 256>>>(convp, conv_b, agent_cs);

    // 5. bias tables (merged)
    bias_both_kernel<<<dim3((NH * AG * N_TOK + 255) / 256, 2), 256>>>(
        an_bias, ah_bias, aw_bias, na_bias, ha_bias, wa_bias, ban, bna);

    // 6. agent attention (tensor-core flash, vectorized V load)
    agent_flash_mma<<<dim3(B, NH), 256, FL_SMEM>>>(qkvh, agent_cs, ban, agv);

    // 7. query attention (tensor-core) -> outh (fp16)
    qattn_mma<<<dim3(B, NH, N_TOK / 64), 128, QA_SMEM>>>(
        qkvh, agent_cs, agv, bna, outh);

    // 8. depthwise conv residual (half2, channel pairs), in-place into outh
    dwc_kernel<<<dim3(HH, B), 256>>>(qkvh, dwc_w, dwc_b, outh);

    // 9. output projection
    gemm_f16a<<<dim3(IC / 128, (B * N_TOK) / 128), 256, GSMEM>>>(
        outh, IC, pwhT, DIM, proj_b, out, nullptr, B * N_TOK, IC, DIM);

    (void)in_sizes; (void)n_in; (void)out_size;
}